// round 1
// baseline (speedup 1.0000x reference)
#include <cuda_runtime.h>
#include <cstdint>

#define B_ 8
#define T_ 1024
#define D_ 1024
#define H_ 16
#define A_ 64

// ---------------- scratch (device globals: allocation-free) ----------------
__device__ float g_q[B_*T_*H_*A_];          // [b,t,h,a]
__device__ float g_k[B_*T_*H_*A_];
__device__ float g_v[B_*T_*H_*A_];
__device__ float g_ctx[B_*T_*H_*A_];
__device__ float g_ksum[B_*T_*H_];          // [b,t,h]
__device__ float g_bs[B_*T_*T_];            // [b,q,k]
__device__ int   g_lastE[B_*T_*T_];
__device__ float g_alpha[B_*H_*T_*T_];      // [b,h,q,k]  (536 MB)
__device__ float g_proj[32];
__device__ int   g_is64;

// ---------------- generic fp32 SGEMM: C[M,N] = A[M,K] * B[K,N] -------------
// 128x128 block tile, BK=8, 256 threads, 8x8 per-thread tile.
__global__ __launch_bounds__(256) void sgemm_nn(
    const float* __restrict__ A, const float* __restrict__ Bm,
    float* __restrict__ C, int M, int N, int K)
{
    __shared__ float As[8][128];
    __shared__ float Bs[8][128];
    const int t  = threadIdx.x;
    const int tx = t & 15, ty = t >> 4;
    const int row0 = blockIdx.y * 128;
    const int col0 = blockIdx.x * 128;
    const int arow = t >> 1;          // 0..127
    const int acol = (t & 1) * 4;     // 0 or 4
    const int brow = t >> 5;          // 0..7
    const int bcol = (t & 31) * 4;    // 0..124
    const float* Ap = A  + (size_t)(row0 + arow) * K + acol;
    const float* Bp = Bm + (size_t)brow * N + col0 + bcol;
    float acc[8][8];
    #pragma unroll
    for (int i = 0; i < 8; i++)
        #pragma unroll
        for (int j = 0; j < 8; j++) acc[i][j] = 0.f;

    for (int k0 = 0; k0 < K; k0 += 8) {
        float4 av = *(const float4*)Ap;
        float4 bv = *(const float4*)Bp;
        As[acol+0][arow] = av.x; As[acol+1][arow] = av.y;
        As[acol+2][arow] = av.z; As[acol+3][arow] = av.w;
        *(float4*)&Bs[brow][bcol] = bv;
        __syncthreads();
        #pragma unroll
        for (int kk = 0; kk < 8; kk++) {
            float ar[8], br[8];
            *(float4*)&ar[0] = *(const float4*)&As[kk][ty*4];
            *(float4*)&ar[4] = *(const float4*)&As[kk][64 + ty*4];
            *(float4*)&br[0] = *(const float4*)&Bs[kk][tx*4];
            *(float4*)&br[4] = *(const float4*)&Bs[kk][64 + tx*4];
            #pragma unroll
            for (int i = 0; i < 8; i++)
                #pragma unroll
                for (int j = 0; j < 8; j++)
                    acc[i][j] += ar[i] * br[j];
        }
        __syncthreads();
        Ap += 8;
        Bp += (size_t)8 * N;
    }
    #pragma unroll
    for (int i = 0; i < 8; i++) {
        int r = row0 + ((i < 4) ? (ty*4 + i) : (64 + ty*4 + (i - 4)));
        float* Cp = C + (size_t)r * N + col0;
        *(float4*)&Cp[tx*4]      = make_float4(acc[i][0], acc[i][1], acc[i][2], acc[i][3]);
        *(float4*)&Cp[64 + tx*4] = make_float4(acc[i][4], acc[i][5], acc[i][6], acc[i][7]);
    }
}

// ---------------- ksum[b,t,h] = sum_a k[b,t,h,a] ---------------------------
__global__ void ksum_kernel() {
    int idx = blockIdx.x * blockDim.x + threadIdx.x;   // B*T*H rows
    const float* p = g_k + (size_t)idx * 64;
    float s = 0.f;
    #pragma unroll
    for (int i = 0; i < 16; i++) {
        float4 v = *(const float4*)(p + i*4);
        s += v.x + v.y + v.z + v.w;
    }
    g_ksum[idx] = s;
}

// ---------------- proj[e] = bias_embs[e,:] . bias_scalar -------------------
__global__ void proj_kernel(const float* __restrict__ embs,
                            const float* __restrict__ sc) {
    int t = threadIdx.x;
    if (t < 32) {
        float s = 0.f;
        #pragma unroll
        for (int a = 0; a < 64; a++) s += embs[t*64 + a] * sc[a];
        g_proj[t] = s;
    }
}

// ---------------- dtype detection for attention_bias -----------------------
__global__ void detect_kernel(const void* __restrict__ ab, int E) {
    if (threadIdx.x == 0 && blockIdx.x == 0) {
        const long long* p = (const long long*)ab;
        int n = E < 256 ? E : 256;
        int ok = 1;
        for (int e = 0; e < n; e++) {
            long long et = p[e*4+0], bi = p[e*4+1], qi = p[e*4+2], ki = p[e*4+3];
            if (et < 0 || et >= 32 || bi < 0 || bi >= B_ ||
                qi < 0 || qi >= T_ || ki < 0 || ki >= T_) { ok = 0; break; }
        }
        g_is64 = ok;
    }
}

// ---------------- bs init + deterministic last-wins scatter ----------------
__global__ void init_bs_kernel() {
    int i = blockIdx.x * blockDim.x + threadIdx.x;     // float4 granularity
    ((float4*)g_bs)[i]   = make_float4(0.f, 0.f, 0.f, 0.f);
    ((int4*)g_lastE)[i]  = make_int4(-1, -1, -1, -1);
}

__device__ __forceinline__ void load_edge(const void* ab, int e,
                                          int& et, int& bi, int& qi, int& ki) {
    if (g_is64) {
        const long long* r = (const long long*)ab + (size_t)e * 4;
        et = (int)r[0]; bi = (int)r[1]; qi = (int)r[2]; ki = (int)r[3];
    } else {
        const int* r = (const int*)ab + (size_t)e * 4;
        et = r[0]; bi = r[1]; qi = r[2]; ki = r[3];
    }
}

__global__ void scatter_max_kernel(const void* __restrict__ ab, int E) {
    int e = blockIdx.x * blockDim.x + threadIdx.x;
    if (e >= E) return;
    int et, bi, qi, ki; load_edge(ab, e, et, bi, qi, ki);
    atomicMax(&g_lastE[((size_t)bi*T_ + qi)*T_ + ki], e);
}

__global__ void scatter_write_kernel(const void* __restrict__ ab, int E) {
    int e = blockIdx.x * blockDim.x + threadIdx.x;
    if (e >= E) return;
    int et, bi, qi, ki; load_edge(ab, e, et, bi, qi, ki);
    size_t idx = ((size_t)bi*T_ + qi)*T_ + ki;
    if (g_lastE[idx] == e) g_bs[idx] = g_proj[et];
}

// ---------------- scores: alpha[b,h,q,k] -----------------------------------
// block: 64q x 64k tile per (b,h); 256 threads, 4x4 per thread, K-dim=64 fully in smem.
__global__ __launch_bounds__(256) void score_kernel(const float* __restrict__ masks) {
    int bh = blockIdx.z; int b = bh >> 4, h = bh & 15;
    int q0 = blockIdx.y * 64, k0 = blockIdx.x * 64;
    __shared__ float QsT[64][68];   // [a][q]
    __shared__ float KsT[64][68];   // [a][k]
    int t = threadIdx.x;
    {
        int r   = t >> 2;          // 0..63
        int seg = (t & 3) * 16;    // a offset
        const float* qrow = g_q + (((size_t)(b*T_ + q0 + r)*H_ + h) * A_) + seg;
        const float* krow = g_k + (((size_t)(b*T_ + k0 + r)*H_ + h) * A_) + seg;
        #pragma unroll
        for (int i = 0; i < 4; i++) {
            float4 qv = *(const float4*)(qrow + i*4);
            QsT[seg+i*4+0][r] = qv.x; QsT[seg+i*4+1][r] = qv.y;
            QsT[seg+i*4+2][r] = qv.z; QsT[seg+i*4+3][r] = qv.w;
            float4 kv = *(const float4*)(krow + i*4);
            KsT[seg+i*4+0][r] = kv.x; KsT[seg+i*4+1][r] = kv.y;
            KsT[seg+i*4+2][r] = kv.z; KsT[seg+i*4+3][r] = kv.w;
        }
    }
    __syncthreads();
    int tx = t & 15, ty = t >> 4;
    float acc[4][4];
    #pragma unroll
    for (int i = 0; i < 4; i++)
        #pragma unroll
        for (int j = 0; j < 4; j++) acc[i][j] = 0.f;
    #pragma unroll
    for (int a = 0; a < 64; a++) {
        float qv[4], kv[4];
        *(float4*)qv = *(const float4*)&QsT[a][ty*4];
        *(float4*)kv = *(const float4*)&KsT[a][tx*4];
        #pragma unroll
        for (int i = 0; i < 4; i++)
            #pragma unroll
            for (int j = 0; j < 4; j++)
                acc[i][j] += qv[i] * kv[j];
    }
    // epilogue: + bs*ksum, *1/sqrt(A), - mask*big
    float ks4[4];
    #pragma unroll
    for (int j = 0; j < 4; j++)
        ks4[j] = g_ksum[((size_t)b*T_ + k0 + tx*4 + j)*H_ + h];
    #pragma unroll
    for (int i = 0; i < 4; i++) {
        int q = q0 + ty*4 + i;
        size_t mbase = ((size_t)b*T_ + q)*T_ + k0 + tx*4;
        float4 bsv = *(const float4*)(g_bs + mbase);
        float4 mv  = *(const float4*)(masks + mbase);
        float4 o;
        o.x = (acc[i][0] + bsv.x*ks4[0]) * 0.125f - mv.x * 1e30f;
        o.y = (acc[i][1] + bsv.y*ks4[1]) * 0.125f - mv.y * 1e30f;
        o.z = (acc[i][2] + bsv.z*ks4[2]) * 0.125f - mv.z * 1e30f;
        o.w = (acc[i][3] + bsv.w*ks4[3]) * 0.125f - mv.w * 1e30f;
        *(float4*)(g_alpha + ((size_t)(b*H_ + h)*T_ + q)*T_ + k0 + tx*4) = o;
    }
}

// ---------------- row softmax over last dim (1024) --------------------------
__global__ __launch_bounds__(256) void softmax_kernel() {
    size_t row = blockIdx.x;
    float* p = g_alpha + row * T_;
    int t = threadIdx.x;
    float4 v = *(float4*)&p[t*4];
    float m = fmaxf(fmaxf(v.x, v.y), fmaxf(v.z, v.w));
    #pragma unroll
    for (int o = 16; o; o >>= 1) m = fmaxf(m, __shfl_xor_sync(0xffffffffu, m, o));
    __shared__ float sred[8];
    if ((t & 31) == 0) sred[t >> 5] = m;
    __syncthreads();
    float mm = sred[0];
    #pragma unroll
    for (int i = 1; i < 8; i++) mm = fmaxf(mm, sred[i]);
    float4 e;
    e.x = expf(v.x - mm); e.y = expf(v.y - mm);
    e.z = expf(v.z - mm); e.w = expf(v.w - mm);
    float s = e.x + e.y + e.z + e.w;
    #pragma unroll
    for (int o = 16; o; o >>= 1) s += __shfl_xor_sync(0xffffffffu, s, o);
    __syncthreads();
    if ((t & 31) == 0) sred[t >> 5] = s;
    __syncthreads();
    float ss = sred[0];
    #pragma unroll
    for (int i = 1; i < 8; i++) ss += sred[i];
    float inv = 1.0f / ss;
    e.x *= inv; e.y *= inv; e.z *= inv; e.w *= inv;
    *(float4*)&p[t*4] = e;
}

// ---------------- context[b,q,h,a] = sum_k alpha[b,h,q,k] * v[b,k,h,a] -----
// block: 64q x 64a per (b,h), K-tile 32, 256 threads, 4x4 per thread.
__global__ __launch_bounds__(256) void context_kernel() {
    int bh = blockIdx.y; int b = bh >> 4, h = bh & 15;
    int q0 = blockIdx.x * 64;
    __shared__ float SsT[32][68];   // [k][q]
    __shared__ float Vs[32][68];    // [k][a]
    int t = threadIdx.x;
    int tx = t & 15, ty = t >> 4;
    float acc[4][4];
    #pragma unroll
    for (int i = 0; i < 4; i++)
        #pragma unroll
        for (int j = 0; j < 4; j++) acc[i][j] = 0.f;

    const float* abase = g_alpha + ((size_t)(b*H_ + h)*T_ + q0) * T_;
    for (int k0 = 0; k0 < T_; k0 += 32) {
        #pragma unroll
        for (int it = 0; it < 2; it++) {
            int idx = t + it * 256;
            int r  = idx >> 3;          // 0..63 q row
            int c4 = (idx & 7) * 4;     // 0..28 k col
            float4 sv = *(const float4*)(abase + (size_t)r * T_ + k0 + c4);
            SsT[c4+0][r] = sv.x; SsT[c4+1][r] = sv.y;
            SsT[c4+2][r] = sv.z; SsT[c4+3][r] = sv.w;
            int kr = idx >> 4;          // 0..31 k row
            int a4 = (idx & 15) * 4;    // 0..60 a col
            *(float4*)&Vs[kr][a4] =
                *(const float4*)(g_v + (((size_t)(b*T_ + k0 + kr)*H_ + h)*A_) + a4);
        }
        __syncthreads();
        #pragma unroll
        for (int kk = 0; kk < 32; kk++) {
            float sr[4], vr[4];
            *(float4*)sr = *(const float4*)&SsT[kk][ty*4];
            *(float4*)vr = *(const float4*)&Vs[kk][tx*4];
            #pragma unroll
            for (int i = 0; i < 4; i++)
                #pragma unroll
                for (int j = 0; j < 4; j++)
                    acc[i][j] += sr[i] * vr[j];
        }
        __syncthreads();
    }
    #pragma unroll
    for (int i = 0; i < 4; i++) {
        int q = q0 + ty*4 + i;
        float* op = g_ctx + (((size_t)(b*T_ + q)*H_ + h)*A_) + tx*4;
        *(float4*)op = make_float4(acc[i][0], acc[i][1], acc[i][2], acc[i][3]);
    }
}

// ---------------- launch ----------------------------------------------------
extern "C" void kernel_launch(void* const* d_in, const int* in_sizes, int n_in,
                              void* d_out, int out_size) {
    const float* states      = (const float*)d_in[0];
    const float* keys        = (const float*)d_in[1];
    const float* masks       = (const float*)d_in[2];
    const void*  abias       = (const void*) d_in[3];
    const float* Wq          = (const float*)d_in[4];
    const float* Wk          = (const float*)d_in[5];
    const float* Wv          = (const float*)d_in[6];
    const float* Wout        = (const float*)d_in[7];
    const float* bias_embs   = (const float*)d_in[8];
    const float* bias_scalar = (const float*)d_in[9];
    float* out = (float*)d_out;
    int E = in_sizes[3] / 4;

    float *pq, *pk, *pv, *pctx;
    cudaGetSymbolAddress((void**)&pq,   g_q);
    cudaGetSymbolAddress((void**)&pk,   g_k);
    cudaGetSymbolAddress((void**)&pv,   g_v);
    cudaGetSymbolAddress((void**)&pctx, g_ctx);

    dim3 gg(D_/128, (B_*T_)/128);     // (8, 64)
    sgemm_nn<<<gg, 256>>>(states, Wq, pq, B_*T_, H_*A_, D_);
    sgemm_nn<<<gg, 256>>>(keys,   Wk, pk, B_*T_, H_*A_, D_);
    sgemm_nn<<<gg, 256>>>(keys,   Wv, pv, B_*T_, H_*A_, D_);

    ksum_kernel<<<(B_*T_*H_)/256, 256>>>();
    proj_kernel<<<1, 32>>>(bias_embs, bias_scalar);
    detect_kernel<<<1, 32>>>(abias, E);
    init_bs_kernel<<<(B_*T_*T_/4)/256, 256>>>();
    scatter_max_kernel<<<(E + 255)/256, 256>>>(abias, E);
    scatter_write_kernel<<<(E + 255)/256, 256>>>(abias, E);

    dim3 gs(T_/64, T_/64, B_*H_);     // (16,16,128)
    score_kernel<<<gs, 256>>>(masks);

    softmax_kernel<<<B_*H_*T_, 256>>>();

    dim3 gc(T_/64, B_*H_);            // (16,128)
    context_kernel<<<gc, 256>>>();

    sgemm_nn<<<gg, 256>>>(pctx, Wout, out, B_*T_, D_, H_*A_);
}

// round 2
// speedup vs baseline: 2.3122x; 2.3122x over previous
#include <cuda_runtime.h>
#include <cuda_bf16.h>
#include <cstdint>

#define B_ 8
#define T_ 1024
#define D_ 1024
#define H_ 16
#define A_ 64

typedef __nv_bfloat16 bf16;

// ---------------- scratch (device globals: allocation-free) ----------------
__device__ float g_q[B_*T_*H_*A_];          // [b,t,h,a]
__device__ float g_k[B_*T_*H_*A_];
__device__ float g_v[B_*T_*H_*A_];
__device__ float g_ctx[B_*T_*H_*A_];
__device__ float g_ksum[B_*T_*H_];          // [b,t,h]
__device__ float g_bs[B_*T_*T_];            // [b,q,k]
__device__ int   g_lastE[B_*T_*T_];
__device__ float g_alpha[B_*H_*T_*T_];      // [b,h,q,k]
__device__ float g_proj[32];
__device__ int   g_is64;

// split-bf16 operands
__device__ __align__(16) bf16 g_sa[8192*3072];          // states-split / ctx-split (reused)
__device__ __align__(16) bf16 g_ka[8192*3072];          // keys-split
__device__ __align__(16) bf16 g_wq[1024*3072];
__device__ __align__(16) bf16 g_wk[1024*3072];
__device__ __align__(16) bf16 g_wv[1024*3072];
__device__ __align__(16) bf16 g_wo[1024*3072];
__device__ __align__(16) bf16 g_qs[B_*H_*T_*192];       // Q split, A-side dup
__device__ __align__(16) bf16 g_kb[B_*H_*T_*192];       // K split, B-side dup

// ---------------- mma.sync m16n8k16 bf16 ------------------------------------
__device__ __forceinline__ void mma16816(float* d, const uint32_t* a,
                                         uint32_t b0, uint32_t b1) {
    asm volatile(
        "mma.sync.aligned.m16n8k16.row.col.f32.bf16.bf16.f32 "
        "{%0,%1,%2,%3}, {%4,%5,%6,%7}, {%8,%9}, {%0,%1,%2,%3};\n"
        : "+f"(d[0]), "+f"(d[1]), "+f"(d[2]), "+f"(d[3])
        : "r"(a[0]), "r"(a[1]), "r"(a[2]), "r"(a[3]), "r"(b0), "r"(b1));
}

// ---------------- split-bf16 NT GEMM: C[M,N] = A[M,K3] * Bt[N,K3]^T ---------
// 128x128 block, BK=32, 256 threads, 8 warps (4m x 2n), warp tile 32x64.
// EPI=0: plain fp32 C write.  EPI=1: score epilogue (+bs*ksum, *1/8, -mask*big)
template<int EPI>
__global__ __launch_bounds__(256) void gemm_nt(
    const bf16* __restrict__ A, const bf16* __restrict__ Bt,
    float* __restrict__ C, int M, int N, int K3,
    size_t sA, size_t sB, size_t sC,
    const float* __restrict__ masks)
{
    __shared__ bf16 As[2][128*40];
    __shared__ bf16 Bs[2][128*40];
    const int t  = threadIdx.x;
    const int z  = blockIdx.z;
    const int m0 = blockIdx.y * 128, n0 = blockIdx.x * 128;
    const bf16* Ag = A  + (size_t)z * sA + (size_t)m0 * K3;
    const bf16* Bg = Bt + (size_t)z * sB + (size_t)n0 * K3;

    const int lrow = t >> 2;          // 0..63
    const int lseg = (t & 3) * 8;     // halves

    const int w = t >> 5, lane = t & 31;
    const int wm = (w & 3) * 32, wn = (w >> 2) * 64;
    const int g  = lane >> 2, t4 = lane & 3;

    float acc[2][8][4];
    #pragma unroll
    for (int i = 0; i < 2; i++)
        #pragma unroll
        for (int j = 0; j < 8; j++)
            #pragma unroll
            for (int c = 0; c < 4; c++) acc[i][j][c] = 0.f;

    uint4 ra0, ra1, rb0, rb1;
    // prologue: tile 0
    ra0 = *(const uint4*)(Ag + (size_t)lrow * K3 + lseg);
    ra1 = *(const uint4*)(Ag + (size_t)(lrow + 64) * K3 + lseg);
    rb0 = *(const uint4*)(Bg + (size_t)lrow * K3 + lseg);
    rb1 = *(const uint4*)(Bg + (size_t)(lrow + 64) * K3 + lseg);
    *(uint4*)&As[0][lrow * 40 + lseg]        = ra0;
    *(uint4*)&As[0][(lrow + 64) * 40 + lseg] = ra1;
    *(uint4*)&Bs[0][lrow * 40 + lseg]        = rb0;
    *(uint4*)&Bs[0][(lrow + 64) * 40 + lseg] = rb1;
    __syncthreads();

    const int nIt = K3 / 32;
    for (int it = 0; it < nIt; it++) {
        const int buf = it & 1;
        if (it + 1 < nIt) {
            const int k0 = (it + 1) * 32;
            ra0 = *(const uint4*)(Ag + (size_t)lrow * K3 + k0 + lseg);
            ra1 = *(const uint4*)(Ag + (size_t)(lrow + 64) * K3 + k0 + lseg);
            rb0 = *(const uint4*)(Bg + (size_t)lrow * K3 + k0 + lseg);
            rb1 = *(const uint4*)(Bg + (size_t)(lrow + 64) * K3 + k0 + lseg);
        }
        const bf16* sA = As[buf];
        const bf16* sB = Bs[buf];
        #pragma unroll
        for (int ks = 0; ks < 32; ks += 16) {
            uint32_t af[2][4];
            #pragma unroll
            for (int mt = 0; mt < 2; mt++) {
                const bf16* p = sA + (wm + mt * 16 + g) * 40 + ks + t4 * 2;
                af[mt][0] = *(const uint32_t*)(p);
                af[mt][1] = *(const uint32_t*)(p + 8 * 40);
                af[mt][2] = *(const uint32_t*)(p + 8);
                af[mt][3] = *(const uint32_t*)(p + 8 * 40 + 8);
            }
            #pragma unroll
            for (int nt8 = 0; nt8 < 8; nt8++) {
                const bf16* p = sB + (wn + nt8 * 8 + g) * 40 + ks + t4 * 2;
                uint32_t b0 = *(const uint32_t*)(p);
                uint32_t b1 = *(const uint32_t*)(p + 8);
                mma16816(acc[0][nt8], af[0], b0, b1);
                mma16816(acc[1][nt8], af[1], b0, b1);
            }
        }
        if (it + 1 < nIt) {
            const int nb = buf ^ 1;
            *(uint4*)&As[nb][lrow * 40 + lseg]        = ra0;
            *(uint4*)&As[nb][(lrow + 64) * 40 + lseg] = ra1;
            *(uint4*)&Bs[nb][lrow * 40 + lseg]        = rb0;
            *(uint4*)&Bs[nb][(lrow + 64) * 40 + lseg] = rb1;
        }
        __syncthreads();
    }

    if (EPI == 0) {
        float* Cg = C + (size_t)z * sC;
        #pragma unroll
        for (int mt = 0; mt < 2; mt++) {
            #pragma unroll
            for (int nt8 = 0; nt8 < 8; nt8++) {
                int row = m0 + wm + mt * 16 + g;
                int col = n0 + wn + nt8 * 8 + t4 * 2;
                *(float2*)&Cg[(size_t)row * N + col] =
                    make_float2(acc[mt][nt8][0], acc[mt][nt8][1]);
                *(float2*)&Cg[(size_t)(row + 8) * N + col] =
                    make_float2(acc[mt][nt8][2], acc[mt][nt8][3]);
            }
        }
    } else {
        const int b = z >> 4, h = z & 15;
        float* Cg = C + (size_t)z * sC;
        #pragma unroll
        for (int mt = 0; mt < 2; mt++) {
            #pragma unroll
            for (int nt8 = 0; nt8 < 8; nt8++) {
                int q  = m0 + wm + mt * 16 + g;
                int kk = n0 + wn + nt8 * 8 + t4 * 2;
                float ks0 = g_ksum[((size_t)b * T_ + kk) * H_ + h];
                float ks1 = g_ksum[((size_t)b * T_ + kk + 1) * H_ + h];
                #pragma unroll
                for (int rr = 0; rr < 2; rr++) {
                    int qq = q + rr * 8;
                    size_t mb = ((size_t)b * T_ + qq) * T_ + kk;
                    float2 bsv = *(const float2*)&g_bs[mb];
                    float2 mv  = *(const float2*)&masks[mb];
                    float o0 = (acc[mt][nt8][rr * 2 + 0] + bsv.x * ks0) * 0.125f - mv.x * 1e30f;
                    float o1 = (acc[mt][nt8][rr * 2 + 1] + bsv.y * ks1) * 0.125f - mv.y * 1e30f;
                    *(float2*)&Cg[(size_t)qq * T_ + kk] = make_float2(o0, o1);
                }
            }
        }
    }
}

// ---------------- conversions ------------------------------------------------
__device__ __forceinline__ void split2(float v, bf16& hi, bf16& lo) {
    hi = __float2bfloat16_rn(v);
    lo = __float2bfloat16_rn(v - __bfloat162float(hi));
}

// f32 [M][K] row-major -> bf16 [M][3K] as [hi | hi | lo]  (A-side)
__global__ void conv_a(const float4* __restrict__ in, bf16* __restrict__ out, int K) {
    size_t idx = (size_t)blockIdx.x * 256 + threadIdx.x;
    float4 v = in[idx];
    int kq = K >> 2;
    size_t m = idx / kq;
    int k4 = (int)(idx % kq) * 4;
    bf16 h0,h1,h2,h3,l0,l1,l2,l3;
    split2(v.x,h0,l0); split2(v.y,h1,l1); split2(v.z,h2,l2); split2(v.w,h3,l3);
    __nv_bfloat162 hp0, hp1, lp0, lp1;
    hp0.x=h0; hp0.y=h1; hp1.x=h2; hp1.y=h3;
    lp0.x=l0; lp0.y=l1; lp1.x=l2; lp1.y=l3;
    bf16* o = out + m * (size_t)(3 * K) + k4;
    ((__nv_bfloat162*)o)[0] = hp0;          ((__nv_bfloat162*)o)[1] = hp1;
    ((__nv_bfloat162*)(o + K))[0] = hp0;    ((__nv_bfloat162*)(o + K))[1] = hp1;
    ((__nv_bfloat162*)(o + 2*K))[0] = lp0;  ((__nv_bfloat162*)(o + 2*K))[1] = lp1;
}

// f32 [K][N] -> bf16 [N][3K] transposed as [hi | lo | hi]  (B-side)
__global__ void conv_bT(const float* __restrict__ in, bf16* __restrict__ out,
                        int K, int N) {
    __shared__ float tile[32][33];
    int k0 = blockIdx.y * 32, n0 = blockIdx.x * 32;
    int tx = threadIdx.x & 31, ty = threadIdx.x >> 5;
    #pragma unroll
    for (int i = 0; i < 4; i++)
        tile[ty + 8*i][tx] = in[(size_t)(k0 + ty + 8*i) * N + n0 + tx];
    __syncthreads();
    #pragma unroll
    for (int i = 0; i < 4; i++) {
        int n = n0 + ty + 8*i, k = k0 + tx;
        float v = tile[tx][ty + 8*i];
        bf16 hi, lo; split2(v, hi, lo);
        bf16* o = out + (size_t)n * (3 * K);
        o[k] = hi; o[K + k] = lo; o[2*K + k] = hi;
    }
}

// [b,t,h,a] f32 -> [(b,h,t)][192] bf16; amode=1: [hi|hi|lo], amode=0: [hi|lo|hi]
__global__ void conv_qk(const float* __restrict__ in, bf16* __restrict__ out,
                        int amode) {
    int row  = blockIdx.x * 8 + (threadIdx.x >> 5);   // b*H*T + h*T + t
    int lane = threadIdx.x & 31;
    int b = row >> 14, h = (row >> 10) & 15, tt = row & 1023;
    float2 v = *(const float2*)(in + (((size_t)b * 1024 + tt) * 16 + h) * 64 + lane * 2);
    bf16 h0,h1,l0,l1;
    split2(v.x,h0,l0); split2(v.y,h1,l1);
    __nv_bfloat162 hp, lp; hp.x=h0; hp.y=h1; lp.x=l0; lp.y=l1;
    __nv_bfloat162* o = (__nv_bfloat162*)(out + (size_t)row * 192) + lane;
    o[0]  = hp;
    o[32] = amode ? hp : lp;
    o[64] = amode ? lp : hp;
}

// ---------------- ksum[b,t,h] = sum_a k[b,t,h,a] ---------------------------
__global__ void ksum_kernel() {
    int idx = blockIdx.x * blockDim.x + threadIdx.x;
    const float* p = g_k + (size_t)idx * 64;
    float s = 0.f;
    #pragma unroll
    for (int i = 0; i < 16; i++) {
        float4 v = *(const float4*)(p + i*4);
        s += v.x + v.y + v.z + v.w;
    }
    g_ksum[idx] = s;
}

// ---------------- proj[e] = bias_embs[e,:] . bias_scalar -------------------
__global__ void proj_kernel(const float* __restrict__ embs,
                            const float* __restrict__ sc) {
    int t = threadIdx.x;
    if (t < 32) {
        float s = 0.f;
        #pragma unroll
        for (int a = 0; a < 64; a++) s += embs[t*64 + a] * sc[a];
        g_proj[t] = s;
    }
}

__global__ void detect_kernel(const void* __restrict__ ab, int E) {
    if (threadIdx.x == 0 && blockIdx.x == 0) {
        const long long* p = (const long long*)ab;
        int n = E < 256 ? E : 256;
        int ok = 1;
        for (int e = 0; e < n; e++) {
            long long et = p[e*4+0], bi = p[e*4+1], qi = p[e*4+2], ki = p[e*4+3];
            if (et < 0 || et >= 32 || bi < 0 || bi >= B_ ||
                qi < 0 || qi >= T_ || ki < 0 || ki >= T_) { ok = 0; break; }
        }
        g_is64 = ok;
    }
}

__global__ void init_bs_kernel() {
    int i = blockIdx.x * blockDim.x + threadIdx.x;
    ((float4*)g_bs)[i]  = make_float4(0.f, 0.f, 0.f, 0.f);
    ((int4*)g_lastE)[i] = make_int4(-1, -1, -1, -1);
}

__device__ __forceinline__ void load_edge(const void* ab, int e,
                                          int& et, int& bi, int& qi, int& ki) {
    if (g_is64) {
        const long long* r = (const long long*)ab + (size_t)e * 4;
        et = (int)r[0]; bi = (int)r[1]; qi = (int)r[2]; ki = (int)r[3];
    } else {
        const int* r = (const int*)ab + (size_t)e * 4;
        et = r[0]; bi = r[1]; qi = r[2]; ki = r[3];
    }
}

__global__ void scatter_max_kernel(const void* __restrict__ ab, int E) {
    int e = blockIdx.x * blockDim.x + threadIdx.x;
    if (e >= E) return;
    int et, bi, qi, ki; load_edge(ab, e, et, bi, qi, ki);
    atomicMax(&g_lastE[((size_t)bi*T_ + qi)*T_ + ki], e);
}

__global__ void scatter_write_kernel(const void* __restrict__ ab, int E) {
    int e = blockIdx.x * blockDim.x + threadIdx.x;
    if (e >= E) return;
    int et, bi, qi, ki; load_edge(ab, e, et, bi, qi, ki);
    size_t idx = ((size_t)bi*T_ + qi)*T_ + ki;
    if (g_lastE[idx] == e) g_bs[idx] = g_proj[et];
}

// ---------------- row softmax over last dim (1024) --------------------------
__global__ __launch_bounds__(256) void softmax_kernel() {
    size_t row = blockIdx.x;
    float* p = g_alpha + row * T_;
    int t = threadIdx.x;
    float4 v = *(float4*)&p[t*4];
    float m = fmaxf(fmaxf(v.x, v.y), fmaxf(v.z, v.w));
    #pragma unroll
    for (int o = 16; o; o >>= 1) m = fmaxf(m, __shfl_xor_sync(0xffffffffu, m, o));
    __shared__ float sred[8];
    if ((t & 31) == 0) sred[t >> 5] = m;
    __syncthreads();
    float mm = sred[0];
    #pragma unroll
    for (int i = 1; i < 8; i++) mm = fmaxf(mm, sred[i]);
    float4 e;
    e.x = expf(v.x - mm); e.y = expf(v.y - mm);
    e.z = expf(v.z - mm); e.w = expf(v.w - mm);
    float s = e.x + e.y + e.z + e.w;
    #pragma unroll
    for (int o = 16; o; o >>= 1) s += __shfl_xor_sync(0xffffffffu, s, o);
    __syncthreads();
    if ((t & 31) == 0) sred[t >> 5] = s;
    __syncthreads();
    float ss = sred[0];
    #pragma unroll
    for (int i = 1; i < 8; i++) ss += sred[i];
    float inv = 1.0f / ss;
    e.x *= inv; e.y *= inv; e.z *= inv; e.w *= inv;
    *(float4*)&p[t*4] = e;
}

// ---------------- context[b,q,h,a] = sum_k alpha[b,h,q,k] * v[b,k,h,a] -----
__global__ __launch_bounds__(256) void context_kernel() {
    int bh = blockIdx.y; int b = bh >> 4, h = bh & 15;
    int q0 = blockIdx.x * 64;
    __shared__ float SsT[32][68];
    __shared__ float Vs[32][68];
    int t = threadIdx.x;
    int tx = t & 15, ty = t >> 4;
    float acc[4][4];
    #pragma unroll
    for (int i = 0; i < 4; i++)
        #pragma unroll
        for (int j = 0; j < 4; j++) acc[i][j] = 0.f;

    const float* abase = g_alpha + ((size_t)(b*H_ + h)*T_ + q0) * T_;
    for (int k0 = 0; k0 < T_; k0 += 32) {
        #pragma unroll
        for (int it = 0; it < 2; it++) {
            int idx = t + it * 256;
            int r  = idx >> 3;
            int c4 = (idx & 7) * 4;
            float4 sv = *(const float4*)(abase + (size_t)r * T_ + k0 + c4);
            SsT[c4+0][r] = sv.x; SsT[c4+1][r] = sv.y;
            SsT[c4+2][r] = sv.z; SsT[c4+3][r] = sv.w;
            int kr = idx >> 4;
            int a4 = (idx & 15) * 4;
            *(float4*)&Vs[kr][a4] =
                *(const float4*)(g_v + (((size_t)(b*T_ + k0 + kr)*H_ + h)*A_) + a4);
        }
        __syncthreads();
        #pragma unroll
        for (int kk = 0; kk < 32; kk++) {
            float sr[4], vr[4];
            *(float4*)sr = *(const float4*)&SsT[kk][ty*4];
            *(float4*)vr = *(const float4*)&Vs[kk][tx*4];
            #pragma unroll
            for (int i = 0; i < 4; i++)
                #pragma unroll
                for (int j = 0; j < 4; j++)
                    acc[i][j] += sr[i] * vr[j];
        }
        __syncthreads();
    }
    #pragma unroll
    for (int i = 0; i < 4; i++) {
        int q = q0 + ty*4 + i;
        float* op = g_ctx + (((size_t)(b*T_ + q)*H_ + h)*A_) + tx*4;
        *(float4*)op = make_float4(acc[i][0], acc[i][1], acc[i][2], acc[i][3]);
    }
}

// ---------------- launch ----------------------------------------------------
extern "C" void kernel_launch(void* const* d_in, const int* in_sizes, int n_in,
                              void* d_out, int out_size) {
    const float* states      = (const float*)d_in[0];
    const float* keys        = (const float*)d_in[1];
    const float* masks       = (const float*)d_in[2];
    const void*  abias       = (const void*) d_in[3];
    const float* Wq          = (const float*)d_in[4];
    const float* Wk          = (const float*)d_in[5];
    const float* Wv          = (const float*)d_in[6];
    const float* Wout        = (const float*)d_in[7];
    const float* bias_embs   = (const float*)d_in[8];
    const float* bias_scalar = (const float*)d_in[9];
    float* out = (float*)d_out;
    int E = in_sizes[3] / 4;

    float *pq, *pk, *pv, *pctx, *palpha;
    bf16 *psa, *pka, *pwq, *pwk, *pwv, *pwo, *pqs, *pkb;
    cudaGetSymbolAddress((void**)&pq,     g_q);
    cudaGetSymbolAddress((void**)&pk,     g_k);
    cudaGetSymbolAddress((void**)&pv,     g_v);
    cudaGetSymbolAddress((void**)&pctx,   g_ctx);
    cudaGetSymbolAddress((void**)&palpha, g_alpha);
    cudaGetSymbolAddress((void**)&psa,    g_sa);
    cudaGetSymbolAddress((void**)&pka,    g_ka);
    cudaGetSymbolAddress((void**)&pwq,    g_wq);
    cudaGetSymbolAddress((void**)&pwk,    g_wk);
    cudaGetSymbolAddress((void**)&pwv,    g_wv);
    cudaGetSymbolAddress((void**)&pwo,    g_wo);
    cudaGetSymbolAddress((void**)&pqs,    g_qs);
    cudaGetSymbolAddress((void**)&pkb,    g_kb);

    // conversions
    conv_a<<<8192, 256>>>((const float4*)states, psa, 1024);
    conv_a<<<8192, 256>>>((const float4*)keys,   pka, 1024);
    dim3 gt(32, 32);
    conv_bT<<<gt, 256>>>(Wq,   pwq, 1024, 1024);
    conv_bT<<<gt, 256>>>(Wk,   pwk, 1024, 1024);
    conv_bT<<<gt, 256>>>(Wv,   pwv, 1024, 1024);
    conv_bT<<<gt, 256>>>(Wout, pwo, 1024, 1024);

    // projections on tensor cores
    dim3 gg(8, 64, 1);
    gemm_nt<0><<<gg, 256>>>(psa, pwq, pq, 8192, 1024, 3072, 0, 0, 0, nullptr);
    gemm_nt<0><<<gg, 256>>>(pka, pwk, pk, 8192, 1024, 3072, 0, 0, 0, nullptr);
    gemm_nt<0><<<gg, 256>>>(pka, pwv, pv, 8192, 1024, 3072, 0, 0, 0, nullptr);

    // side computations
    ksum_kernel<<<(B_*T_*H_)/256, 256>>>();
    proj_kernel<<<1, 32>>>(bias_embs, bias_scalar);
    detect_kernel<<<1, 32>>>(abias, E);
    init_bs_kernel<<<(B_*T_*T_/4)/256, 256>>>();
    scatter_max_kernel<<<(E + 255)/256, 256>>>(abias, E);
    scatter_write_kernel<<<(E + 255)/256, 256>>>(abias, E);

    // q/k split for score GEMM
    conv_qk<<<B_*H_*T_/8, 256>>>(pq, pqs, 1);
    conv_qk<<<B_*H_*T_/8, 256>>>(pk, pkb, 0);

    // batched score GEMM + epilogue
    dim3 gs(8, 8, 128);
    gemm_nt<1><<<gs, 256>>>(pqs, pkb, palpha, 1024, 1024, 192,
                            (size_t)1024*192, (size_t)1024*192,
                            (size_t)1024*1024, masks);

    softmax_kernel<<<B_*H_*T_, 256>>>();

    dim3 gc(T_/64, B_*H_);
    context_kernel<<<gc, 256>>>();

    // output projection
    conv_a<<<8192, 256>>>((const float4*)pctx, psa, 1024);
    gemm_nt<0><<<gg, 256>>>(psa, pwo, out, 8192, 1024, 3072, 0, 0, 0, nullptr);
}

// round 5
// speedup vs baseline: 3.1468x; 1.3609x over previous
#include <cuda_runtime.h>
#include <cuda_bf16.h>
#include <cstdint>

#define B_ 8
#define T_ 1024
#define D_ 1024
#define H_ 16
#define A_ 64

typedef __nv_bfloat16 bf16;

// ---------------- scratch (device globals: allocation-free) ----------------
__device__ float g_q[B_*T_*H_*A_];          // [b,t,h,a]
__device__ float g_k[B_*T_*H_*A_];
__device__ float g_v[B_*T_*H_*A_];
__device__ float g_ksumT[B_*H_*T_];         // [(b,h),t]
__device__ float g_bs[B_*T_*T_];            // [b,q,k]
__device__ int   g_lastE[B_*T_*T_];
__device__ float g_proj[32];
__device__ int   g_is64;

// split-bf16 operands
__device__ __align__(16) bf16 g_sa[8192*3072];          // states-split, later ctx-split
__device__ __align__(16) bf16 g_ka[8192*3072];          // keys-split
__device__ __align__(16) bf16 g_wq[1024*3072];
__device__ __align__(16) bf16 g_wk[1024*3072];
__device__ __align__(16) bf16 g_wv[1024*3072];
__device__ __align__(16) bf16 g_wo[1024*3072];
__device__ __align__(16) bf16 g_qs[B_*H_*T_*192];       // Q split [hi|hi|lo], rows (b,h,t)
__device__ __align__(16) bf16 g_kb[B_*H_*T_*192];       // K split [hi|lo|hi], rows (b,h,t)
__device__ __align__(16) bf16 g_vhi[B_*H_*A_*T_];       // [(b,h),a,k]
__device__ __align__(16) bf16 g_vlo[B_*H_*A_*T_];

// ---------------- mma.sync m16n8k16 bf16 ------------------------------------
__device__ __forceinline__ void mma16816(float* d, const uint32_t* a,
                                         uint32_t b0, uint32_t b1) {
    asm volatile(
        "mma.sync.aligned.m16n8k16.row.col.f32.bf16.bf16.f32 "
        "{%0,%1,%2,%3}, {%4,%5,%6,%7}, {%8,%9}, {%0,%1,%2,%3};\n"
        : "+f"(d[0]), "+f"(d[1]), "+f"(d[2]), "+f"(d[3])
        : "r"(a[0]), "r"(a[1]), "r"(a[2]), "r"(a[3]), "r"(b0), "r"(b1));
}

__device__ __forceinline__ float ex2f(float x) {
    float r;
    asm("ex2.approx.f32 %0, %1;" : "=f"(r) : "f"(x));
    return r;
}

// ---------------- split-bf16 NT GEMM: C[M,N] = A[M,K3] * Bt[N,K3]^T ---------
__global__ __launch_bounds__(256) void gemm_nt(
    const bf16* __restrict__ A, const bf16* __restrict__ Bt,
    float* __restrict__ C, int M, int N, int K3)
{
    __shared__ bf16 As[2][128*40];
    __shared__ bf16 Bs[2][128*40];
    const int t  = threadIdx.x;
    const int m0 = blockIdx.y * 128, n0 = blockIdx.x * 128;
    const bf16* Ag = A  + (size_t)m0 * K3;
    const bf16* Bg = Bt + (size_t)n0 * K3;

    const int lrow = t >> 2;
    const int lseg = (t & 3) * 8;
    const int w = t >> 5, lane = t & 31;
    const int wm = (w & 3) * 32, wn = (w >> 2) * 64;
    const int g  = lane >> 2, t4 = lane & 3;

    float acc[2][8][4];
    #pragma unroll
    for (int i = 0; i < 2; i++)
        #pragma unroll
        for (int j = 0; j < 8; j++)
            #pragma unroll
            for (int c = 0; c < 4; c++) acc[i][j][c] = 0.f;

    uint4 ra0, ra1, rb0, rb1;
    ra0 = *(const uint4*)(Ag + (size_t)lrow * K3 + lseg);
    ra1 = *(const uint4*)(Ag + (size_t)(lrow + 64) * K3 + lseg);
    rb0 = *(const uint4*)(Bg + (size_t)lrow * K3 + lseg);
    rb1 = *(const uint4*)(Bg + (size_t)(lrow + 64) * K3 + lseg);
    *(uint4*)&As[0][lrow * 40 + lseg]        = ra0;
    *(uint4*)&As[0][(lrow + 64) * 40 + lseg] = ra1;
    *(uint4*)&Bs[0][lrow * 40 + lseg]        = rb0;
    *(uint4*)&Bs[0][(lrow + 64) * 40 + lseg] = rb1;
    __syncthreads();

    const int nIt = K3 / 32;
    for (int it = 0; it < nIt; it++) {
        const int buf = it & 1;
        if (it + 1 < nIt) {
            const int k0 = (it + 1) * 32;
            ra0 = *(const uint4*)(Ag + (size_t)lrow * K3 + k0 + lseg);
            ra1 = *(const uint4*)(Ag + (size_t)(lrow + 64) * K3 + k0 + lseg);
            rb0 = *(const uint4*)(Bg + (size_t)lrow * K3 + k0 + lseg);
            rb1 = *(const uint4*)(Bg + (size_t)(lrow + 64) * K3 + k0 + lseg);
        }
        const bf16* sA = As[buf];
        const bf16* sB = Bs[buf];
        #pragma unroll
        for (int ks = 0; ks < 32; ks += 16) {
            uint32_t af[2][4];
            #pragma unroll
            for (int mt = 0; mt < 2; mt++) {
                const bf16* p = sA + (wm + mt * 16 + g) * 40 + ks + t4 * 2;
                af[mt][0] = *(const uint32_t*)(p);
                af[mt][1] = *(const uint32_t*)(p + 8 * 40);
                af[mt][2] = *(const uint32_t*)(p + 8);
                af[mt][3] = *(const uint32_t*)(p + 8 * 40 + 8);
            }
            #pragma unroll
            for (int nt8 = 0; nt8 < 8; nt8++) {
                const bf16* p = sB + (wn + nt8 * 8 + g) * 40 + ks + t4 * 2;
                uint32_t b0 = *(const uint32_t*)(p);
                uint32_t b1 = *(const uint32_t*)(p + 8);
                mma16816(acc[0][nt8], af[0], b0, b1);
                mma16816(acc[1][nt8], af[1], b0, b1);
            }
        }
        if (it + 1 < nIt) {
            const int nb = buf ^ 1;
            *(uint4*)&As[nb][lrow * 40 + lseg]        = ra0;
            *(uint4*)&As[nb][(lrow + 64) * 40 + lseg] = ra1;
            *(uint4*)&Bs[nb][lrow * 40 + lseg]        = rb0;
            *(uint4*)&Bs[nb][(lrow + 64) * 40 + lseg] = rb1;
        }
        __syncthreads();
    }

    #pragma unroll
    for (int mt = 0; mt < 2; mt++) {
        #pragma unroll
        for (int nt8 = 0; nt8 < 8; nt8++) {
            int row = m0 + wm + mt * 16 + g;
            int col = n0 + wn + nt8 * 8 + t4 * 2;
            *(float2*)&C[(size_t)row * N + col] =
                make_float2(acc[mt][nt8][0], acc[mt][nt8][1]);
            *(float2*)&C[(size_t)(row + 8) * N + col] =
                make_float2(acc[mt][nt8][2], acc[mt][nt8][3]);
        }
    }
}

// ---------------- conversions ------------------------------------------------
__device__ __forceinline__ void split2(float v, bf16& hi, bf16& lo) {
    hi = __float2bfloat16_rn(v);
    lo = __float2bfloat16_rn(v - __bfloat162float(hi));
}

__global__ void conv_a(const float4* __restrict__ in, bf16* __restrict__ out, int K) {
    size_t idx = (size_t)blockIdx.x * 256 + threadIdx.x;
    float4 v = in[idx];
    int kq = K >> 2;
    size_t m = idx / kq;
    int k4 = (int)(idx % kq) * 4;
    bf16 h0,h1,h2,h3,l0,l1,l2,l3;
    split2(v.x,h0,l0); split2(v.y,h1,l1); split2(v.z,h2,l2); split2(v.w,h3,l3);
    __nv_bfloat162 hp0, hp1, lp0, lp1;
    hp0.x=h0; hp0.y=h1; hp1.x=h2; hp1.y=h3;
    lp0.x=l0; lp0.y=l1; lp1.x=l2; lp1.y=l3;
    bf16* o = out + m * (size_t)(3 * K) + k4;
    ((__nv_bfloat162*)o)[0] = hp0;          ((__nv_bfloat162*)o)[1] = hp1;
    ((__nv_bfloat162*)(o + K))[0] = hp0;    ((__nv_bfloat162*)(o + K))[1] = hp1;
    ((__nv_bfloat162*)(o + 2*K))[0] = lp0;  ((__nv_bfloat162*)(o + 2*K))[1] = lp1;
}

__global__ void conv_bT(const float* __restrict__ in, bf16* __restrict__ out,
                        int K, int N) {
    __shared__ float tile[32][33];
    int k0 = blockIdx.y * 32, n0 = blockIdx.x * 32;
    int tx = threadIdx.x & 31, ty = threadIdx.x >> 5;
    #pragma unroll
    for (int i = 0; i < 4; i++)
        tile[ty + 8*i][tx] = in[(size_t)(k0 + ty + 8*i) * N + n0 + tx];
    __syncthreads();
    #pragma unroll
    for (int i = 0; i < 4; i++) {
        int n = n0 + ty + 8*i, k = k0 + tx;
        float v = tile[tx][ty + 8*i];
        bf16 hi, lo; split2(v, hi, lo);
        bf16* o = out + (size_t)n * (3 * K);
        o[k] = hi; o[K + k] = lo; o[2*K + k] = hi;
    }
}

// [b,t,h,a] f32 -> [(b,h,t)][192] bf16; amode=1: [hi|hi|lo], amode=0: [hi|lo|hi]
__global__ void conv_qk(const float* __restrict__ in, bf16* __restrict__ out,
                        int amode) {
    int row  = blockIdx.x * 8 + (threadIdx.x >> 5);
    int lane = threadIdx.x & 31;
    int b = row >> 14, h = (row >> 10) & 15, tt = row & 1023;
    float2 v = *(const float2*)(in + (((size_t)b * 1024 + tt) * 16 + h) * 64 + lane * 2);
    bf16 h0,h1,l0,l1;
    split2(v.x,h0,l0); split2(v.y,h1,l1);
    __nv_bfloat162 hp, lp; hp.x=h0; hp.y=h1; lp.x=l0; lp.y=l1;
    __nv_bfloat162* o = (__nv_bfloat162*)(out + (size_t)row * 192) + lane;
    o[0]  = hp;
    o[32] = amode ? hp : lp;
    o[64] = amode ? lp : hp;
}

// g_v [b,k,h,a] -> g_vhi/g_vlo [(b,h), a, k]
__global__ void conv_vT() {
    __shared__ float tile[32][33];
    int bh = blockIdx.z, b = bh >> 4, h = bh & 15;
    int k0 = blockIdx.x * 32, a0 = blockIdx.y * 32;
    int tx = threadIdx.x & 31, ty = threadIdx.x >> 5;
    #pragma unroll
    for (int i = 0; i < 4; i++)
        tile[ty + 8*i][tx] =
            g_v[((((size_t)b << 10) + k0 + ty + 8*i) * 16 + h) * 64 + a0 + tx];
    __syncthreads();
    #pragma unroll
    for (int i = 0; i < 4; i++) {
        int a = a0 + ty + 8*i, k = k0 + tx;
        float v = tile[tx][ty + 8*i];
        bf16 hi, lo; split2(v, hi, lo);
        size_t o = ((size_t)bh * 64 + a) * 1024 + k;
        g_vhi[o] = hi;
        g_vlo[o] = lo;
    }
}

// ---------------- ksumT[(b,h),t] = sum_a k[b,t,h,a] -------------------------
__global__ void ksum_kernel() {
    int idx = blockIdx.x * blockDim.x + threadIdx.x;   // rows (b,t,h)
    const float* p = g_k + (size_t)idx * 64;
    float s = 0.f;
    #pragma unroll
    for (int i = 0; i < 16; i++) {
        float4 v = *(const float4*)(p + i*4);
        s += v.x + v.y + v.z + v.w;
    }
    int b = idx >> 14, tt = (idx >> 4) & 1023, h = idx & 15;
    g_ksumT[(((b << 4) + h) << 10) + tt] = s;
}

__global__ void proj_kernel(const float* __restrict__ embs,
                            const float* __restrict__ sc) {
    int t = threadIdx.x;
    if (t < 32) {
        float s = 0.f;
        #pragma unroll
        for (int a = 0; a < 64; a++) s += embs[t*64 + a] * sc[a];
        g_proj[t] = s;
    }
}

__global__ void detect_kernel(const void* __restrict__ ab, int E) {
    __shared__ int bad;
    if (threadIdx.x == 0) bad = 0;
    __syncthreads();
    int n = E < 256 ? E : 256;
    if ((int)threadIdx.x < n) {
        const long long* p = (const long long*)ab + (size_t)threadIdx.x * 4;
        long long et = p[0], bi = p[1], qi = p[2], ki = p[3];
        if (et < 0 || et >= 32 || bi < 0 || bi >= B_ ||
            qi < 0 || qi >= T_ || ki < 0 || ki >= T_) atomicExch(&bad, 1);
    }
    __syncthreads();
    if (threadIdx.x == 0) g_is64 = !bad;
}

__global__ void init_bs_kernel() {
    int i = blockIdx.x * blockDim.x + threadIdx.x;
    ((float4*)g_bs)[i]  = make_float4(0.f, 0.f, 0.f, 0.f);
    ((int4*)g_lastE)[i] = make_int4(-1, -1, -1, -1);
}

__device__ __forceinline__ void load_edge(const void* ab, int e,
                                          int& et, int& bi, int& qi, int& ki) {
    if (g_is64) {
        const long long* r = (const long long*)ab + (size_t)e * 4;
        et = (int)r[0]; bi = (int)r[1]; qi = (int)r[2]; ki = (int)r[3];
    } else {
        const int* r = (const int*)ab + (size_t)e * 4;
        et = r[0]; bi = r[1]; qi = r[2]; ki = r[3];
    }
}

__global__ void scatter_max_kernel(const void* __restrict__ ab, int E) {
    int e = blockIdx.x * blockDim.x + threadIdx.x;
    if (e >= E) return;
    int et, bi, qi, ki; load_edge(ab, e, et, bi, qi, ki);
    atomicMax(&g_lastE[((size_t)bi*T_ + qi)*T_ + ki], e);
}

__global__ void scatter_write_kernel(const void* __restrict__ ab, int E) {
    int e = blockIdx.x * blockDim.x + threadIdx.x;
    if (e >= E) return;
    int et, bi, qi, ki; load_edge(ab, e, et, bi, qi, ki);
    size_t idx = ((size_t)bi*T_ + qi)*T_ + ki;
    if (g_lastE[idx] == e) g_bs[idx] = g_proj[et];
}

// ---------------- flash attention: fused score+softmax+context ---------------
// grid (T/128, B*H), 256 threads (8 warps x 16 q-rows). K tile 64, 16 iters.
#define FL_QBYTES 51200
#define FL_STAGE  44032
#define FL_SMEM   (FL_QBYTES + 2*FL_STAGE)

__device__ __forceinline__ void cpa16(void* smem, const void* gmem) {
    uint32_t d = (uint32_t)__cvta_generic_to_shared(smem);
    asm volatile("cp.async.cg.shared.global [%0], [%1], 16;\n" :: "r"(d), "l"(gmem));
}

__device__ __forceinline__ void flash_load_kv(char* smem_raw, int t, int bh, int kt,
                                              int stage) {
    char* base = smem_raw + FL_QBYTES + stage * FL_STAGE;
    bf16* Ks = (bf16*)base;
    bf16* Vh = (bf16*)(base + 25600);
    bf16* Vl = (bf16*)(base + 25600 + 9216);
    const bf16* ksrc = g_kb + ((size_t)(bh << 10) + kt) * 192;
    #pragma unroll
    for (int i = 0; i < 6; i++) {
        int u = t + i * 256;
        int row = u / 24, c = u % 24;
        cpa16(&Ks[row * 200 + c * 8], &ksrc[(size_t)row * 192 + c * 8]);
    }
    const bf16* vh = g_vhi + (size_t)bh * 64 * 1024 + kt;
    const bf16* vl = g_vlo + (size_t)bh * 64 * 1024 + kt;
    #pragma unroll
    for (int i = 0; i < 2; i++) {
        int u = t + i * 256;
        int row = u >> 3, c = u & 7;
        cpa16(&Vh[row * 72 + c * 8], &vh[(size_t)row * 1024 + c * 8]);
        cpa16(&Vl[row * 72 + c * 8], &vl[(size_t)row * 1024 + c * 8]);
    }
    asm volatile("cp.async.commit_group;\n");
}

__global__ __launch_bounds__(256) void flash_kernel(const float* __restrict__ masks) {
    extern __shared__ char smem_raw[];
    bf16* Qs = (bf16*)smem_raw;                 // [128][200]
    const int t = threadIdx.x;
    const int w = t >> 5, lane = t & 31;
    const int g = lane >> 2, t4 = lane & 3;
    const int bh = blockIdx.y, b = bh >> 4, h = bh & 15;
    const int q0 = blockIdx.x * 128;

    // stage Q tile: 128 rows x 192 bf16 = 3072 16B chunks = 12 iters x 256 thr
    {
        const bf16* src = g_qs + ((size_t)(bh << 10) + q0) * 192;
        #pragma unroll
        for (int i = 0; i < 12; i++) {
            int u = t + i * 256;
            int row = u / 24, c = u % 24;
            *(uint4*)&Qs[row * 200 + c * 8] = *(const uint4*)&src[(size_t)row * 192 + c * 8];
        }
    }
    flash_load_kv(smem_raw, t, bh, 0, 0);
    flash_load_kv(smem_raw, t, bh, 64, 1);
    __syncthreads();

    // Q fragments -> registers (persistent)
    uint32_t qf[12][4];
    #pragma unroll
    for (int kc = 0; kc < 12; kc++) {
        const bf16* p = &Qs[(w * 16 + g) * 200 + kc * 16 + t4 * 2];
        qf[kc][0] = *(const uint32_t*)(p);
        qf[kc][1] = *(const uint32_t*)(p + 8 * 200);
        qf[kc][2] = *(const uint32_t*)(p + 8);
        qf[kc][3] = *(const uint32_t*)(p + 8 * 200 + 8);
    }

    const int r0 = q0 + w * 16 + g;
    float m0 = -1e38f, m1 = -1e38f, l0 = 0.f, l1 = 0.f;
    float oacc[8][4];
    #pragma unroll
    for (int nt = 0; nt < 8; nt++)
        #pragma unroll
        for (int c = 0; c < 4; c++) oacc[nt][c] = 0.f;

    const float C1 = 0.125f * 1.44269504f;
    const float C2 = 1.44269504e30f;

    for (int it = 0; it < 16; it++) {
        if (it < 15) asm volatile("cp.async.wait_group 1;\n");
        else         asm volatile("cp.async.wait_group 0;\n");
        __syncthreads();
        const int stage = it & 1;
        char* base = smem_raw + FL_QBYTES + stage * FL_STAGE;
        const bf16* Ks = (const bf16*)base;
        const bf16* Vh = (const bf16*)(base + 25600);
        const bf16* Vl = (const bf16*)(base + 25600 + 9216);
        const int kt = it * 64;

        // S = Q K^T (split-bf16, K3=192)
        float sacc[8][4];
        #pragma unroll
        for (int nt = 0; nt < 8; nt++)
            #pragma unroll
            for (int c = 0; c < 4; c++) sacc[nt][c] = 0.f;
        #pragma unroll
        for (int kc = 0; kc < 12; kc++)
            #pragma unroll
            for (int nt = 0; nt < 8; nt++) {
                const bf16* p = &Ks[(nt * 8 + g) * 200 + kc * 16 + t4 * 2];
                uint32_t b0 = *(const uint32_t*)(p);
                uint32_t b1 = *(const uint32_t*)(p + 8);
                mma16816(sacc[nt], qf[kc], b0, b1);
            }

        // epilogue: + bs*ksum, scale, mask; log2 domain
        float mt0 = -1e38f, mt1 = -1e38f;
        #pragma unroll
        for (int nt = 0; nt < 8; nt++) {
            int c0 = kt + nt * 8 + t4 * 2;
            float2 ks2 = *(const float2*)&g_ksumT[((size_t)bh << 10) + c0];
            size_t mb0 = ((((size_t)b << 10) + r0) << 10) + c0;
            size_t mb1 = ((((size_t)b << 10) + r0 + 8) << 10) + c0;
            float2 bs0 = *(const float2*)&g_bs[mb0];
            float2 mk0 = *(const float2*)&masks[mb0];
            float2 bs1 = *(const float2*)&g_bs[mb1];
            float2 mk1 = *(const float2*)&masks[mb1];
            sacc[nt][0] = (sacc[nt][0] + bs0.x * ks2.x) * C1 - mk0.x * C2;
            sacc[nt][1] = (sacc[nt][1] + bs0.y * ks2.y) * C1 - mk0.y * C2;
            sacc[nt][2] = (sacc[nt][2] + bs1.x * ks2.x) * C1 - mk1.x * C2;
            sacc[nt][3] = (sacc[nt][3] + bs1.y * ks2.y) * C1 - mk1.y * C2;
            mt0 = fmaxf(mt0, fmaxf(sacc[nt][0], sacc[nt][1]));
            mt1 = fmaxf(mt1, fmaxf(sacc[nt][2], sacc[nt][3]));
        }
        mt0 = fmaxf(mt0, __shfl_xor_sync(0xffffffffu, mt0, 1));
        mt0 = fmaxf(mt0, __shfl_xor_sync(0xffffffffu, mt0, 2));
        mt1 = fmaxf(mt1, __shfl_xor_sync(0xffffffffu, mt1, 1));
        mt1 = fmaxf(mt1, __shfl_xor_sync(0xffffffffu, mt1, 2));
        float mn0 = fmaxf(m0, mt0), mn1 = fmaxf(m1, mt1);
        float sc0 = ex2f(m0 - mn0), sc1 = ex2f(m1 - mn1);
        m0 = mn0; m1 = mn1;
        l0 *= sc0; l1 *= sc1;

        uint32_t phi0[8], phi1[8], plo0[8], plo1[8];
        #pragma unroll
        for (int nt = 0; nt < 8; nt++) {
            float p0 = ex2f(sacc[nt][0] - m0), p1 = ex2f(sacc[nt][1] - m0);
            float p2 = ex2f(sacc[nt][2] - m1), p3 = ex2f(sacc[nt][3] - m1);
            l0 += p0 + p1; l1 += p2 + p3;
            __nv_bfloat162 h0 = __floats2bfloat162_rn(p0, p1);
            float2 f0 = __bfloat1622float2(h0);
            __nv_bfloat162 e0 = __floats2bfloat162_rn(p0 - f0.x, p1 - f0.y);
            __nv_bfloat162 h1 = __floats2bfloat162_rn(p2, p3);
            float2 f1 = __bfloat1622float2(h1);
            __nv_bfloat162 e1 = __floats2bfloat162_rn(p2 - f1.x, p3 - f1.y);
            phi0[nt] = *(uint32_t*)&h0; plo0[nt] = *(uint32_t*)&e0;
            phi1[nt] = *(uint32_t*)&h1; plo1[nt] = *(uint32_t*)&e1;
            oacc[nt][0] *= sc0; oacc[nt][1] *= sc0;
            oacc[nt][2] *= sc1; oacc[nt][3] *= sc1;
        }

        // O += P * V  (3-term split)
        #pragma unroll
        for (int kc = 0; kc < 4; kc++) {
            uint32_t ah[4] = {phi0[2*kc], phi1[2*kc], phi0[2*kc+1], phi1[2*kc+1]};
            uint32_t al[4] = {plo0[2*kc], plo1[2*kc], plo0[2*kc+1], plo1[2*kc+1]};
            #pragma unroll
            for (int nt = 0; nt < 8; nt++) {
                const bf16* ph = &Vh[(nt * 8 + g) * 72 + kc * 16 + t4 * 2];
                const bf16* pl = &Vl[(nt * 8 + g) * 72 + kc * 16 + t4 * 2];
                uint32_t bh0 = *(const uint32_t*)(ph);
                uint32_t bh1 = *(const uint32_t*)(ph + 8);
                uint32_t bl0 = *(const uint32_t*)(pl);
                uint32_t bl1 = *(const uint32_t*)(pl + 8);
                mma16816(oacc[nt], ah, bh0, bh1);
                mma16816(oacc[nt], ah, bl0, bl1);
                mma16816(oacc[nt], al, bh0, bh1);
            }
        }
        __syncthreads();
        if (it + 2 < 16) flash_load_kv(smem_raw, t, bh, (it + 2) * 64, stage);
    }

    // final: normalize, write ctx directly in split-bf16 [hi|hi|lo] layout
    l0 += __shfl_xor_sync(0xffffffffu, l0, 1);
    l0 += __shfl_xor_sync(0xffffffffu, l0, 2);
    l1 += __shfl_xor_sync(0xffffffffu, l1, 1);
    l1 += __shfl_xor_sync(0xffffffffu, l1, 2);
    float inv0 = 1.0f / l0, inv1 = 1.0f / l1;
    size_t rowA0 = ((size_t)b << 10) + r0;
    size_t rowA1 = rowA0 + 8;
    #pragma unroll
    for (int nt = 0; nt < 8; nt++) {
        int col = (h << 6) + nt * 8 + t4 * 2;
        float o0 = oacc[nt][0] * inv0, o1 = oacc[nt][1] * inv0;
        float o2 = oacc[nt][2] * inv1, o3 = oacc[nt][3] * inv1;
        __nv_bfloat162 H0 = __floats2bfloat162_rn(o0, o1);
        float2 F0 = __bfloat1622float2(H0);
        __nv_bfloat162 L0 = __floats2bfloat162_rn(o0 - F0.x, o1 - F0.y);
        __nv_bfloat162 H1 = __floats2bfloat162_rn(o2, o3);
        float2 F1 = __bfloat1622float2(H1);
        __nv_bfloat162 L1 = __floats2bfloat162_rn(o2 - F1.x, o3 - F1.y);
        bf16* d0 = g_sa + rowA0 * 3072 + col;
        bf16* d1 = g_sa + rowA1 * 3072 + col;
        *(__nv_bfloat162*)(d0)        = H0;
        *(__nv_bfloat162*)(d0 + 1024) = H0;
        *(__nv_bfloat162*)(d0 + 2048) = L0;
        *(__nv_bfloat162*)(d1)        = H1;
        *(__nv_bfloat162*)(d1 + 1024) = H1;
        *(__nv_bfloat162*)(d1 + 2048) = L1;
    }
}

// ---------------- launch ----------------------------------------------------
extern "C" void kernel_launch(void* const* d_in, const int* in_sizes, int n_in,
                              void* d_out, int out_size) {
    const float* states      = (const float*)d_in[0];
    const float* keys        = (const float*)d_in[1];
    const float* masks       = (const float*)d_in[2];
    const void*  abias       = (const void*) d_in[3];
    const float* Wq          = (const float*)d_in[4];
    const float* Wk          = (const float*)d_in[5];
    const float* Wv          = (const float*)d_in[6];
    const float* Wout        = (const float*)d_in[7];
    const float* bias_embs   = (const float*)d_in[8];
    const float* bias_scalar = (const float*)d_in[9];
    float* out = (float*)d_out;
    int E = in_sizes[3] / 4;

    cudaFuncSetAttribute(flash_kernel,
                         cudaFuncAttributeMaxDynamicSharedMemorySize, FL_SMEM);

    float *pq, *pk, *pv;
    bf16 *psa, *pka, *pwq, *pwk, *pwv, *pwo, *pqs, *pkb;
    cudaGetSymbolAddress((void**)&pq,  g_q);
    cudaGetSymbolAddress((void**)&pk,  g_k);
    cudaGetSymbolAddress((void**)&pv,  g_v);
    cudaGetSymbolAddress((void**)&psa, g_sa);
    cudaGetSymbolAddress((void**)&pka, g_ka);
    cudaGetSymbolAddress((void**)&pwq, g_wq);
    cudaGetSymbolAddress((void**)&pwk, g_wk);
    cudaGetSymbolAddress((void**)&pwv, g_wv);
    cudaGetSymbolAddress((void**)&pwo, g_wo);
    cudaGetSymbolAddress((void**)&pqs, g_qs);
    cudaGetSymbolAddress((void**)&pkb, g_kb);

    // conversions
    conv_a<<<8192, 256>>>((const float4*)states, psa, 1024);
    conv_a<<<8192, 256>>>((const float4*)keys,   pka, 1024);
    dim3 gt(32, 32);
    conv_bT<<<gt, 256>>>(Wq,   pwq, 1024, 1024);
    conv_bT<<<gt, 256>>>(Wk,   pwk, 1024, 1024);
    conv_bT<<<gt, 256>>>(Wv,   pwv, 1024, 1024);
    conv_bT<<<gt, 256>>>(Wout, pwo, 1024, 1024);

    // projections on tensor cores
    dim3 gg(8, 64);
    gemm_nt<<<gg, 256>>>(psa, pwq, pq, 8192, 1024, 3072);
    gemm_nt<<<gg, 256>>>(pka, pwk, pk, 8192, 1024, 3072);
    gemm_nt<<<gg, 256>>>(pka, pwv, pv, 8192, 1024, 3072);

    // side computations
    ksum_kernel<<<(B_*T_*H_)/256, 256>>>();
    proj_kernel<<<1, 32>>>(bias_embs, bias_scalar);
    detect_kernel<<<1, 256>>>(abias, E);
    init_bs_kernel<<<(B_*T_*T_/4)/256, 256>>>();
    scatter_max_kernel<<<(E + 255)/256, 256>>>(abias, E);
    scatter_write_kernel<<<(E + 255)/256, 256>>>(abias, E);

    // operand prep for flash
    conv_qk<<<B_*H_*T_/8, 256>>>(pq, pqs, 1);
    conv_qk<<<B_*H_*T_/8, 256>>>(pk, pkb, 0);
    dim3 gv(32, 2, 128);
    conv_vT<<<gv, 256>>>();

    // fused attention (writes ctx split-bf16 into g_sa)
    dim3 gf(T_/128, B_*H_);
    flash_kernel<<<gf, 256, FL_SMEM>>>(masks);

    // output projection
    gemm_nt<<<gg, 256>>>(psa, pwo, out, 8192, 1024, 3072);
}

// round 9
// speedup vs baseline: 3.7338x; 1.1865x over previous
#include <cuda_runtime.h>
#include <cuda_bf16.h>
#include <cstdint>

#define B_ 8
#define T_ 1024
#define D_ 1024
#define H_ 16
#define A_ 64

typedef __nv_bfloat16 bf16;

// ---------------- scratch (device globals: allocation-free) ----------------
__device__ float g_q[B_*T_*H_*A_];          // [b,t,h,a]
__device__ float g_k[B_*T_*H_*A_];
__device__ float g_v[B_*T_*H_*A_];
__device__ float g_ksumT[B_*H_*T_];         // [(b,h),t]
__device__ float g_bs[B_*T_*T_];            // [b,q,k]
__device__ int   g_lastE[B_*T_*T_];
__device__ float g_proj[32];
__device__ int   g_is64;

// split-bf16 operands
__device__ __align__(16) bf16 g_sa[8192*3072];          // states-split, later ctx-split
__device__ __align__(16) bf16 g_ka[8192*3072];          // keys-split
__device__ __align__(16) bf16 g_wq[1024*3072];
__device__ __align__(16) bf16 g_wk[1024*3072];
__device__ __align__(16) bf16 g_wv[1024*3072];
__device__ __align__(16) bf16 g_wo[1024*3072];
__device__ __align__(16) bf16 g_qs[B_*H_*T_*192];       // Q split [hi|hi|lo], rows (b,h,t)
__device__ __align__(16) bf16 g_kb[B_*H_*T_*192];       // K split [hi|lo|hi], rows (b,h,t)
__device__ __align__(16) bf16 g_vhi[B_*H_*A_*T_];       // [(b,h),a,k]
__device__ __align__(16) bf16 g_vlo[B_*H_*A_*T_];

// ---------------- mma.sync m16n8k16 bf16 ------------------------------------
__device__ __forceinline__ void mma16816(float* d, const uint32_t* a,
                                         uint32_t b0, uint32_t b1) {
    asm volatile(
        "mma.sync.aligned.m16n8k16.row.col.f32.bf16.bf16.f32 "
        "{%0,%1,%2,%3}, {%4,%5,%6,%7}, {%8,%9}, {%0,%1,%2,%3};\n"
        : "+f"(d[0]), "+f"(d[1]), "+f"(d[2]), "+f"(d[3])
        : "r"(a[0]), "r"(a[1]), "r"(a[2]), "r"(a[3]), "r"(b0), "r"(b1));
}

__device__ __forceinline__ void ldsm_x4(uint32_t& r0, uint32_t& r1,
                                        uint32_t& r2, uint32_t& r3, uint32_t addr) {
    asm volatile("ldmatrix.sync.aligned.m8n8.x4.shared.b16 {%0,%1,%2,%3}, [%4];"
                 : "=r"(r0), "=r"(r1), "=r"(r2), "=r"(r3) : "r"(addr));
}

__device__ __forceinline__ float ex2f(float x) {
    float r;
    asm("ex2.approx.f32 %0, %1;" : "=f"(r) : "f"(x));
    return r;
}

__device__ __forceinline__ void cpa16s(uint32_t smem, const void* gmem) {
    asm volatile("cp.async.cg.shared.global [%0], [%1], 16;\n"
                 :: "r"(smem), "l"(gmem));
}

// ---------------- pipelined ldmatrix NT GEMM: C = A[M,K3] * Bt[N,K3]^T ------
// 128x128 block tile, BK=32, 256 threads (8 warps: 4m x 2n), 4-stage cp.async.
// Smem per stage: A 128x32 bf16 (8KB, 64B rows) + B 128x32 (8KB).
// Swizzle: 16B chunk c at row r stored at chunk (c ^ ((r>>1)&3)).
#define GNS 4
#define GSB 16384
#define GSMEM (GNS*GSB)

__device__ __forceinline__ void g_ld_stage(uint32_t sb, const bf16* Ag,
                                           const bf16* Bg, int K3, int k0, int t) {
    #pragma unroll
    for (int i = 0; i < 2; i++) {
        int j = t + (i << 8);              // 0..511
        int row = j >> 2, c = j & 3;
        uint32_t sw = (uint32_t)((c ^ ((row >> 1) & 3)) << 4);
        const bf16* ga = Ag + (size_t)row * K3 + k0 + c * 8;
        const bf16* gb = Bg + (size_t)row * K3 + k0 + c * 8;
        cpa16s(sb + row * 64 + sw, ga);
        cpa16s(sb + 8192 + row * 64 + sw, gb);
    }
}

__global__ __launch_bounds__(256) void gemm_nt(
    const bf16* __restrict__ A, const bf16* __restrict__ Bt,
    float* __restrict__ C, int M, int N, int K3)
{
    extern __shared__ char gsm[];
    const uint32_t dbase = (uint32_t)__cvta_generic_to_shared(gsm);
    const int t = threadIdx.x;
    const int m0 = blockIdx.y * 128, n0 = blockIdx.x * 128;
    const bf16* Ag = A  + (size_t)m0 * K3;
    const bf16* Bg = Bt + (size_t)n0 * K3;

    const int w = t >> 5, lane = t & 31;
    const int wm = (w & 3) * 32, wn = (w >> 2) * 64;
    const int g  = lane >> 2, t4 = lane & 3;
    const int lrow = lane & 15;            // ldmatrix row within 16-row group
    const int lchk = lane >> 4;            // 0/1: k-chunk selector

    float acc[2][8][4];
    #pragma unroll
    for (int i = 0; i < 2; i++)
        #pragma unroll
        for (int j = 0; j < 8; j++)
            #pragma unroll
            for (int c = 0; c < 4; c++) acc[i][j][c] = 0.f;

    const int nIt = K3 >> 5;               // 96 for K3=3072
    // prologue: stages 0..2
    #pragma unroll
    for (int s = 0; s < GNS - 1; s++) {
        g_ld_stage(dbase + s * GSB, Ag, Bg, K3, s << 5, t);
        asm volatile("cp.async.commit_group;\n");
    }

    for (int i = 0; i < nIt; i++) {
        asm volatile("cp.async.wait_group %0;\n" :: "n"(GNS - 2));
        __syncthreads();
        if (i + GNS - 1 < nIt)
            g_ld_stage(dbase + ((i + 3) & 3) * GSB, Ag, Bg, K3, (i + 3) << 5, t);
        asm volatile("cp.async.commit_group;\n");

        const uint32_t sA = dbase + (i & 3) * GSB;
        const uint32_t sB = sA + 8192;

        #pragma unroll
        for (int k16 = 0; k16 < 2; k16++) {
            const int kc2 = k16 * 2;
            // A fragments (2 m16 tiles)
            uint32_t af[2][4];
            #pragma unroll
            for (int mt = 0; mt < 2; mt++) {
                int row = wm + mt * 16 + lrow;
                int chk = kc2 + lchk;
                uint32_t addr = sA + row * 64 + ((chk ^ ((row >> 1) & 3)) << 4);
                ldsm_x4(af[mt][0], af[mt][1], af[mt][2], af[mt][3], addr);
            }
            // B fragments (4 n16 tiles) + mma
            #pragma unroll
            for (int nq = 0; nq < 4; nq++) {
                int row = wn + nq * 16 + lrow;
                int chk = kc2 + lchk;
                uint32_t addr = sB + row * 64 + ((chk ^ ((row >> 1) & 3)) << 4);
                uint32_t r0, r1, r2, r3;
                ldsm_x4(r0, r1, r2, r3, addr);
                mma16816(acc[0][nq*2+0], af[0], r0, r2);
                mma16816(acc[0][nq*2+1], af[0], r1, r3);
                mma16816(acc[1][nq*2+0], af[1], r0, r2);
                mma16816(acc[1][nq*2+1], af[1], r1, r3);
            }
        }
    }

    #pragma unroll
    for (int mt = 0; mt < 2; mt++) {
        #pragma unroll
        for (int nt8 = 0; nt8 < 8; nt8++) {
            int row = m0 + wm + mt * 16 + g;
            int col = n0 + wn + nt8 * 8 + t4 * 2;
            *(float2*)&C[(size_t)row * N + col] =
                make_float2(acc[mt][nt8][0], acc[mt][nt8][1]);
            *(float2*)&C[(size_t)(row + 8) * N + col] =
                make_float2(acc[mt][nt8][2], acc[mt][nt8][3]);
        }
    }
}

// ---------------- conversions ------------------------------------------------
__device__ __forceinline__ void split2(float v, bf16& hi, bf16& lo) {
    hi = __float2bfloat16_rn(v);
    lo = __float2bfloat16_rn(v - __bfloat162float(hi));
}

__global__ void conv_a(const float4* __restrict__ in, bf16* __restrict__ out, int K) {
    size_t idx = (size_t)blockIdx.x * 256 + threadIdx.x;
    float4 v = in[idx];
    int kq = K >> 2;
    size_t m = idx / kq;
    int k4 = (int)(idx % kq) * 4;
    bf16 h0,h1,h2,h3,l0,l1,l2,l3;
    split2(v.x,h0,l0); split2(v.y,h1,l1); split2(v.z,h2,l2); split2(v.w,h3,l3);
    __nv_bfloat162 hp0, hp1, lp0, lp1;
    hp0.x=h0; hp0.y=h1; hp1.x=h2; hp1.y=h3;
    lp0.x=l0; lp0.y=l1; lp1.x=l2; lp1.y=l3;
    bf16* o = out + m * (size_t)(3 * K) + k4;
    ((__nv_bfloat162*)o)[0] = hp0;          ((__nv_bfloat162*)o)[1] = hp1;
    ((__nv_bfloat162*)(o + K))[0] = hp0;    ((__nv_bfloat162*)(o + K))[1] = hp1;
    ((__nv_bfloat162*)(o + 2*K))[0] = lp0;  ((__nv_bfloat162*)(o + 2*K))[1] = lp1;
}

__global__ void conv_bT(const float* __restrict__ in, bf16* __restrict__ out,
                        int K, int N) {
    __shared__ float tile[32][33];
    int k0 = blockIdx.y * 32, n0 = blockIdx.x * 32;
    int tx = threadIdx.x & 31, ty = threadIdx.x >> 5;
    #pragma unroll
    for (int i = 0; i < 4; i++)
        tile[ty + 8*i][tx] = in[(size_t)(k0 + ty + 8*i) * N + n0 + tx];
    __syncthreads();
    #pragma unroll
    for (int i = 0; i < 4; i++) {
        int n = n0 + ty + 8*i, k = k0 + tx;
        float v = tile[tx][ty + 8*i];
        bf16 hi, lo; split2(v, hi, lo);
        bf16* o = out + (size_t)n * (3 * K);
        o[k] = hi; o[K + k] = lo; o[2*K + k] = hi;
    }
}

// [b,t,h,a] f32 -> [(b,h,t)][192] bf16; amode=1: [hi|hi|lo], amode=0: [hi|lo|hi]
__global__ void conv_qk(const float* __restrict__ in, bf16* __restrict__ out,
                        int amode) {
    int row  = blockIdx.x * 8 + (threadIdx.x >> 5);
    int lane = threadIdx.x & 31;
    int b = row >> 14, h = (row >> 10) & 15, tt = row & 1023;
    float2 v = *(const float2*)(in + (((size_t)b * 1024 + tt) * 16 + h) * 64 + lane * 2);
    bf16 h0,h1,l0,l1;
    split2(v.x,h0,l0); split2(v.y,h1,l1);
    __nv_bfloat162 hp, lp; hp.x=h0; hp.y=h1; lp.x=l0; lp.y=l1;
    __nv_bfloat162* o = (__nv_bfloat162*)(out + (size_t)row * 192) + lane;
    o[0]  = hp;
    o[32] = amode ? hp : lp;
    o[64] = amode ? lp : hp;
}

// g_v [b,k,h,a] -> g_vhi/g_vlo [(b,h), a, k]
__global__ void conv_vT() {
    __shared__ float tile[32][33];
    int bh = blockIdx.z, b = bh >> 4, h = bh & 15;
    int k0 = blockIdx.x * 32, a0 = blockIdx.y * 32;
    int tx = threadIdx.x & 31, ty = threadIdx.x >> 5;
    #pragma unroll
    for (int i = 0; i < 4; i++)
        tile[ty + 8*i][tx] =
            g_v[((((size_t)b << 10) + k0 + ty + 8*i) * 16 + h) * 64 + a0 + tx];
    __syncthreads();
    #pragma unroll
    for (int i = 0; i < 4; i++) {
        int a = a0 + ty + 8*i, k = k0 + tx;
        float v = tile[tx][ty + 8*i];
        bf16 hi, lo; split2(v, hi, lo);
        size_t o = ((size_t)bh * 64 + a) * 1024 + k;
        g_vhi[o] = hi;
        g_vlo[o] = lo;
    }
}

// ---------------- ksumT[(b,h),t] = sum_a k[b,t,h,a] -------------------------
__global__ void ksum_kernel() {
    int idx = blockIdx.x * blockDim.x + threadIdx.x;
    const float* p = g_k + (size_t)idx * 64;
    float s = 0.f;
    #pragma unroll
    for (int i = 0; i < 16; i++) {
        float4 v = *(const float4*)(p + i*4);
        s += v.x + v.y + v.z + v.w;
    }
    int b = idx >> 14, tt = (idx >> 4) & 1023, h = idx & 15;
    g_ksumT[(((b << 4) + h) << 10) + tt] = s;
}

__global__ void proj_kernel(const float* __restrict__ embs,
                            const float* __restrict__ sc) {
    int t = threadIdx.x;
    if (t < 32) {
        float s = 0.f;
        #pragma unroll
        for (int a = 0; a < 64; a++) s += embs[t*64 + a] * sc[a];
        g_proj[t] = s;
    }
}

__global__ void detect_kernel(const void* __restrict__ ab, int E) {
    __shared__ int bad;
    if (threadIdx.x == 0) bad = 0;
    __syncthreads();
    int n = E < 256 ? E : 256;
    if ((int)threadIdx.x < n) {
        const long long* p = (const long long*)ab + (size_t)threadIdx.x * 4;
        long long et = p[0], bi = p[1], qi = p[2], ki = p[3];
        if (et < 0 || et >= 32 || bi < 0 || bi >= B_ ||
            qi < 0 || qi >= T_ || ki < 0 || ki >= T_) atomicExch(&bad, 1);
    }
    __syncthreads();
    if (threadIdx.x == 0) g_is64 = !bad;
}

__global__ void init_bs_kernel() {
    int i = blockIdx.x * blockDim.x + threadIdx.x;
    ((float4*)g_bs)[i]  = make_float4(0.f, 0.f, 0.f, 0.f);
    ((int4*)g_lastE)[i] = make_int4(-1, -1, -1, -1);
}

__device__ __forceinline__ void load_edge(const void* ab, int e,
                                          int& et, int& bi, int& qi, int& ki) {
    if (g_is64) {
        const long long* r = (const long long*)ab + (size_t)e * 4;
        et = (int)r[0]; bi = (int)r[1]; qi = (int)r[2]; ki = (int)r[3];
    } else {
        const int* r = (const int*)ab + (size_t)e * 4;
        et = r[0]; bi = r[1]; qi = r[2]; ki = r[3];
    }
}

__global__ void scatter_max_kernel(const void* __restrict__ ab, int E) {
    int e = blockIdx.x * blockDim.x + threadIdx.x;
    if (e >= E) return;
    int et, bi, qi, ki; load_edge(ab, e, et, bi, qi, ki);
    atomicMax(&g_lastE[((size_t)bi*T_ + qi)*T_ + ki], e);
}

__global__ void scatter_write_kernel(const void* __restrict__ ab, int E) {
    int e = blockIdx.x * blockDim.x + threadIdx.x;
    if (e >= E) return;
    int et, bi, qi, ki; load_edge(ab, e, et, bi, qi, ki);
    size_t idx = ((size_t)bi*T_ + qi)*T_ + ki;
    if (g_lastE[idx] == e) g_bs[idx] = g_proj[et];
}

// ---------------- flash attention: fused score+softmax+context ---------------
#define FL_QBYTES 51200
#define FL_STAGE  44032
#define FL_SMEM   (FL_QBYTES + 2*FL_STAGE)

__device__ __forceinline__ void cpa16(void* smem, const void* gmem) {
    uint32_t d = (uint32_t)__cvta_generic_to_shared(smem);
    asm volatile("cp.async.cg.shared.global [%0], [%1], 16;\n" :: "r"(d), "l"(gmem));
}

__device__ __forceinline__ void flash_load_kv(char* smem_raw, int t, int bh, int kt,
                                              int stage) {
    char* base = smem_raw + FL_QBYTES + stage * FL_STAGE;
    bf16* Ks = (bf16*)base;
    bf16* Vh = (bf16*)(base + 25600);
    bf16* Vl = (bf16*)(base + 25600 + 9216);
    const bf16* ksrc = g_kb + ((size_t)(bh << 10) + kt) * 192;
    #pragma unroll
    for (int i = 0; i < 6; i++) {
        int u = t + i * 256;
        int row = u / 24, c = u % 24;
        cpa16(&Ks[row * 200 + c * 8], &ksrc[(size_t)row * 192 + c * 8]);
    }
    const bf16* vh = g_vhi + (size_t)bh * 64 * 1024 + kt;
    const bf16* vl = g_vlo + (size_t)bh * 64 * 1024 + kt;
    #pragma unroll
    for (int i = 0; i < 2; i++) {
        int u = t + i * 256;
        int row = u >> 3, c = u & 7;
        cpa16(&Vh[row * 72 + c * 8], &vh[(size_t)row * 1024 + c * 8]);
        cpa16(&Vl[row * 72 + c * 8], &vl[(size_t)row * 1024 + c * 8]);
    }
    asm volatile("cp.async.commit_group;\n");
}

__global__ __launch_bounds__(256) void flash_kernel(const float* __restrict__ masks) {
    extern __shared__ char smem_raw[];
    bf16* Qs = (bf16*)smem_raw;                 // [128][200]
    const int t = threadIdx.x;
    const int w = t >> 5, lane = t & 31;
    const int g = lane >> 2, t4 = lane & 3;
    const int bh = blockIdx.y, b = bh >> 4, h = bh & 15;
    const int q0 = blockIdx.x * 128;

    {
        const bf16* src = g_qs + ((size_t)(bh << 10) + q0) * 192;
        #pragma unroll
        for (int i = 0; i < 12; i++) {
            int u = t + i * 256;
            int row = u / 24, c = u % 24;
            *(uint4*)&Qs[row * 200 + c * 8] = *(const uint4*)&src[(size_t)row * 192 + c * 8];
        }
    }
    flash_load_kv(smem_raw, t, bh, 0, 0);
    flash_load_kv(smem_raw, t, bh, 64, 1);
    __syncthreads();

    uint32_t qf[12][4];
    #pragma unroll
    for (int kc = 0; kc < 12; kc++) {
        const bf16* p = &Qs[(w * 16 + g) * 200 + kc * 16 + t4 * 2];
        qf[kc][0] = *(const uint32_t*)(p);
        qf[kc][1] = *(const uint32_t*)(p + 8 * 200);
        qf[kc][2] = *(const uint32_t*)(p + 8);
        qf[kc][3] = *(const uint32_t*)(p + 8 * 200 + 8);
    }

    const int r0 = q0 + w * 16 + g;
    float m0 = -1e38f, m1 = -1e38f, l0 = 0.f, l1 = 0.f;
    float oacc[8][4];
    #pragma unroll
    for (int nt = 0; nt < 8; nt++)
        #pragma unroll
        for (int c = 0; c < 4; c++) oacc[nt][c] = 0.f;

    const float C1 = 0.125f * 1.44269504f;
    const float C2 = 1.44269504e30f;

    for (int it = 0; it < 16; it++) {
        if (it < 15) asm volatile("cp.async.wait_group 1;\n");
        else         asm volatile("cp.async.wait_group 0;\n");
        __syncthreads();
        const int stage = it & 1;
        char* base = smem_raw + FL_QBYTES + stage * FL_STAGE;
        const bf16* Ks = (const bf16*)base;
        const bf16* Vh = (const bf16*)(base + 25600);
        const bf16* Vl = (const bf16*)(base + 25600 + 9216);
        const int kt = it * 64;

        float sacc[8][4];
        #pragma unroll
        for (int nt = 0; nt < 8; nt++)
            #pragma unroll
            for (int c = 0; c < 4; c++) sacc[nt][c] = 0.f;
        #pragma unroll
        for (int kc = 0; kc < 12; kc++)
            #pragma unroll
            for (int nt = 0; nt < 8; nt++) {
                const bf16* p = &Ks[(nt * 8 + g) * 200 + kc * 16 + t4 * 2];
                uint32_t b0 = *(const uint32_t*)(p);
                uint32_t b1 = *(const uint32_t*)(p + 8);
                mma16816(sacc[nt], qf[kc], b0, b1);
            }

        float mt0 = -1e38f, mt1 = -1e38f;
        #pragma unroll
        for (int nt = 0; nt < 8; nt++) {
            int c0 = kt + nt * 8 + t4 * 2;
            float2 ks2 = *(const float2*)&g_ksumT[((size_t)bh << 10) + c0];
            size_t mb0 = ((((size_t)b << 10) + r0) << 10) + c0;
            size_t mb1 = ((((size_t)b << 10) + r0 + 8) << 10) + c0;
            float2 bs0 = *(const float2*)&g_bs[mb0];
            float2 mk0 = *(const float2*)&masks[mb0];
            float2 bs1 = *(const float2*)&g_bs[mb1];
            float2 mk1 = *(const float2*)&masks[mb1];
            sacc[nt][0] = (sacc[nt][0] + bs0.x * ks2.x) * C1 - mk0.x * C2;
            sacc[nt][1] = (sacc[nt][1] + bs0.y * ks2.y) * C1 - mk0.y * C2;
            sacc[nt][2] = (sacc[nt][2] + bs1.x * ks2.x) * C1 - mk1.x * C2;
            sacc[nt][3] = (sacc[nt][3] + bs1.y * ks2.y) * C1 - mk1.y * C2;
            mt0 = fmaxf(mt0, fmaxf(sacc[nt][0], sacc[nt][1]));
            mt1 = fmaxf(mt1, fmaxf(sacc[nt][2], sacc[nt][3]));
        }
        mt0 = fmaxf(mt0, __shfl_xor_sync(0xffffffffu, mt0, 1));
        mt0 = fmaxf(mt0, __shfl_xor_sync(0xffffffffu, mt0, 2));
        mt1 = fmaxf(mt1, __shfl_xor_sync(0xffffffffu, mt1, 1));
        mt1 = fmaxf(mt1, __shfl_xor_sync(0xffffffffu, mt1, 2));
        float mn0 = fmaxf(m0, mt0), mn1 = fmaxf(m1, mt1);
        float sc0 = ex2f(m0 - mn0), sc1 = ex2f(m1 - mn1);
        m0 = mn0; m1 = mn1;
        l0 *= sc0; l1 *= sc1;

        uint32_t phi0[8], phi1[8], plo0[8], plo1[8];
        #pragma unroll
        for (int nt = 0; nt < 8; nt++) {
            float p0 = ex2f(sacc[nt][0] - m0), p1 = ex2f(sacc[nt][1] - m0);
            float p2 = ex2f(sacc[nt][2] - m1), p3 = ex2f(sacc[nt][3] - m1);
            l0 += p0 + p1; l1 += p2 + p3;
            __nv_bfloat162 h0 = __floats2bfloat162_rn(p0, p1);
            float2 f0 = __bfloat1622float2(h0);
            __nv_bfloat162 e0 = __floats2bfloat162_rn(p0 - f0.x, p1 - f0.y);
            __nv_bfloat162 h1 = __floats2bfloat162_rn(p2, p3);
            float2 f1 = __bfloat1622float2(h1);
            __nv_bfloat162 e1 = __floats2bfloat162_rn(p2 - f1.x, p3 - f1.y);
            phi0[nt] = *(uint32_t*)&h0; plo0[nt] = *(uint32_t*)&e0;
            phi1[nt] = *(uint32_t*)&h1; plo1[nt] = *(uint32_t*)&e1;
            oacc[nt][0] *= sc0; oacc[nt][1] *= sc0;
            oacc[nt][2] *= sc1; oacc[nt][3] *= sc1;
        }

        #pragma unroll
        for (int kc = 0; kc < 4; kc++) {
            uint32_t ah[4] = {phi0[2*kc], phi1[2*kc], phi0[2*kc+1], phi1[2*kc+1]};
            uint32_t al[4] = {plo0[2*kc], plo1[2*kc], plo0[2*kc+1], plo1[2*kc+1]};
            #pragma unroll
            for (int nt = 0; nt < 8; nt++) {
                const bf16* ph = &Vh[(nt * 8 + g) * 72 + kc * 16 + t4 * 2];
                const bf16* pl = &Vl[(nt * 8 + g) * 72 + kc * 16 + t4 * 2];
                uint32_t bh0 = *(const uint32_t*)(ph);
                uint32_t bh1 = *(const uint32_t*)(ph + 8);
                uint32_t bl0 = *(const uint32_t*)(pl);
                uint32_t bl1 = *(const uint32_t*)(pl + 8);
                mma16816(oacc[nt], ah, bh0, bh1);
                mma16816(oacc[nt], ah, bl0, bl1);
                mma16816(oacc[nt], al, bh0, bh1);
            }
        }
        __syncthreads();
        if (it + 2 < 16) flash_load_kv(smem_raw, t, bh, (it + 2) * 64, stage);
    }

    l0 += __shfl_xor_sync(0xffffffffu, l0, 1);
    l0 += __shfl_xor_sync(0xffffffffu, l0, 2);
    l1 += __shfl_xor_sync(0xffffffffu, l1, 1);
    l1 += __shfl_xor_sync(0xffffffffu, l1, 2);
    float inv0 = 1.0f / l0, inv1 = 1.0f / l1;
    size_t rowA0 = ((size_t)b << 10) + r0;
    size_t rowA1 = rowA0 + 8;
    #pragma unroll
    for (int nt = 0; nt < 8; nt++) {
        int col = (h << 6) + nt * 8 + t4 * 2;
        float o0 = oacc[nt][0] * inv0, o1 = oacc[nt][1] * inv0;
        float o2 = oacc[nt][2] * inv1, o3 = oacc[nt][3] * inv1;
        __nv_bfloat162 H0 = __floats2bfloat162_rn(o0, o1);
        float2 F0 = __bfloat1622float2(H0);
        __nv_bfloat162 L0 = __floats2bfloat162_rn(o0 - F0.x, o1 - F0.y);
        __nv_bfloat162 H1 = __floats2bfloat162_rn(o2, o3);
        float2 F1 = __bfloat1622float2(H1);
        __nv_bfloat162 L1 = __floats2bfloat162_rn(o2 - F1.x, o3 - F1.y);
        bf16* d0 = g_sa + rowA0 * 3072 + col;
        bf16* d1 = g_sa + rowA1 * 3072 + col;
        *(__nv_bfloat162*)(d0)        = H0;
        *(__nv_bfloat162*)(d0 + 1024) = H0;
        *(__nv_bfloat162*)(d0 + 2048) = L0;
        *(__nv_bfloat162*)(d1)        = H1;
        *(__nv_bfloat162*)(d1 + 1024) = H1;
        *(__nv_bfloat162*)(d1 + 2048) = L1;
    }
}

// ---------------- launch ----------------------------------------------------
extern "C" void kernel_launch(void* const* d_in, const int* in_sizes, int n_in,
                              void* d_out, int out_size) {
    const float* states      = (const float*)d_in[0];
    const float* keys        = (const float*)d_in[1];
    const float* masks       = (const float*)d_in[2];
    const void*  abias       = (const void*) d_in[3];
    const float* Wq          = (const float*)d_in[4];
    const float* Wk          = (const float*)d_in[5];
    const float* Wv          = (const float*)d_in[6];
    const float* Wout        = (const float*)d_in[7];
    const float* bias_embs   = (const float*)d_in[8];
    const float* bias_scalar = (const float*)d_in[9];
    float* out = (float*)d_out;
    int E = in_sizes[3] / 4;

    cudaFuncSetAttribute(flash_kernel,
                         cudaFuncAttributeMaxDynamicSharedMemorySize, FL_SMEM);
    cudaFuncSetAttribute(gemm_nt,
                         cudaFuncAttributeMaxDynamicSharedMemorySize, GSMEM);

    float *pq, *pk, *pv;
    bf16 *psa, *pka, *pwq, *pwk, *pwv, *pwo, *pqs, *pkb;
    cudaGetSymbolAddress((void**)&pq,  g_q);
    cudaGetSymbolAddress((void**)&pk,  g_k);
    cudaGetSymbolAddress((void**)&pv,  g_v);
    cudaGetSymbolAddress((void**)&psa, g_sa);
    cudaGetSymbolAddress((void**)&pka, g_ka);
    cudaGetSymbolAddress((void**)&pwq, g_wq);
    cudaGetSymbolAddress((void**)&pwk, g_wk);
    cudaGetSymbolAddress((void**)&pwv, g_wv);
    cudaGetSymbolAddress((void**)&pwo, g_wo);
    cudaGetSymbolAddress((void**)&pqs, g_qs);
    cudaGetSymbolAddress((void**)&pkb, g_kb);

    // conversions
    conv_a<<<8192, 256>>>((const float4*)states, psa, 1024);
    conv_a<<<8192, 256>>>((const float4*)keys,   pka, 1024);
    dim3 gt(32, 32);
    conv_bT<<<gt, 256>>>(Wq,   pwq, 1024, 1024);
    conv_bT<<<gt, 256>>>(Wk,   pwk, 1024, 1024);
    conv_bT<<<gt, 256>>>(Wv,   pwv, 1024, 1024);
    conv_bT<<<gt, 256>>>(Wout, pwo, 1024, 1024);

    // projections on tensor cores (pipelined ldmatrix mma.sync)
    dim3 gg(8, 64);
    gemm_nt<<<gg, 256, GSMEM>>>(psa, pwq, pq, 8192, 1024, 3072);
    gemm_nt<<<gg, 256, GSMEM>>>(pka, pwk, pk, 8192, 1024, 3072);
    gemm_nt<<<gg, 256, GSMEM>>>(pka, pwv, pv, 8192, 1024, 3072);

    // side computations
    ksum_kernel<<<(B_*T_*H_)/256, 256>>>();
    proj_kernel<<<1, 32>>>(bias_embs, bias_scalar);
    detect_kernel<<<1, 256>>>(abias, E);
    init_bs_kernel<<<(B_*T_*T_/4)/256, 256>>>();
    scatter_max_kernel<<<(E + 255)/256, 256>>>(abias, E);
    scatter_write_kernel<<<(E + 255)/256, 256>>>(abias, E);

    // operand prep for flash
    conv_qk<<<B_*H_*T_/8, 256>>>(pq, pqs, 1);
    conv_qk<<<B_*H_*T_/8, 256>>>(pk, pkb, 0);
    dim3 gv(32, 2, 128);
    conv_vT<<<gv, 256>>>();

    // fused attention (writes ctx split-bf16 into g_sa)
    dim3 gf(T_/128, B_*H_);
    flash_kernel<<<gf, 256, FL_SMEM>>>(masks);

    // output projection
    gemm_nt<<<gg, 256, GSMEM>>>(psa, pwo, out, 8192, 1024, 3072);
}

// round 10
// speedup vs baseline: 3.7756x; 1.0112x over previous
#include <cuda_runtime.h>
#include <cuda_bf16.h>
#include <cstdint>

#define B_ 8
#define T_ 1024
#define D_ 1024
#define H_ 16
#define A_ 64

typedef __nv_bfloat16 bf16;

// ---------------- scratch (device globals: allocation-free) ----------------
__device__ float g_q[B_*T_*H_*A_];          // [b,t,h,a]
__device__ float g_k[B_*T_*H_*A_];
__device__ float g_v[B_*T_*H_*A_];
__device__ float g_ksumT[B_*H_*T_];         // [(b,h),t]
__device__ float g_bs[B_*T_*T_];            // [b,q,k]
__device__ int   g_lastE[B_*T_*T_];
__device__ float g_proj[32];
__device__ int   g_is64;
__device__ uint64_t g_mpack[B_*T_*16];      // mask bits: [(b,q)][k/64]

// split-bf16 operands: [hi(1024) | lo(1024)] layouts
__device__ __align__(16) bf16 g_sa[8192*2048];          // states-split, later ctx-split
__device__ __align__(16) bf16 g_ka[8192*2048];          // keys-split
__device__ __align__(16) bf16 g_wq[1024*2048];
__device__ __align__(16) bf16 g_wk[1024*2048];
__device__ __align__(16) bf16 g_wv[1024*2048];
__device__ __align__(16) bf16 g_wo[1024*2048];
__device__ __align__(16) bf16 g_qs[B_*H_*T_*128];       // Q split [hi|lo], rows (b,h,t)
__device__ __align__(16) bf16 g_kb[B_*H_*T_*128];       // K split [hi|lo], rows (b,h,t)
__device__ __align__(16) bf16 g_vhi[B_*H_*A_*T_];       // [(b,h),a,k]
__device__ __align__(16) bf16 g_vlo[B_*H_*A_*T_];

// ---------------- mma.sync m16n8k16 bf16 ------------------------------------
__device__ __forceinline__ void mma16816(float* d, const uint32_t* a,
                                         uint32_t b0, uint32_t b1) {
    asm volatile(
        "mma.sync.aligned.m16n8k16.row.col.f32.bf16.bf16.f32 "
        "{%0,%1,%2,%3}, {%4,%5,%6,%7}, {%8,%9}, {%0,%1,%2,%3};\n"
        : "+f"(d[0]), "+f"(d[1]), "+f"(d[2]), "+f"(d[3])
        : "r"(a[0]), "r"(a[1]), "r"(a[2]), "r"(a[3]), "r"(b0), "r"(b1));
}

__device__ __forceinline__ void ldsm_x4(uint32_t& r0, uint32_t& r1,
                                        uint32_t& r2, uint32_t& r3, uint32_t addr) {
    asm volatile("ldmatrix.sync.aligned.m8n8.x4.shared.b16 {%0,%1,%2,%3}, [%4];"
                 : "=r"(r0), "=r"(r1), "=r"(r2), "=r"(r3) : "r"(addr));
}

__device__ __forceinline__ float ex2f(float x) {
    float r;
    asm("ex2.approx.f32 %0, %1;" : "=f"(r) : "f"(x));
    return r;
}

__device__ __forceinline__ void cpa16s(uint32_t smem, const void* gmem) {
    asm volatile("cp.async.cg.shared.global [%0], [%1], 16;\n"
                 :: "r"(smem), "l"(gmem));
}

// ---------------- dedup split NT GEMM: C = A[M,2048] * Bt[N,2048]^T ---------
// A,B stored [hi|lo]; computes Ah·Bh + Ah·Bl + Al·Bh over logical K=1024.
// 128x128 tile, logical BK=32, 256 threads (8 warps: 4m x 2n), 3-stage cp.async.
// Stage (32KB): Ah@0, Al@8192, Bh@16384, Bl@24576; each 128 rows x 64B,
// swizzle: 16B chunk c at row r -> chunk (c ^ ((r>>1)&3)).
#define GNS 3
#define GSB 32768
#define GSMEM (GNS*GSB)

__device__ __forceinline__ void g_ld_stage(uint32_t sb, const bf16* Ag,
                                           const bf16* Bg, int k0, int t) {
    #pragma unroll
    for (int i = 0; i < 2; i++) {
        int j = t + (i << 8);              // 0..511
        int row = j >> 2, c = j & 3;
        uint32_t sw = (uint32_t)((c ^ ((row >> 1) & 3)) << 4);
        const bf16* ga = Ag + (size_t)row * 2048 + k0 + c * 8;
        const bf16* gb = Bg + (size_t)row * 2048 + k0 + c * 8;
        cpa16s(sb + row * 64 + sw,           ga);           // Ah
        cpa16s(sb + 8192  + row * 64 + sw,   ga + 1024);    // Al
        cpa16s(sb + 16384 + row * 64 + sw,   gb);           // Bh
        cpa16s(sb + 24576 + row * 64 + sw,   gb + 1024);    // Bl
    }
}

__global__ __launch_bounds__(256, 2) void gemm_nt(
    const bf16* __restrict__ A, const bf16* __restrict__ Bt,
    float* __restrict__ C, int N)
{
    extern __shared__ char gsm[];
    const uint32_t dbase = (uint32_t)__cvta_generic_to_shared(gsm);
    const int t = threadIdx.x;
    const int m0 = blockIdx.y * 128, n0 = blockIdx.x * 128;
    const bf16* Ag = A  + (size_t)m0 * 2048;
    const bf16* Bg = Bt + (size_t)n0 * 2048;

    const int w = t >> 5, lane = t & 31;
    const int wm = (w & 3) * 32, wn = (w >> 2) * 64;
    const int g  = lane >> 2, t4 = lane & 3;
    const int lrow = lane & 15;
    const int lchk = lane >> 4;

    float acc[2][8][4];
    #pragma unroll
    for (int i = 0; i < 2; i++)
        #pragma unroll
        for (int j = 0; j < 8; j++)
            #pragma unroll
            for (int c = 0; c < 4; c++) acc[i][j][c] = 0.f;

    const int nIt = 32;                    // 1024 / 32
    #pragma unroll
    for (int s = 0; s < GNS - 1; s++) {
        g_ld_stage(dbase + s * GSB, Ag, Bg, s << 5, t);
        asm volatile("cp.async.commit_group;\n");
    }

    int st = 0, pst = GNS - 1;
    for (int i = 0; i < nIt; i++) {
        asm volatile("cp.async.wait_group %0;\n" :: "n"(GNS - 2));
        __syncthreads();
        if (i + GNS - 1 < nIt)
            g_ld_stage(dbase + pst * GSB, Ag, Bg, (i + 2) << 5, t);
        asm volatile("cp.async.commit_group;\n");

        const uint32_t sA = dbase + st * GSB;

        #pragma unroll
        for (int k16 = 0; k16 < 2; k16++) {
            const int kc2 = k16 * 2;
            const int chk = kc2 + lchk;
            uint32_t afh[2][4], afl[2][4];
            #pragma unroll
            for (int mt = 0; mt < 2; mt++) {
                int row = wm + mt * 16 + lrow;
                uint32_t off = row * 64 + ((chk ^ ((row >> 1) & 3)) << 4);
                ldsm_x4(afh[mt][0], afh[mt][1], afh[mt][2], afh[mt][3], sA + off);
                ldsm_x4(afl[mt][0], afl[mt][1], afl[mt][2], afl[mt][3],
                        sA + 8192 + off);
            }
            #pragma unroll
            for (int nq = 0; nq < 4; nq++) {
                int row = wn + nq * 16 + lrow;
                uint32_t off = row * 64 + ((chk ^ ((row >> 1) & 3)) << 4);
                uint32_t h0, h1, h2, h3, l0, l1, l2, l3;
                ldsm_x4(h0, h1, h2, h3, sA + 16384 + off);
                ldsm_x4(l0, l1, l2, l3, sA + 24576 + off);
                mma16816(acc[0][nq*2+0], afh[0], h0, h2);
                mma16816(acc[0][nq*2+1], afh[0], h1, h3);
                mma16816(acc[1][nq*2+0], afh[1], h0, h2);
                mma16816(acc[1][nq*2+1], afh[1], h1, h3);
                mma16816(acc[0][nq*2+0], afh[0], l0, l2);
                mma16816(acc[0][nq*2+1], afh[0], l1, l3);
                mma16816(acc[1][nq*2+0], afh[1], l0, l2);
                mma16816(acc[1][nq*2+1], afh[1], l1, l3);
                mma16816(acc[0][nq*2+0], afl[0], h0, h2);
                mma16816(acc[0][nq*2+1], afl[0], h1, h3);
                mma16816(acc[1][nq*2+0], afl[1], h0, h2);
                mma16816(acc[1][nq*2+1], afl[1], h1, h3);
            }
        }
        st = (st + 1 == GNS) ? 0 : st + 1;
        pst = (pst + 1 == GNS) ? 0 : pst + 1;
    }

    #pragma unroll
    for (int mt = 0; mt < 2; mt++) {
        #pragma unroll
        for (int nt8 = 0; nt8 < 8; nt8++) {
            int row = m0 + wm + mt * 16 + g;
            int col = n0 + wn + nt8 * 8 + t4 * 2;
            *(float2*)&C[(size_t)row * N + col] =
                make_float2(acc[mt][nt8][0], acc[mt][nt8][1]);
            *(float2*)&C[(size_t)(row + 8) * N + col] =
                make_float2(acc[mt][nt8][2], acc[mt][nt8][3]);
        }
    }
}

// ---------------- conversions ------------------------------------------------
__device__ __forceinline__ void split2(float v, bf16& hi, bf16& lo) {
    hi = __float2bfloat16_rn(v);
    lo = __float2bfloat16_rn(v - __bfloat162float(hi));
}

// f32 [M][1024] -> bf16 [M][2048] as [hi|lo]
__global__ void conv_a(const float4* __restrict__ in, bf16* __restrict__ out) {
    size_t idx = (size_t)blockIdx.x * 256 + threadIdx.x;
    float4 v = in[idx];
    size_t m = idx >> 8;
    int k4 = (int)(idx & 255) * 4;
    bf16 h0,h1,h2,h3,l0,l1,l2,l3;
    split2(v.x,h0,l0); split2(v.y,h1,l1); split2(v.z,h2,l2); split2(v.w,h3,l3);
    __nv_bfloat162 hp0, hp1, lp0, lp1;
    hp0.x=h0; hp0.y=h1; hp1.x=h2; hp1.y=h3;
    lp0.x=l0; lp0.y=l1; lp1.x=l2; lp1.y=l3;
    bf16* o = out + m * 2048 + k4;
    ((__nv_bfloat162*)o)[0] = hp0;          ((__nv_bfloat162*)o)[1] = hp1;
    ((__nv_bfloat162*)(o + 1024))[0] = lp0; ((__nv_bfloat162*)(o + 1024))[1] = lp1;
}

// f32 [K=1024][N] -> bf16 [N][2048] transposed [hi|lo]
__global__ void conv_bT(const float* __restrict__ in, bf16* __restrict__ out,
                        int N) {
    __shared__ float tile[32][33];
    int k0 = blockIdx.y * 32, n0 = blockIdx.x * 32;
    int tx = threadIdx.x & 31, ty = threadIdx.x >> 5;
    #pragma unroll
    for (int i = 0; i < 4; i++)
        tile[ty + 8*i][tx] = in[(size_t)(k0 + ty + 8*i) * N + n0 + tx];
    __syncthreads();
    #pragma unroll
    for (int i = 0; i < 4; i++) {
        int n = n0 + ty + 8*i, k = k0 + tx;
        float v = tile[tx][ty + 8*i];
        bf16 hi, lo; split2(v, hi, lo);
        bf16* o = out + (size_t)n * 2048;
        o[k] = hi; o[1024 + k] = lo;
    }
}

// [b,t,h,a] f32 -> [(b,h,t)][128] bf16 [hi|lo]
__global__ void conv_qk(const float* __restrict__ in, bf16* __restrict__ out) {
    int row  = blockIdx.x * 8 + (threadIdx.x >> 5);
    int lane = threadIdx.x & 31;
    int b = row >> 14, h = (row >> 10) & 15, tt = row & 1023;
    float2 v = *(const float2*)(in + (((size_t)b * 1024 + tt) * 16 + h) * 64 + lane * 2);
    bf16 h0,h1,l0,l1;
    split2(v.x,h0,l0); split2(v.y,h1,l1);
    __nv_bfloat162 hp, lp; hp.x=h0; hp.y=h1; lp.x=l0; lp.y=l1;
    __nv_bfloat162* o = (__nv_bfloat162*)(out + (size_t)row * 128) + lane;
    o[0]  = hp;
    o[32] = lp;
}

// g_v [b,k,h,a] -> g_vhi/g_vlo [(b,h), a, k]
__global__ void conv_vT() {
    __shared__ float tile[32][33];
    int bh = blockIdx.z, b = bh >> 4, h = bh & 15;
    int k0 = blockIdx.x * 32, a0 = blockIdx.y * 32;
    int tx = threadIdx.x & 31, ty = threadIdx.x >> 5;
    #pragma unroll
    for (int i = 0; i < 4; i++)
        tile[ty + 8*i][tx] =
            g_v[((((size_t)b << 10) + k0 + ty + 8*i) * 16 + h) * 64 + a0 + tx];
    __syncthreads();
    #pragma unroll
    for (int i = 0; i < 4; i++) {
        int a = a0 + ty + 8*i, k = k0 + tx;
        float v = tile[tx][ty + 8*i];
        bf16 hi, lo; split2(v, hi, lo);
        size_t o = ((size_t)bh * 64 + a) * 1024 + k;
        g_vhi[o] = hi;
        g_vlo[o] = lo;
    }
}

// masks f32 [b,q,k] -> bit-packed uint64 [(b,q)][k/64]
__global__ void mask_pack(const float* __restrict__ masks) {
    int idx = blockIdx.x * 256 + threadIdx.x;       // 0..B*T*16-1
    const float4* p = (const float4*)masks + (size_t)idx * 16;
    uint64_t bits = 0;
    #pragma unroll
    for (int i = 0; i < 16; i++) {
        float4 v = p[i];
        bits |= (uint64_t)(v.x != 0.f) << (i*4 + 0);
        bits |= (uint64_t)(v.y != 0.f) << (i*4 + 1);
        bits |= (uint64_t)(v.z != 0.f) << (i*4 + 2);
        bits |= (uint64_t)(v.w != 0.f) << (i*4 + 3);
    }
    g_mpack[idx] = bits;
}

// ---------------- ksumT[(b,h),t] = sum_a k[b,t,h,a] -------------------------
__global__ void ksum_kernel() {
    int idx = blockIdx.x * blockDim.x + threadIdx.x;
    const float* p = g_k + (size_t)idx * 64;
    float s = 0.f;
    #pragma unroll
    for (int i = 0; i < 16; i++) {
        float4 v = *(const float4*)(p + i*4);
        s += v.x + v.y + v.z + v.w;
    }
    int b = idx >> 14, tt = (idx >> 4) & 1023, h = idx & 15;
    g_ksumT[(((b << 4) + h) << 10) + tt] = s;
}

__global__ void proj_kernel(const float* __restrict__ embs,
                            const float* __restrict__ sc) {
    int t = threadIdx.x;
    if (t < 32) {
        float s = 0.f;
        #pragma unroll
        for (int a = 0; a < 64; a++) s += embs[t*64 + a] * sc[a];
        g_proj[t] = s;
    }
}

__global__ void detect_kernel(const void* __restrict__ ab, int E) {
    __shared__ int bad;
    if (threadIdx.x == 0) bad = 0;
    __syncthreads();
    int n = E < 256 ? E : 256;
    if ((int)threadIdx.x < n) {
        const long long* p = (const long long*)ab + (size_t)threadIdx.x * 4;
        long long et = p[0], bi = p[1], qi = p[2], ki = p[3];
        if (et < 0 || et >= 32 || bi < 0 || bi >= B_ ||
            qi < 0 || qi >= T_ || ki < 0 || ki >= T_) atomicExch(&bad, 1);
    }
    __syncthreads();
    if (threadIdx.x == 0) g_is64 = !bad;
}

__global__ void init_bs_kernel() {
    int i = blockIdx.x * blockDim.x + threadIdx.x;
    ((float4*)g_bs)[i]  = make_float4(0.f, 0.f, 0.f, 0.f);
    ((int4*)g_lastE)[i] = make_int4(-1, -1, -1, -1);
}

__device__ __forceinline__ void load_edge(const void* ab, int e,
                                          int& et, int& bi, int& qi, int& ki) {
    if (g_is64) {
        const long long* r = (const long long*)ab + (size_t)e * 4;
        et = (int)r[0]; bi = (int)r[1]; qi = (int)r[2]; ki = (int)r[3];
    } else {
        const int* r = (const int*)ab + (size_t)e * 4;
        et = r[0]; bi = r[1]; qi = r[2]; ki = r[3];
    }
}

__global__ void scatter_max_kernel(const void* __restrict__ ab, int E) {
    int e = blockIdx.x * blockDim.x + threadIdx.x;
    if (e >= E) return;
    int et, bi, qi, ki; load_edge(ab, e, et, bi, qi, ki);
    atomicMax(&g_lastE[((size_t)bi*T_ + qi)*T_ + ki], e);
}

__global__ void scatter_write_kernel(const void* __restrict__ ab, int E) {
    int e = blockIdx.x * blockDim.x + threadIdx.x;
    if (e >= E) return;
    int et, bi, qi, ki; load_edge(ab, e, et, bi, qi, ki);
    size_t idx = ((size_t)bi*T_ + qi)*T_ + ki;
    if (g_lastE[idx] == e) g_bs[idx] = g_proj[et];
}

// ---------------- flash attention: fused score+softmax+context ---------------
// Q/K split [hi|lo] 128-wide. Q tile 128x136 pitch; K stage 64x136; V 64x72 x2.
#define FL_QBYTES 34816
#define FL_STAGE  35840
#define FL_VHOFF  17408
#define FL_VLOFF  26624
#define FL_SMEM   (FL_QBYTES + 2*FL_STAGE)

__device__ __forceinline__ void cpa16(void* smem, const void* gmem) {
    uint32_t d = (uint32_t)__cvta_generic_to_shared(smem);
    asm volatile("cp.async.cg.shared.global [%0], [%1], 16;\n" :: "r"(d), "l"(gmem));
}

__device__ __forceinline__ void flash_load_kv(char* smem_raw, int t, int bh, int kt,
                                              int stage) {
    char* base = smem_raw + FL_QBYTES + stage * FL_STAGE;
    bf16* Ks = (bf16*)base;
    bf16* Vh = (bf16*)(base + FL_VHOFF);
    bf16* Vl = (bf16*)(base + FL_VLOFF);
    const bf16* ksrc = g_kb + ((size_t)(bh << 10) + kt) * 128;
    #pragma unroll
    for (int i = 0; i < 4; i++) {
        int u = t + i * 256;
        int row = u >> 4, c = u & 15;
        cpa16(&Ks[row * 136 + c * 8], &ksrc[(size_t)row * 128 + c * 8]);
    }
    const bf16* vh = g_vhi + (size_t)bh * 64 * 1024 + kt;
    const bf16* vl = g_vlo + (size_t)bh * 64 * 1024 + kt;
    #pragma unroll
    for (int i = 0; i < 2; i++) {
        int u = t + i * 256;
        int row = u >> 3, c = u & 7;
        cpa16(&Vh[row * 72 + c * 8], &vh[(size_t)row * 1024 + c * 8]);
        cpa16(&Vl[row * 72 + c * 8], &vl[(size_t)row * 1024 + c * 8]);
    }
    asm volatile("cp.async.commit_group;\n");
}

__global__ __launch_bounds__(256) void flash_kernel() {
    extern __shared__ char smem_raw[];
    bf16* Qs = (bf16*)smem_raw;                 // [128][136]
    const int t = threadIdx.x;
    const int w = t >> 5, lane = t & 31;
    const int g = lane >> 2, t4 = lane & 3;
    const int bh = blockIdx.y, b = bh >> 4, h = bh & 15;
    const int q0 = blockIdx.x * 128;

    // stage Q tile: 128 rows x 128 bf16 = 2048 16B chunks = 8 iters
    {
        const bf16* src = g_qs + ((size_t)(bh << 10) + q0) * 128;
        #pragma unroll
        for (int i = 0; i < 8; i++) {
            int u = t + i * 256;
            int row = u >> 4, c = u & 15;
            *(uint4*)&Qs[row * 136 + c * 8] = *(const uint4*)&src[(size_t)row * 128 + c * 8];
        }
    }
    flash_load_kv(smem_raw, t, bh, 0, 0);
    flash_load_kv(smem_raw, t, bh, 64, 1);
    __syncthreads();

    // Q fragments: kc 0..3 = hi, 4..7 = lo
    uint32_t qf[8][4];
    #pragma unroll
    for (int kc = 0; kc < 8; kc++) {
        const bf16* p = &Qs[(w * 16 + g) * 136 + kc * 16 + t4 * 2];
        qf[kc][0] = *(const uint32_t*)(p);
        qf[kc][1] = *(const uint32_t*)(p + 8 * 136);
        qf[kc][2] = *(const uint32_t*)(p + 8);
        qf[kc][3] = *(const uint32_t*)(p + 8 * 136 + 8);
    }

    const int r0 = q0 + w * 16 + g;
    float m0 = -1e38f, m1 = -1e38f, l0 = 0.f, l1 = 0.f;
    float oacc[8][4];
    #pragma unroll
    for (int nt = 0; nt < 8; nt++)
        #pragma unroll
        for (int c = 0; c < 4; c++) oacc[nt][c] = 0.f;

    const float C1 = 0.125f * 1.44269504f;

    for (int it = 0; it < 16; it++) {
        if (it < 15) asm volatile("cp.async.wait_group 1;\n");
        else         asm volatile("cp.async.wait_group 0;\n");
        __syncthreads();
        const int stage = it & 1;
        char* base = smem_raw + FL_QBYTES + stage * FL_STAGE;
        const bf16* Ks = (const bf16*)base;
        const bf16* Vh = (const bf16*)(base + FL_VHOFF);
        const bf16* Vl = (const bf16*)(base + FL_VLOFF);
        const int kt = it * 64;

        // S = Qh·Kh + Qh·Kl + Ql·Kh
        float sacc[8][4];
        #pragma unroll
        for (int nt = 0; nt < 8; nt++)
            #pragma unroll
            for (int c = 0; c < 4; c++) sacc[nt][c] = 0.f;
        #pragma unroll
        for (int nt = 0; nt < 8; nt++) {
            const bf16* pr = &Ks[(nt * 8 + g) * 136 + t4 * 2];
            #pragma unroll
            for (int kc = 0; kc < 4; kc++) {
                uint32_t h0 = *(const uint32_t*)(pr + kc * 16);
                uint32_t h1 = *(const uint32_t*)(pr + kc * 16 + 8);
                mma16816(sacc[nt], qf[kc], h0, h1);         // Qh·Kh
                mma16816(sacc[nt], qf[4 + kc], h0, h1);     // Ql·Kh
                uint32_t l0r = *(const uint32_t*)(pr + 64 + kc * 16);
                uint32_t l1r = *(const uint32_t*)(pr + 64 + kc * 16 + 8);
                mma16816(sacc[nt], qf[kc], l0r, l1r);       // Qh·Kl
            }
        }

        // epilogue: + bs*ksum, scale, bit-mask; log2 domain
        uint64_t w0 = g_mpack[(((size_t)b << 10) + r0) * 16 + it];
        uint64_t w1 = g_mpack[(((size_t)b << 10) + r0 + 8) * 16 + it];
        float mt0 = -1e38f, mt1 = -1e38f;
        #pragma unroll
        for (int nt = 0; nt < 8; nt++) {
            int c0 = kt + nt * 8 + t4 * 2;
            int sh = nt * 8 + t4 * 2;
            float2 ks2 = *(const float2*)&g_ksumT[((size_t)bh << 10) + c0];
            size_t mb0 = ((((size_t)b << 10) + r0) << 10) + c0;
            size_t mb1 = ((((size_t)b << 10) + r0 + 8) << 10) + c0;
            float2 bs0 = *(const float2*)&g_bs[mb0];
            float2 bs1 = *(const float2*)&g_bs[mb1];
            float s0 = (sacc[nt][0] + bs0.x * ks2.x) * C1;
            float s1 = (sacc[nt][1] + bs0.y * ks2.y) * C1;
            float s2 = (sacc[nt][2] + bs1.x * ks2.x) * C1;
            float s3 = (sacc[nt][3] + bs1.y * ks2.y) * C1;
            sacc[nt][0] = ((w0 >> sh) & 1)       ? -1e37f : s0;
            sacc[nt][1] = ((w0 >> (sh + 1)) & 1) ? -1e37f : s1;
            sacc[nt][2] = ((w1 >> sh) & 1)       ? -1e37f : s2;
            sacc[nt][3] = ((w1 >> (sh + 1)) & 1) ? -1e37f : s3;
            mt0 = fmaxf(mt0, fmaxf(sacc[nt][0], sacc[nt][1]));
            mt1 = fmaxf(mt1, fmaxf(sacc[nt][2], sacc[nt][3]));
        }
        mt0 = fmaxf(mt0, __shfl_xor_sync(0xffffffffu, mt0, 1));
        mt0 = fmaxf(mt0, __shfl_xor_sync(0xffffffffu, mt0, 2));
        mt1 = fmaxf(mt1, __shfl_xor_sync(0xffffffffu, mt1, 1));
        mt1 = fmaxf(mt1, __shfl_xor_sync(0xffffffffu, mt1, 2));
        float mn0 = fmaxf(m0, mt0), mn1 = fmaxf(m1, mt1);
        float sc0 = ex2f(m0 - mn0), sc1 = ex2f(m1 - mn1);
        m0 = mn0; m1 = mn1;
        l0 *= sc0; l1 *= sc1;

        uint32_t phi0[8], phi1[8], plo0[8], plo1[8];
        #pragma unroll
        for (int nt = 0; nt < 8; nt++) {
            float p0 = ex2f(sacc[nt][0] - m0), p1 = ex2f(sacc[nt][1] - m0);
            float p2 = ex2f(sacc[nt][2] - m1), p3 = ex2f(sacc[nt][3] - m1);
            l0 += p0 + p1; l1 += p2 + p3;
            __nv_bfloat162 h0 = __floats2bfloat162_rn(p0, p1);
            float2 f0 = __bfloat1622float2(h0);
            __nv_bfloat162 e0 = __floats2bfloat162_rn(p0 - f0.x, p1 - f0.y);
            __nv_bfloat162 h1 = __floats2bfloat162_rn(p2, p3);
            float2 f1 = __bfloat1622float2(h1);
            __nv_bfloat162 e1 = __floats2bfloat162_rn(p2 - f1.x, p3 - f1.y);
            phi0[nt] = *(uint32_t*)&h0; plo0[nt] = *(uint32_t*)&e0;
            phi1[nt] = *(uint32_t*)&h1; plo1[nt] = *(uint32_t*)&e1;
            oacc[nt][0] *= sc0; oacc[nt][1] *= sc0;
            oacc[nt][2] *= sc1; oacc[nt][3] *= sc1;
        }

        // O += P * V  (3-term split)
        #pragma unroll
        for (int kc = 0; kc < 4; kc++) {
            uint32_t ah[4] = {phi0[2*kc], phi1[2*kc], phi0[2*kc+1], phi1[2*kc+1]};
            uint32_t al[4] = {plo0[2*kc], plo1[2*kc], plo0[2*kc+1], plo1[2*kc+1]};
            #pragma unroll
            for (int nt = 0; nt < 8; nt++) {
                const bf16* ph = &Vh[(nt * 8 + g) * 72 + kc * 16 + t4 * 2];
                const bf16* pl = &Vl[(nt * 8 + g) * 72 + kc * 16 + t4 * 2];
                uint32_t bh0 = *(const uint32_t*)(ph);
                uint32_t bh1 = *(const uint32_t*)(ph + 8);
                uint32_t bl0 = *(const uint32_t*)(pl);
                uint32_t bl1 = *(const uint32_t*)(pl + 8);
                mma16816(oacc[nt], ah, bh0, bh1);
                mma16816(oacc[nt], ah, bl0, bl1);
                mma16816(oacc[nt], al, bh0, bh1);
            }
        }
        __syncthreads();
        if (it + 2 < 16) flash_load_kv(smem_raw, t, bh, (it + 2) * 64, stage);
    }

    l0 += __shfl_xor_sync(0xffffffffu, l0, 1);
    l0 += __shfl_xor_sync(0xffffffffu, l0, 2);
    l1 += __shfl_xor_sync(0xffffffffu, l1, 1);
    l1 += __shfl_xor_sync(0xffffffffu, l1, 2);
    float inv0 = 1.0f / l0, inv1 = 1.0f / l1;
    size_t rowA0 = ((size_t)b << 10) + r0;
    size_t rowA1 = rowA0 + 8;
    #pragma unroll
    for (int nt = 0; nt < 8; nt++) {
        int col = (h << 6) + nt * 8 + t4 * 2;
        float o0 = oacc[nt][0] * inv0, o1 = oacc[nt][1] * inv0;
        float o2 = oacc[nt][2] * inv1, o3 = oacc[nt][3] * inv1;
        __nv_bfloat162 H0 = __floats2bfloat162_rn(o0, o1);
        float2 F0 = __bfloat1622float2(H0);
        __nv_bfloat162 L0 = __floats2bfloat162_rn(o0 - F0.x, o1 - F0.y);
        __nv_bfloat162 H1 = __floats2bfloat162_rn(o2, o3);
        float2 F1 = __bfloat1622float2(H1);
        __nv_bfloat162 L1 = __floats2bfloat162_rn(o2 - F1.x, o3 - F1.y);
        bf16* d0 = g_sa + rowA0 * 2048 + col;
        bf16* d1 = g_sa + rowA1 * 2048 + col;
        *(__nv_bfloat162*)(d0)        = H0;
        *(__nv_bfloat162*)(d0 + 1024) = L0;
        *(__nv_bfloat162*)(d1)        = H1;
        *(__nv_bfloat162*)(d1 + 1024) = L1;
    }
}

// ---------------- launch ----------------------------------------------------
extern "C" void kernel_launch(void* const* d_in, const int* in_sizes, int n_in,
                              void* d_out, int out_size) {
    const float* states      = (const float*)d_in[0];
    const float* keys        = (const float*)d_in[1];
    const float* masks       = (const float*)d_in[2];
    const void*  abias       = (const void*) d_in[3];
    const float* Wq          = (const float*)d_in[4];
    const float* Wk          = (const float*)d_in[5];
    const float* Wv          = (const float*)d_in[6];
    const float* Wout        = (const float*)d_in[7];
    const float* bias_embs   = (const float*)d_in[8];
    const float* bias_scalar = (const float*)d_in[9];
    float* out = (float*)d_out;
    int E = in_sizes[3] / 4;

    cudaFuncSetAttribute(flash_kernel,
                         cudaFuncAttributeMaxDynamicSharedMemorySize, FL_SMEM);
    cudaFuncSetAttribute(gemm_nt,
                         cudaFuncAttributeMaxDynamicSharedMemorySize, GSMEM);

    float *pq, *pk, *pv;
    bf16 *psa, *pka, *pwq, *pwk, *pwv, *pwo, *pqs, *pkb;
    cudaGetSymbolAddress((void**)&pq,  g_q);
    cudaGetSymbolAddress((void**)&pk,  g_k);
    cudaGetSymbolAddress((void**)&pv,  g_v);
    cudaGetSymbolAddress((void**)&psa, g_sa);
    cudaGetSymbolAddress((void**)&pka, g_ka);
    cudaGetSymbolAddress((void**)&pwq, g_wq);
    cudaGetSymbolAddress((void**)&pwk, g_wk);
    cudaGetSymbolAddress((void**)&pwv, g_wv);
    cudaGetSymbolAddress((void**)&pwo, g_wo);
    cudaGetSymbolAddress((void**)&pqs, g_qs);
    cudaGetSymbolAddress((void**)&pkb, g_kb);

    // conversions
    conv_a<<<8192, 256>>>((const float4*)states, psa);
    conv_a<<<8192, 256>>>((const float4*)keys,   pka);
    dim3 gt(32, 32);
    conv_bT<<<gt, 256>>>(Wq,   pwq, 1024);
    conv_bT<<<gt, 256>>>(Wk,   pwk, 1024);
    conv_bT<<<gt, 256>>>(Wv,   pwv, 1024);
    conv_bT<<<gt, 256>>>(Wout, pwo, 1024);
    mask_pack<<<512, 256>>>(masks);

    // projections on tensor cores
    dim3 gg(8, 64);
    gemm_nt<<<gg, 256, GSMEM>>>(psa, pwq, pq, 1024);
    gemm_nt<<<gg, 256, GSMEM>>>(pka, pwk, pk, 1024);
    gemm_nt<<<gg, 256, GSMEM>>>(pka, pwv, pv, 1024);

    // side computations
    ksum_kernel<<<(B_*T_*H_)/256, 256>>>();
    proj_kernel<<<1, 32>>>(bias_embs, bias_scalar);
    detect_kernel<<<1, 256>>>(abias, E);
    init_bs_kernel<<<(B_*T_*T_/4)/256, 256>>>();
    scatter_max_kernel<<<(E + 255)/256, 256>>>(abias, E);
    scatter_write_kernel<<<(E + 255)/256, 256>>>(abias, E);

    // operand prep for flash
    conv_qk<<<B_*H_*T_/8, 256>>>(pq, pqs);
    conv_qk<<<B_*H_*T_/8, 256>>>(pk, pkb);
    dim3 gv(32, 2, 128);
    conv_vT<<<gv, 256>>>();

    // fused attention (writes ctx split-bf16 into g_sa)
    dim3 gf(T_/128, B_*H_);
    flash_kernel<<<gf, 256, FL_SMEM>>>();

    // output projection
    gemm_nt<<<gg, 256, GSMEM>>>(psa, pwo, out, 1024);
}

// round 12
// speedup vs baseline: 4.6170x; 1.2228x over previous
#include <cuda_runtime.h>
#include <cuda_fp16.h>
#include <cstdint>

#define B_ 8
#define T_ 1024
#define D_ 1024
#define H_ 16
#define A_ 64

// ---------------- scratch (device globals: allocation-free) ----------------
__device__ float g_q[B_*T_*H_*A_];          // [b,t,h,a]
__device__ float g_k[B_*T_*H_*A_];
__device__ float g_v[B_*T_*H_*A_];
__device__ float g_ksumT[B_*H_*T_];         // [(b,h),t]
__device__ float g_bs[B_*T_*T_];            // [b,q,k]
__device__ int   g_lastE[B_*T_*T_];
__device__ float g_proj[32];
__device__ int   g_is64;
__device__ uint64_t g_mpack[B_*T_*16];      // mask bits: [(b,q)][k/64]

// split-fp16 operands
__device__ __align__(16) __half g_sa[8192*2048];        // A-side [hi|lo]: states, later ctx
__device__ __align__(16) __half g_ka[8192*2048];        // keys [hi|lo]
__device__ __align__(16) __half g_wq[1024*1024];        // weights hi-only, [N][K]
__device__ __align__(16) __half g_wk[1024*1024];
__device__ __align__(16) __half g_wv[1024*1024];
__device__ __align__(16) __half g_wo[1024*1024];
__device__ __align__(16) __half g_qs[B_*H_*T_*128];     // Q [hi|lo], rows (b,h,t)
__device__ __align__(16) __half g_kb[B_*H_*T_*64];      // K hi-only, rows (b,h,t)
__device__ __align__(16) __half g_vhi[B_*H_*A_*T_];     // [(b,h),a,k]
__device__ __align__(16) __half g_vlo[B_*H_*A_*T_];

// ---------------- mma.sync m16n8k16 fp16 ------------------------------------
__device__ __forceinline__ void mma16816(float* d, const uint32_t* a,
                                         uint32_t b0, uint32_t b1) {
    asm volatile(
        "mma.sync.aligned.m16n8k16.row.col.f32.f16.f16.f32 "
        "{%0,%1,%2,%3}, {%4,%5,%6,%7}, {%8,%9}, {%0,%1,%2,%3};\n"
        : "+f"(d[0]), "+f"(d[1]), "+f"(d[2]), "+f"(d[3])
        : "r"(a[0]), "r"(a[1]), "r"(a[2]), "r"(a[3]), "r"(b0), "r"(b1));
}

__device__ __forceinline__ void ldsm_x4(uint32_t& r0, uint32_t& r1,
                                        uint32_t& r2, uint32_t& r3, uint32_t addr) {
    asm volatile("ldmatrix.sync.aligned.m8n8.x4.shared.b16 {%0,%1,%2,%3}, [%4];"
                 : "=r"(r0), "=r"(r1), "=r"(r2), "=r"(r3) : "r"(addr));
}

__device__ __forceinline__ float ex2f(float x) {
    float r;
    asm("ex2.approx.f32 %0, %1;" : "=f"(r) : "f"(x));
    return r;
}

__device__ __forceinline__ void cpa16s(uint32_t smem, const void* gmem) {
    asm volatile("cp.async.cg.shared.global [%0], [%1], 16;\n"
                 :: "r"(smem), "l"(gmem));
}

// ---------------- 2-term split NT GEMM: C = (Ah+Al)[M] * Bh[N]^T ------------
// A [M][2048] fp16 [hi|lo]; B [N][1024] fp16 hi-only. Logical K=1024, BK=32.
// 128x128 tile, 256 threads (8 warps: 4m x 2n), 4-stage cp.async.
// Stage (24KB): Ah@0, Al@8192, Bh@16384; 128 rows x 64B each;
// swizzle: 16B chunk c at row r -> chunk (c ^ ((r>>1)&3)).
#define GNS 4
#define GSB 24576
#define GSMEM (GNS*GSB)

__device__ __forceinline__ void g_ld_stage(uint32_t sb, const __half* Ag,
                                           const __half* Bg, int k0, int t) {
    #pragma unroll
    for (int i = 0; i < 2; i++) {
        int j = t + (i << 8);              // 0..511
        int row = j >> 2, c = j & 3;
        uint32_t sw = (uint32_t)((c ^ ((row >> 1) & 3)) << 4);
        const __half* ga = Ag + (size_t)row * 2048 + k0 + c * 8;
        cpa16s(sb + row * 64 + sw,           ga);                              // Ah
        cpa16s(sb + 8192  + row * 64 + sw,   ga + 1024);                       // Al
        cpa16s(sb + 16384 + row * 64 + sw,   Bg + (size_t)row * 1024 + k0 + c * 8); // Bh
    }
}

__global__ __launch_bounds__(256, 2) void gemm_nt(
    const __half* __restrict__ A, const __half* __restrict__ Bt,
    float* __restrict__ C, int N)
{
    extern __shared__ char gsm[];
    const uint32_t dbase = (uint32_t)__cvta_generic_to_shared(gsm);
    const int t = threadIdx.x;
    const int m0 = blockIdx.y * 128, n0 = blockIdx.x * 128;
    const __half* Ag = A  + (size_t)m0 * 2048;
    const __half* Bg = Bt + (size_t)n0 * 1024;

    const int w = t >> 5, lane = t & 31;
    const int wm = (w & 3) * 32, wn = (w >> 2) * 64;
    const int g  = lane >> 2, t4 = lane & 3;
    const int lrow = lane & 15;
    const int lchk = lane >> 4;

    float acc[2][8][4];
    #pragma unroll
    for (int i = 0; i < 2; i++)
        #pragma unroll
        for (int j = 0; j < 8; j++)
            #pragma unroll
            for (int c = 0; c < 4; c++) acc[i][j][c] = 0.f;

    const int nIt = 32;                    // 1024 / 32
    #pragma unroll
    for (int s = 0; s < GNS - 1; s++) {
        g_ld_stage(dbase + s * GSB, Ag, Bg, s << 5, t);
        asm volatile("cp.async.commit_group;\n");
    }

    int st = 0, pst = GNS - 1;
    for (int i = 0; i < nIt; i++) {
        asm volatile("cp.async.wait_group %0;\n" :: "n"(GNS - 2));
        __syncthreads();
        if (i + GNS - 1 < nIt)
            g_ld_stage(dbase + pst * GSB, Ag, Bg, (i + 3) << 5, t);
        asm volatile("cp.async.commit_group;\n");

        const uint32_t sA = dbase + st * GSB;

        #pragma unroll
        for (int k16 = 0; k16 < 2; k16++) {
            const int chk = k16 * 2 + lchk;
            uint32_t afh[2][4], afl[2][4];
            #pragma unroll
            for (int mt = 0; mt < 2; mt++) {
                int row = wm + mt * 16 + lrow;
                uint32_t off = row * 64 + ((chk ^ ((row >> 1) & 3)) << 4);
                ldsm_x4(afh[mt][0], afh[mt][1], afh[mt][2], afh[mt][3], sA + off);
                ldsm_x4(afl[mt][0], afl[mt][1], afl[mt][2], afl[mt][3],
                        sA + 8192 + off);
            }
            #pragma unroll
            for (int nq = 0; nq < 4; nq++) {
                int row = wn + nq * 16 + lrow;
                uint32_t off = row * 64 + ((chk ^ ((row >> 1) & 3)) << 4);
                uint32_t h0, h1, h2, h3;
                ldsm_x4(h0, h1, h2, h3, sA + 16384 + off);
                mma16816(acc[0][nq*2+0], afh[0], h0, h2);
                mma16816(acc[0][nq*2+1], afh[0], h1, h3);
                mma16816(acc[1][nq*2+0], afh[1], h0, h2);
                mma16816(acc[1][nq*2+1], afh[1], h1, h3);
                mma16816(acc[0][nq*2+0], afl[0], h0, h2);
                mma16816(acc[0][nq*2+1], afl[0], h1, h3);
                mma16816(acc[1][nq*2+0], afl[1], h0, h2);
                mma16816(acc[1][nq*2+1], afl[1], h1, h3);
            }
        }
        st = (st + 1 == GNS) ? 0 : st + 1;
        pst = (pst + 1 == GNS) ? 0 : pst + 1;
    }

    #pragma unroll
    for (int mt = 0; mt < 2; mt++) {
        #pragma unroll
        for (int nt8 = 0; nt8 < 8; nt8++) {
            int row = m0 + wm + mt * 16 + g;
            int col = n0 + wn + nt8 * 8 + t4 * 2;
            *(float2*)&C[(size_t)row * N + col] =
                make_float2(acc[mt][nt8][0], acc[mt][nt8][1]);
            *(float2*)&C[(size_t)(row + 8) * N + col] =
                make_float2(acc[mt][nt8][2], acc[mt][nt8][3]);
        }
    }
}

// ---------------- conversions ------------------------------------------------
__device__ __forceinline__ void split2h(float v, __half& hi, __half& lo) {
    hi = __float2half_rn(v);
    lo = __float2half_rn(v - __half2float(hi));
}

// f32 [M][1024] -> fp16 [M][2048] as [hi|lo]
__global__ void conv_a(const float4* __restrict__ in, __half* __restrict__ out) {
    size_t idx = (size_t)blockIdx.x * 256 + threadIdx.x;
    float4 v = in[idx];
    size_t m = idx >> 8;
    int k4 = (int)(idx & 255) * 4;
    __half h0,h1,h2,h3,l0,l1,l2,l3;
    split2h(v.x,h0,l0); split2h(v.y,h1,l1); split2h(v.z,h2,l2); split2h(v.w,h3,l3);
    __half2 hp0, hp1, lp0, lp1;
    hp0.x=h0; hp0.y=h1; hp1.x=h2; hp1.y=h3;
    lp0.x=l0; lp0.y=l1; lp1.x=l2; lp1.y=l3;
    __half* o = out + m * 2048 + k4;
    ((__half2*)o)[0] = hp0;          ((__half2*)o)[1] = hp1;
    ((__half2*)(o + 1024))[0] = lp0; ((__half2*)(o + 1024))[1] = lp1;
}

// f32 [K=1024][N] -> fp16 [N][1024] transposed, hi only
__global__ void conv_bT(const float* __restrict__ in, __half* __restrict__ out,
                        int N) {
    __shared__ float tile[32][33];
    int k0 = blockIdx.y * 32, n0 = blockIdx.x * 32;
    int tx = threadIdx.x & 31, ty = threadIdx.x >> 5;
    #pragma unroll
    for (int i = 0; i < 4; i++)
        tile[ty + 8*i][tx] = in[(size_t)(k0 + ty + 8*i) * N + n0 + tx];
    __syncthreads();
    #pragma unroll
    for (int i = 0; i < 4; i++) {
        int n = n0 + ty + 8*i, k = k0 + tx;
        out[(size_t)n * 1024 + k] = __float2half_rn(tile[tx][ty + 8*i]);
    }
}

// [b,t,h,a] f32 -> [(b,h,t)][128] fp16 [hi|lo]  (Q side)
__global__ void conv_qk(const float* __restrict__ in, __half* __restrict__ out) {
    int row  = blockIdx.x * 8 + (threadIdx.x >> 5);
    int lane = threadIdx.x & 31;
    int b = row >> 14, h = (row >> 10) & 15, tt = row & 1023;
    float2 v = *(const float2*)(in + (((size_t)b * 1024 + tt) * 16 + h) * 64 + lane * 2);
    __half h0,h1,l0,l1;
    split2h(v.x,h0,l0); split2h(v.y,h1,l1);
    __half2 hp, lp; hp.x=h0; hp.y=h1; lp.x=l0; lp.y=l1;
    __half2* o = (__half2*)(out + (size_t)row * 128) + lane;
    o[0]  = hp;
    o[32] = lp;
}

// [b,t,h,a] f32 -> [(b,h,t)][64] fp16 hi-only  (K side)
__global__ void conv_k(const float* __restrict__ in, __half* __restrict__ out) {
    int row  = blockIdx.x * 8 + (threadIdx.x >> 5);
    int lane = threadIdx.x & 31;
    int b = row >> 14, h = (row >> 10) & 15, tt = row & 1023;
    float2 v = *(const float2*)(in + (((size_t)b * 1024 + tt) * 16 + h) * 64 + lane * 2);
    __half2 hp; hp.x = __float2half_rn(v.x); hp.y = __float2half_rn(v.y);
    ((__half2*)(out + (size_t)row * 64))[lane] = hp;
}

// g_v [b,k,h,a] -> g_vhi/g_vlo [(b,h), a, k]
__global__ void conv_vT() {
    __shared__ float tile[32][33];
    int bh = blockIdx.z, b = bh >> 4, h = bh & 15;
    int k0 = blockIdx.x * 32, a0 = blockIdx.y * 32;
    int tx = threadIdx.x & 31, ty = threadIdx.x >> 5;
    #pragma unroll
    for (int i = 0; i < 4; i++)
        tile[ty + 8*i][tx] =
            g_v[((((size_t)b << 10) + k0 + ty + 8*i) * 16 + h) * 64 + a0 + tx];
    __syncthreads();
    #pragma unroll
    for (int i = 0; i < 4; i++) {
        int a = a0 + ty + 8*i, k = k0 + tx;
        __half hi, lo; split2h(tile[tx][ty + 8*i], hi, lo);
        size_t o = ((size_t)bh * 64 + a) * 1024 + k;
        g_vhi[o] = hi;
        g_vlo[o] = lo;
    }
}

// masks f32 [b,q,k] -> bit-packed uint64 [(b,q)][k/64]
__global__ void mask_pack(const float* __restrict__ masks) {
    int idx = blockIdx.x * 256 + threadIdx.x;       // 0..B*T*16-1
    const float4* p = (const float4*)masks + (size_t)idx * 16;
    uint64_t bits = 0;
    #pragma unroll
    for (int i = 0; i < 16; i++) {
        float4 v = p[i];
        bits |= (uint64_t)(v.x != 0.f) << (i*4 + 0);
        bits |= (uint64_t)(v.y != 0.f) << (i*4 + 1);
        bits |= (uint64_t)(v.z != 0.f) << (i*4 + 2);
        bits |= (uint64_t)(v.w != 0.f) << (i*4 + 3);
    }
    g_mpack[idx] = bits;
}

// ---------------- ksumT[(b,h),t] = sum_a k[b,t,h,a] -------------------------
__global__ void ksum_kernel() {
    int idx = blockIdx.x * blockDim.x + threadIdx.x;
    const float* p = g_k + (size_t)idx * 64;
    float s = 0.f;
    #pragma unroll
    for (int i = 0; i < 16; i++) {
        float4 v = *(const float4*)(p + i*4);
        s += v.x + v.y + v.z + v.w;
    }
    int b = idx >> 14, tt = (idx >> 4) & 1023, h = idx & 15;
    g_ksumT[(((b << 4) + h) << 10) + tt] = s;
}

__global__ void proj_kernel(const float* __restrict__ embs,
                            const float* __restrict__ sc) {
    int t = threadIdx.x;
    if (t < 32) {
        float s = 0.f;
        #pragma unroll
        for (int a = 0; a < 64; a++) s += embs[t*64 + a] * sc[a];
        g_proj[t] = s;
    }
}

__global__ void detect_kernel(const void* __restrict__ ab, int E) {
    __shared__ int bad;
    if (threadIdx.x == 0) bad = 0;
    __syncthreads();
    int n = E < 256 ? E : 256;
    if ((int)threadIdx.x < n) {
        const long long* p = (const long long*)ab + (size_t)threadIdx.x * 4;
        long long et = p[0], bi = p[1], qi = p[2], ki = p[3];
        if (et < 0 || et >= 32 || bi < 0 || bi >= B_ ||
            qi < 0 || qi >= T_ || ki < 0 || ki >= T_) atomicExch(&bad, 1);
    }
    __syncthreads();
    if (threadIdx.x == 0) g_is64 = !bad;
}

__global__ void init_bs_kernel() {
    int i = blockIdx.x * blockDim.x + threadIdx.x;
    ((float4*)g_bs)[i]  = make_float4(0.f, 0.f, 0.f, 0.f);
    ((int4*)g_lastE)[i] = make_int4(-1, -1, -1, -1);
}

__device__ __forceinline__ void load_edge(const void* ab, int e,
                                          int& et, int& bi, int& qi, int& ki) {
    if (g_is64) {
        const long long* r = (const long long*)ab + (size_t)e * 4;
        et = (int)r[0]; bi = (int)r[1]; qi = (int)r[2]; ki = (int)r[3];
    } else {
        const int* r = (const int*)ab + (size_t)e * 4;
        et = r[0]; bi = r[1]; qi = r[2]; ki = r[3];
    }
}

__global__ void scatter_max_kernel(const void* __restrict__ ab, int E) {
    int e = blockIdx.x * blockDim.x + threadIdx.x;
    if (e >= E) return;
    int et, bi, qi, ki; load_edge(ab, e, et, bi, qi, ki);
    atomicMax(&g_lastE[((size_t)bi*T_ + qi)*T_ + ki], e);
}

__global__ void scatter_write_kernel(const void* __restrict__ ab, int E) {
    int e = blockIdx.x * blockDim.x + threadIdx.x;
    if (e >= E) return;
    int et, bi, qi, ki; load_edge(ab, e, et, bi, qi, ki);
    size_t idx = ((size_t)bi*T_ + qi)*T_ + ki;
    if (g_lastE[idx] == e) g_bs[idx] = g_proj[et];
}

// ---------------- flash attention: fused score+softmax+context ---------------
// Q [hi|lo] 128-wide; K hi-only 64-wide; V hi/lo planes.
// Q tile 128x136 pitch; stage = { K 64x72, Vh 64x72, Vl 64x72 }.
#define FL_QBYTES 34816
#define FL_STAGE  27648
#define FL_VHOFF  9216
#define FL_VLOFF  18432
#define FL_SMEM   (FL_QBYTES + 2*FL_STAGE)

__device__ __forceinline__ void cpa16(void* smem, const void* gmem) {
    uint32_t d = (uint32_t)__cvta_generic_to_shared(smem);
    asm volatile("cp.async.cg.shared.global [%0], [%1], 16;\n" :: "r"(d), "l"(gmem));
}

__device__ __forceinline__ void flash_load_kv(char* smem_raw, int t, int bh, int kt,
                                              int stage) {
    char* base = smem_raw + FL_QBYTES + stage * FL_STAGE;
    __half* Ks = (__half*)base;
    __half* Vh = (__half*)(base + FL_VHOFF);
    __half* Vl = (__half*)(base + FL_VLOFF);
    const __half* ksrc = g_kb + ((size_t)(bh << 10) + kt) * 64;
    #pragma unroll
    for (int i = 0; i < 2; i++) {
        int u = t + i * 256;
        int row = u >> 3, c = u & 7;
        cpa16(&Ks[row * 72 + c * 8], &ksrc[(size_t)row * 64 + c * 8]);
    }
    const __half* vh = g_vhi + (size_t)bh * 64 * 1024 + kt;
    const __half* vl = g_vlo + (size_t)bh * 64 * 1024 + kt;
    #pragma unroll
    for (int i = 0; i < 2; i++) {
        int u = t + i * 256;
        int row = u >> 3, c = u & 7;
        cpa16(&Vh[row * 72 + c * 8], &vh[(size_t)row * 1024 + c * 8]);
        cpa16(&Vl[row * 72 + c * 8], &vl[(size_t)row * 1024 + c * 8]);
    }
    asm volatile("cp.async.commit_group;\n");
}

__global__ __launch_bounds__(256) void flash_kernel() {
    extern __shared__ char smem_raw[];
    __half* Qs = (__half*)smem_raw;             // [128][136]
    const int t = threadIdx.x;
    const int w = t >> 5, lane = t & 31;
    const int g = lane >> 2, t4 = lane & 3;
    const int bh = blockIdx.y, b = bh >> 4, h = bh & 15;
    const int q0 = blockIdx.x * 128;

    // stage Q tile: 128 rows x 128 fp16 = 2048 16B chunks = 8 iters
    {
        const __half* src = g_qs + ((size_t)(bh << 10) + q0) * 128;
        #pragma unroll
        for (int i = 0; i < 8; i++) {
            int u = t + i * 256;
            int row = u >> 4, c = u & 15;
            *(uint4*)&Qs[row * 136 + c * 8] = *(const uint4*)&src[(size_t)row * 128 + c * 8];
        }
    }
    flash_load_kv(smem_raw, t, bh, 0, 0);
    flash_load_kv(smem_raw, t, bh, 64, 1);
    __syncthreads();

    // Q fragments: kc 0..3 = hi, 4..7 = lo
    uint32_t qf[8][4];
    #pragma unroll
    for (int kc = 0; kc < 8; kc++) {
        const __half* p = &Qs[(w * 16 + g) * 136 + kc * 16 + t4 * 2];
        qf[kc][0] = *(const uint32_t*)(p);
        qf[kc][1] = *(const uint32_t*)(p + 8 * 136);
        qf[kc][2] = *(const uint32_t*)(p + 8);
        qf[kc][3] = *(const uint32_t*)(p + 8 * 136 + 8);
    }

    const int r0 = q0 + w * 16 + g;
    float m0 = -1e38f, m1 = -1e38f, l0 = 0.f, l1 = 0.f;
    float oacc[8][4];
    #pragma unroll
    for (int nt = 0; nt < 8; nt++)
        #pragma unroll
        for (int c = 0; c < 4; c++) oacc[nt][c] = 0.f;

    const float C1 = 0.125f * 1.44269504f;

    for (int it = 0; it < 16; it++) {
        if (it < 15) asm volatile("cp.async.wait_group 1;\n");
        else         asm volatile("cp.async.wait_group 0;\n");
        __syncthreads();
        const int stage = it & 1;
        char* base = smem_raw + FL_QBYTES + stage * FL_STAGE;
        const __half* Ks = (const __half*)base;
        const __half* Vh = (const __half*)(base + FL_VHOFF);
        const __half* Vl = (const __half*)(base + FL_VLOFF);
        const int kt = it * 64;

        // S = (Qh + Ql) · Kh
        float sacc[8][4];
        #pragma unroll
        for (int nt = 0; nt < 8; nt++)
            #pragma unroll
            for (int c = 0; c < 4; c++) sacc[nt][c] = 0.f;
        #pragma unroll
        for (int nt = 0; nt < 8; nt++) {
            const __half* pr = &Ks[(nt * 8 + g) * 72 + t4 * 2];
            #pragma unroll
            for (int kc = 0; kc < 4; kc++) {
                uint32_t h0 = *(const uint32_t*)(pr + kc * 16);
                uint32_t h1 = *(const uint32_t*)(pr + kc * 16 + 8);
                mma16816(sacc[nt], qf[kc], h0, h1);         // Qh·Kh
                mma16816(sacc[nt], qf[4 + kc], h0, h1);     // Ql·Kh
            }
        }

        // epilogue: + bs*ksum, scale, bit-mask; log2 domain
        uint64_t w0 = g_mpack[(((size_t)b << 10) + r0) * 16 + it];
        uint64_t w1 = g_mpack[(((size_t)b << 10) + r0 + 8) * 16 + it];
        float mt0 = -1e38f, mt1 = -1e38f;
        #pragma unroll
        for (int nt = 0; nt < 8; nt++) {
            int c0 = kt + nt * 8 + t4 * 2;
            int sh = nt * 8 + t4 * 2;
            float2 ks2 = *(const float2*)&g_ksumT[((size_t)bh << 10) + c0];
            size_t mb0 = ((((size_t)b << 10) + r0) << 10) + c0;
            size_t mb1 = ((((size_t)b << 10) + r0 + 8) << 10) + c0;
            float2 bs0 = *(const float2*)&g_bs[mb0];
            float2 bs1 = *(const float2*)&g_bs[mb1];
            float s0 = (sacc[nt][0] + bs0.x * ks2.x) * C1;
            float s1 = (sacc[nt][1] + bs0.y * ks2.y) * C1;
            float s2 = (sacc[nt][2] + bs1.x * ks2.x) * C1;
            float s3 = (sacc[nt][3] + bs1.y * ks2.y) * C1;
            sacc[nt][0] = ((w0 >> sh) & 1)       ? -1e37f : s0;
            sacc[nt][1] = ((w0 >> (sh + 1)) & 1) ? -1e37f : s1;
            sacc[nt][2] = ((w1 >> sh) & 1)       ? -1e37f : s2;
            sacc[nt][3] = ((w1 >> (sh + 1)) & 1) ? -1e37f : s3;
            mt0 = fmaxf(mt0, fmaxf(sacc[nt][0], sacc[nt][1]));
            mt1 = fmaxf(mt1, fmaxf(sacc[nt][2], sacc[nt][3]));
        }
        mt0 = fmaxf(mt0, __shfl_xor_sync(0xffffffffu, mt0, 1));
        mt0 = fmaxf(mt0, __shfl_xor_sync(0xffffffffu, mt0, 2));
        mt1 = fmaxf(mt1, __shfl_xor_sync(0xffffffffu, mt1, 1));
        mt1 = fmaxf(mt1, __shfl_xor_sync(0xffffffffu, mt1, 2));
        float mn0 = fmaxf(m0, mt0), mn1 = fmaxf(m1, mt1);
        float sc0 = ex2f(m0 - mn0), sc1 = ex2f(m1 - mn1);
        m0 = mn0; m1 = mn1;
        l0 *= sc0; l1 *= sc1;

        // P = exp2(s - m) -> fp16 (hi only); rescale O
        uint32_t phi0[8], phi1[8];
        #pragma unroll
        for (int nt = 0; nt < 8; nt++) {
            float p0 = ex2f(sacc[nt][0] - m0), p1 = ex2f(sacc[nt][1] - m0);
            float p2 = ex2f(sacc[nt][2] - m1), p3 = ex2f(sacc[nt][3] - m1);
            l0 += p0 + p1; l1 += p2 + p3;
            __half2 h0 = __float22half2_rn(make_float2(p0, p1));
            __half2 h1 = __float22half2_rn(make_float2(p2, p3));
            phi0[nt] = *(uint32_t*)&h0;
            phi1[nt] = *(uint32_t*)&h1;
            oacc[nt][0] *= sc0; oacc[nt][1] *= sc0;
            oacc[nt][2] *= sc1; oacc[nt][3] *= sc1;
        }

        // O += Ph · (Vh + Vl)
        #pragma unroll
        for (int kc = 0; kc < 4; kc++) {
            uint32_t ah[4] = {phi0[2*kc], phi1[2*kc], phi0[2*kc+1], phi1[2*kc+1]};
            #pragma unroll
            for (int nt = 0; nt < 8; nt++) {
                const __half* ph = &Vh[(nt * 8 + g) * 72 + kc * 16 + t4 * 2];
                const __half* pl = &Vl[(nt * 8 + g) * 72 + kc * 16 + t4 * 2];
                uint32_t bh0 = *(const uint32_t*)(ph);
                uint32_t bh1 = *(const uint32_t*)(ph + 8);
                uint32_t bl0 = *(const uint32_t*)(pl);
                uint32_t bl1 = *(const uint32_t*)(pl + 8);
                mma16816(oacc[nt], ah, bh0, bh1);
                mma16816(oacc[nt], ah, bl0, bl1);
            }
        }
        __syncthreads();
        if (it + 2 < 16) flash_load_kv(smem_raw, t, bh, (it + 2) * 64, stage);
    }

    l0 += __shfl_xor_sync(0xffffffffu, l0, 1);
    l0 += __shfl_xor_sync(0xffffffffu, l0, 2);
    l1 += __shfl_xor_sync(0xffffffffu, l1, 1);
    l1 += __shfl_xor_sync(0xffffffffu, l1, 2);
    float inv0 = 1.0f / l0, inv1 = 1.0f / l1;
    size_t rowA0 = ((size_t)b << 10) + r0;
    size_t rowA1 = rowA0 + 8;
    #pragma unroll
    for (int nt = 0; nt < 8; nt++) {
        int col = (h << 6) + nt * 8 + t4 * 2;
        float o0 = oacc[nt][0] * inv0, o1 = oacc[nt][1] * inv0;
        float o2 = oacc[nt][2] * inv1, o3 = oacc[nt][3] * inv1;
        __half h0a, l0a, h1a, l1a, h2a, l2a, h3a, l3a;
        split2h(o0, h0a, l0a); split2h(o1, h1a, l1a);
        split2h(o2, h2a, l2a); split2h(o3, h3a, l3a);
        __half2 H0; H0.x=h0a; H0.y=h1a;
        __half2 L0; L0.x=l0a; L0.y=l1a;
        __half2 H1; H1.x=h2a; H1.y=h3a;
        __half2 L1; L1.x=l2a; L1.y=l3a;
        __half* d0 = g_sa + rowA0 * 2048 + col;
        __half* d1 = g_sa + rowA1 * 2048 + col;
        *(__half2*)(d0)        = H0;
        *(__half2*)(d0 + 1024) = L0;
        *(__half2*)(d1)        = H1;
        *(__half2*)(d1 + 1024) = L1;
    }
}

// ---------------- launch ----------------------------------------------------
extern "C" void kernel_launch(void* const* d_in, const int* in_sizes, int n_in,
                              void* d_out, int out_size) {
    const float* states      = (const float*)d_in[0];
    const float* keys        = (const float*)d_in[1];
    const float* masks       = (const float*)d_in[2];
    const void*  abias       = (const void*) d_in[3];
    const float* Wq          = (const float*)d_in[4];
    const float* Wk          = (const float*)d_in[5];
    const float* Wv          = (const float*)d_in[6];
    const float* Wout        = (const float*)d_in[7];
    const float* bias_embs   = (const float*)d_in[8];
    const float* bias_scalar = (const float*)d_in[9];
    float* out = (float*)d_out;
    int E = in_sizes[3] / 4;

    cudaFuncSetAttribute(flash_kernel,
                         cudaFuncAttributeMaxDynamicSharedMemorySize, FL_SMEM);
    cudaFuncSetAttribute(gemm_nt,
                         cudaFuncAttributeMaxDynamicSharedMemorySize, GSMEM);

    float *pq, *pk, *pv;
    __half *psa, *pka, *pwq, *pwk, *pwv, *pwo, *pqs, *pkb;
    cudaGetSymbolAddress((void**)&pq,  g_q);
    cudaGetSymbolAddress((void**)&pk,  g_k);
    cudaGetSymbolAddress((void**)&pv,  g_v);
    cudaGetSymbolAddress((void**)&psa, g_sa);
    cudaGetSymbolAddress((void**)&pka, g_ka);
    cudaGetSymbolAddress((void**)&pwq, g_wq);
    cudaGetSymbolAddress((void**)&pwk, g_wk);
    cudaGetSymbolAddress((void**)&pwv, g_wv);
    cudaGetSymbolAddress((void**)&pwo, g_wo);
    cudaGetSymbolAddress((void**)&pqs, g_qs);
    cudaGetSymbolAddress((void**)&pkb, g_kb);

    // conversions
    conv_a<<<8192, 256>>>((const float4*)states, psa);
    conv_a<<<8192, 256>>>((const float4*)keys,   pka);
    dim3 gt(32, 32);
    conv_bT<<<gt, 256>>>(Wq,   pwq, 1024);
    conv_bT<<<gt, 256>>>(Wk,   pwk, 1024);
    conv_bT<<<gt, 256>>>(Wv,   pwv, 1024);
    conv_bT<<<gt, 256>>>(Wout, pwo, 1024);
    mask_pack<<<512, 256>>>(masks);

    // projections on tensor cores (2-term fp16 split)
    dim3 gg(8, 64);
    gemm_nt<<<gg, 256, GSMEM>>>(psa, pwq, pq, 1024);
    gemm_nt<<<gg, 256, GSMEM>>>(pka, pwk, pk, 1024);
    gemm_nt<<<gg, 256, GSMEM>>>(pka, pwv, pv, 1024);

    // side computations
    ksum_kernel<<<(B_*T_*H_)/256, 256>>>();
    proj_kernel<<<1, 32>>>(bias_embs, bias_scalar);
    detect_kernel<<<1, 256>>>(abias, E);
    init_bs_kernel<<<(B_*T_*T_/4)/256, 256>>>();
    scatter_max_kernel<<<(E + 255)/256, 256>>>(abias, E);
    scatter_write_kernel<<<(E + 255)/256, 256>>>(abias, E);

    // operand prep for flash
    conv_qk<<<B_*H_*T_/8, 256>>>(pq, pqs);
    conv_k<<<B_*H_*T_/8, 256>>>(pk, pkb);
    dim3 gv(32, 2, 128);
    conv_vT<<<gv, 256>>>();

    // fused attention (writes ctx split-fp16 into g_sa)
    dim3 gf(T_/128, B_*H_);
    flash_kernel<<<gf, 256, FL_SMEM>>>();

    // output projection
    gemm_nt<<<gg, 256, GSMEM>>>(psa, pwo, out, 1024);
}

// round 13
// speedup vs baseline: 4.9614x; 1.0746x over previous
#include <cuda_runtime.h>
#include <cuda_fp16.h>
#include <cstdint>

#define B_ 8
#define T_ 1024
#define D_ 1024
#define H_ 16
#define A_ 64

// ---------------- scratch (device globals: allocation-free) ----------------
__device__ float g_v[B_*T_*H_*A_];          // [b,t,h,a] (V proj, fp32 for transpose)
__device__ float g_ksumT[B_*H_*T_];         // [(b,h),t]
__device__ float g_bs[B_*T_*T_];            // [b,q,k]
__device__ int   g_lastE[B_*T_*T_];
__device__ float g_proj[32];
__device__ int   g_is64;
__device__ uint64_t g_mpack[B_*T_*16];      // mask bits: [(b,q)][k/64]

// split-fp16 operands
__device__ __align__(16) __half g_sa[8192*2048];        // A-side [hi|lo]: states, later ctx
__device__ __align__(16) __half g_ka[8192*2048];        // keys [hi|lo]
__device__ __align__(16) __half g_wq[1024*1024];        // weights hi-only, [N][K]
__device__ __align__(16) __half g_wk[1024*1024];
__device__ __align__(16) __half g_wv[1024*1024];
__device__ __align__(16) __half g_wo[1024*1024];
__device__ __align__(16) __half g_qs[B_*H_*T_*128];     // Q [hi|lo], rows (b,h,t)
__device__ __align__(16) __half g_kb[B_*H_*T_*64];      // K hi-only, rows (b,h,t)
__device__ __align__(16) __half g_vhi[B_*H_*A_*T_];     // [(b,h),a,k]
__device__ __align__(16) __half g_vlo[B_*H_*A_*T_];

// ---------------- mma.sync m16n8k16 fp16 ------------------------------------
__device__ __forceinline__ void mma16816(float* d, const uint32_t* a,
                                         uint32_t b0, uint32_t b1) {
    asm volatile(
        "mma.sync.aligned.m16n8k16.row.col.f32.f16.f16.f32 "
        "{%0,%1,%2,%3}, {%4,%5,%6,%7}, {%8,%9}, {%0,%1,%2,%3};\n"
        : "+f"(d[0]), "+f"(d[1]), "+f"(d[2]), "+f"(d[3])
        : "r"(a[0]), "r"(a[1]), "r"(a[2]), "r"(a[3]), "r"(b0), "r"(b1));
}

__device__ __forceinline__ void ldsm_x4(uint32_t& r0, uint32_t& r1,
                                        uint32_t& r2, uint32_t& r3, uint32_t addr) {
    asm volatile("ldmatrix.sync.aligned.m8n8.x4.shared.b16 {%0,%1,%2,%3}, [%4];"
                 : "=r"(r0), "=r"(r1), "=r"(r2), "=r"(r3) : "r"(addr));
}

__device__ __forceinline__ float ex2f(float x) {
    float r;
    asm("ex2.approx.f32 %0, %1;" : "=f"(r) : "f"(x));
    return r;
}

__device__ __forceinline__ void cpa16s(uint32_t smem, const void* gmem) {
    asm volatile("cp.async.cg.shared.global [%0], [%1], 16;\n"
                 :: "r"(smem), "l"(gmem));
}

__device__ __forceinline__ void split2h(float v, __half& hi, __half& lo) {
    hi = __float2half_rn(v);
    lo = __float2half_rn(v - __half2float(hi));
}

// ---------------- 2-term split NT GEMM core ---------------------------------
// A [M][2048] fp16 [hi|lo]; B [N][1024] fp16 hi-only. Logical K=1024, BK=32.
// 128x128 tile, 256 threads (8 warps: 4m x 2n), 4-stage cp.async.
// Stage (24KB): Ah@0, Al@8192, Bh@16384; 128 rows x 64B each;
// swizzle: 16B chunk c at row r -> chunk (c ^ ((r>>1)&3)).
#define GNS 4
#define GSB 24576
#define GSMEM (GNS*GSB)

__device__ __forceinline__ void g_ld_stage(uint32_t sb, const __half* Ag,
                                           const __half* Bg, int k0, int t) {
    #pragma unroll
    for (int i = 0; i < 2; i++) {
        int j = t + (i << 8);              // 0..511
        int row = j >> 2, c = j & 3;
        uint32_t sw = (uint32_t)((c ^ ((row >> 1) & 3)) << 4);
        const __half* ga = Ag + (size_t)row * 2048 + k0 + c * 8;
        cpa16s(sb + row * 64 + sw,           ga);                              // Ah
        cpa16s(sb + 8192  + row * 64 + sw,   ga + 1024);                       // Al
        cpa16s(sb + 16384 + row * 64 + sw,   Bg + (size_t)row * 1024 + k0 + c * 8); // Bh
    }
}

// mainloop shared by both GEMM kernels (acc must be zeroed by caller)
__device__ __forceinline__ void gemm_mainloop(
    uint32_t dbase, const __half* Ag, const __half* Bg, int t,
    int wm, int wn, int lrow, int lchk, float acc[2][8][4])
{
    const int nIt = 32;
    #pragma unroll
    for (int s = 0; s < GNS - 1; s++) {
        g_ld_stage(dbase + s * GSB, Ag, Bg, s << 5, t);
        asm volatile("cp.async.commit_group;\n");
    }
    int st = 0, pst = GNS - 1;
    for (int i = 0; i < nIt; i++) {
        asm volatile("cp.async.wait_group %0;\n" :: "n"(GNS - 2));
        __syncthreads();
        if (i + GNS - 1 < nIt)
            g_ld_stage(dbase + pst * GSB, Ag, Bg, (i + 3) << 5, t);
        asm volatile("cp.async.commit_group;\n");

        const uint32_t sA = dbase + st * GSB;
        #pragma unroll
        for (int k16 = 0; k16 < 2; k16++) {
            const int chk = k16 * 2 + lchk;
            uint32_t afh[2][4], afl[2][4];
            #pragma unroll
            for (int mt = 0; mt < 2; mt++) {
                int row = wm + mt * 16 + lrow;
                uint32_t off = row * 64 + ((chk ^ ((row >> 1) & 3)) << 4);
                ldsm_x4(afh[mt][0], afh[mt][1], afh[mt][2], afh[mt][3], sA + off);
                ldsm_x4(afl[mt][0], afl[mt][1], afl[mt][2], afl[mt][3],
                        sA + 8192 + off);
            }
            #pragma unroll
            for (int nq = 0; nq < 4; nq++) {
                int row = wn + nq * 16 + lrow;
                uint32_t off = row * 64 + ((chk ^ ((row >> 1) & 3)) << 4);
                uint32_t h0, h1, h2, h3;
                ldsm_x4(h0, h1, h2, h3, sA + 16384 + off);
                mma16816(acc[0][nq*2+0], afh[0], h0, h2);
                mma16816(acc[0][nq*2+1], afh[0], h1, h3);
                mma16816(acc[1][nq*2+0], afh[1], h0, h2);
                mma16816(acc[1][nq*2+1], afh[1], h1, h3);
                mma16816(acc[0][nq*2+0], afl[0], h0, h2);
                mma16816(acc[0][nq*2+1], afl[0], h1, h3);
                mma16816(acc[1][nq*2+0], afl[1], h0, h2);
                mma16816(acc[1][nq*2+1], afl[1], h1, h3);
            }
        }
        st = (st + 1 == GNS) ? 0 : st + 1;
        pst = (pst + 1 == GNS) ? 0 : pst + 1;
    }
}

// fused Q/K/V projection GEMM; blockIdx.z: 0=Q, 1=K, 2=V
__global__ __launch_bounds__(256, 2) void proj_gemm() {
    extern __shared__ char gsm[];
    const uint32_t dbase = (uint32_t)__cvta_generic_to_shared(gsm);
    const int t = threadIdx.x;
    const int z = blockIdx.z;
    const int m0 = blockIdx.y * 128, n0 = blockIdx.x * 128;

    const __half* Ag = (z == 0) ? g_sa : g_ka;
    const __half* Bg = (z == 0) ? g_wq : (z == 1) ? g_wk : g_wv;
    Ag += (size_t)m0 * 2048;
    Bg += (size_t)n0 * 1024;

    const int w = t >> 5, lane = t & 31;
    const int wm = (w & 3) * 32, wn = (w >> 2) * 64;
    const int g  = lane >> 2, t4 = lane & 3;
    const int lrow = lane & 15;
    const int lchk = lane >> 4;

    float acc[2][8][4];
    #pragma unroll
    for (int i = 0; i < 2; i++)
        #pragma unroll
        for (int j = 0; j < 8; j++)
            #pragma unroll
            for (int c = 0; c < 4; c++) acc[i][j][c] = 0.f;

    gemm_mainloop(dbase, Ag, Bg, t, wm, wn, lrow, lchk, acc);

    if (z == 2) {
        // V: fp32 [b,t,h,a] (row-major [M][1024])
        #pragma unroll
        for (int mt = 0; mt < 2; mt++) {
            #pragma unroll
            for (int nt8 = 0; nt8 < 8; nt8++) {
                int row = m0 + wm + mt * 16 + g;
                int col = n0 + wn + nt8 * 8 + t4 * 2;
                *(float2*)&g_v[(size_t)row * 1024 + col] =
                    make_float2(acc[mt][nt8][0], acc[mt][nt8][1]);
                *(float2*)&g_v[(size_t)(row + 8) * 1024 + col] =
                    make_float2(acc[mt][nt8][2], acc[mt][nt8][3]);
            }
        }
    } else if (z == 0) {
        // Q: split [hi|lo] into g_qs rows (b,h,t)
        const int h = (n0 + wn) >> 6;
        #pragma unroll
        for (int mt = 0; mt < 2; mt++) {
            int r = m0 + wm + mt * 16 + g;
            int b = r >> 10, tt = r & 1023;
            size_t rq0 = ((((size_t)b << 4) + h) << 10) + tt;
            #pragma unroll
            for (int nt8 = 0; nt8 < 8; nt8++) {
                int a = nt8 * 8 + t4 * 2;
                __half h0,l0,h1,l1,h2,l2,h3,l3;
                split2h(acc[mt][nt8][0], h0, l0);
                split2h(acc[mt][nt8][1], h1, l1);
                split2h(acc[mt][nt8][2], h2, l2);
                split2h(acc[mt][nt8][3], h3, l3);
                __half2 H0; H0.x=h0; H0.y=h1;
                __half2 L0; L0.x=l0; L0.y=l1;
                __half2 H1; H1.x=h2; H1.y=h3;
                __half2 L1; L1.x=l2; L1.y=l3;
                *(__half2*)&g_qs[rq0 * 128 + a]            = H0;
                *(__half2*)&g_qs[rq0 * 128 + 64 + a]       = L0;
                *(__half2*)&g_qs[(rq0 + 8) * 128 + a]      = H1;
                *(__half2*)&g_qs[(rq0 + 8) * 128 + 64 + a] = L1;
            }
        }
    } else {
        // K: hi-only into g_kb rows (b,h,t) + fused ksumT
        const int h = (n0 + wn) >> 6;
        #pragma unroll
        for (int mt = 0; mt < 2; mt++) {
            int r = m0 + wm + mt * 16 + g;
            int b = r >> 10, tt = r & 1023;
            size_t rk0 = ((((size_t)b << 4) + h) << 10) + tt;
            float s0 = 0.f, s1 = 0.f;
            #pragma unroll
            for (int nt8 = 0; nt8 < 8; nt8++) {
                int a = nt8 * 8 + t4 * 2;
                __half2 H0; H0.x = __float2half_rn(acc[mt][nt8][0]);
                            H0.y = __float2half_rn(acc[mt][nt8][1]);
                __half2 H1; H1.x = __float2half_rn(acc[mt][nt8][2]);
                            H1.y = __float2half_rn(acc[mt][nt8][3]);
                *(__half2*)&g_kb[rk0 * 64 + a]       = H0;
                *(__half2*)&g_kb[(rk0 + 8) * 64 + a] = H1;
                s0 += acc[mt][nt8][0] + acc[mt][nt8][1];
                s1 += acc[mt][nt8][2] + acc[mt][nt8][3];
            }
            s0 += __shfl_xor_sync(0xffffffffu, s0, 1);
            s0 += __shfl_xor_sync(0xffffffffu, s0, 2);
            s1 += __shfl_xor_sync(0xffffffffu, s1, 1);
            s1 += __shfl_xor_sync(0xffffffffu, s1, 2);
            if (t4 == 0) {
                g_ksumT[rk0]     = s0;
                g_ksumT[rk0 + 8] = s1;
            }
        }
    }
}

// output projection: C = (Ah+Al)·Wo^T, fp32 out
__global__ __launch_bounds__(256, 2) void gemm_out(float* __restrict__ C) {
    extern __shared__ char gsm[];
    const uint32_t dbase = (uint32_t)__cvta_generic_to_shared(gsm);
    const int t = threadIdx.x;
    const int m0 = blockIdx.y * 128, n0 = blockIdx.x * 128;
    const __half* Ag = g_sa + (size_t)m0 * 2048;
    const __half* Bg = g_wo + (size_t)n0 * 1024;

    const int w = t >> 5, lane = t & 31;
    const int wm = (w & 3) * 32, wn = (w >> 2) * 64;
    const int g  = lane >> 2, t4 = lane & 3;
    const int lrow = lane & 15;
    const int lchk = lane >> 4;

    float acc[2][8][4];
    #pragma unroll
    for (int i = 0; i < 2; i++)
        #pragma unroll
        for (int j = 0; j < 8; j++)
            #pragma unroll
            for (int c = 0; c < 4; c++) acc[i][j][c] = 0.f;

    gemm_mainloop(dbase, Ag, Bg, t, wm, wn, lrow, lchk, acc);

    #pragma unroll
    for (int mt = 0; mt < 2; mt++) {
        #pragma unroll
        for (int nt8 = 0; nt8 < 8; nt8++) {
            int row = m0 + wm + mt * 16 + g;
            int col = n0 + wn + nt8 * 8 + t4 * 2;
            *(float2*)&C[(size_t)row * 1024 + col] =
                make_float2(acc[mt][nt8][0], acc[mt][nt8][1]);
            *(float2*)&C[(size_t)(row + 8) * 1024 + col] =
                make_float2(acc[mt][nt8][2], acc[mt][nt8][3]);
        }
    }
}

// ---------------- conversions ------------------------------------------------
// f32 [M][1024] -> fp16 [M][2048] as [hi|lo]
__global__ void conv_a(const float4* __restrict__ in, __half* __restrict__ out) {
    size_t idx = (size_t)blockIdx.x * 256 + threadIdx.x;
    float4 v = in[idx];
    size_t m = idx >> 8;
    int k4 = (int)(idx & 255) * 4;
    __half h0,h1,h2,h3,l0,l1,l2,l3;
    split2h(v.x,h0,l0); split2h(v.y,h1,l1); split2h(v.z,h2,l2); split2h(v.w,h3,l3);
    __half2 hp0, hp1, lp0, lp1;
    hp0.x=h0; hp0.y=h1; hp1.x=h2; hp1.y=h3;
    lp0.x=l0; lp0.y=l1; lp1.x=l2; lp1.y=l3;
    __half* o = out + m * 2048 + k4;
    ((__half2*)o)[0] = hp0;          ((__half2*)o)[1] = hp1;
    ((__half2*)(o + 1024))[0] = lp0; ((__half2*)(o + 1024))[1] = lp1;
}

// f32 [K=1024][N] -> fp16 [N][1024] transposed, hi only
__global__ void conv_bT(const float* __restrict__ in, __half* __restrict__ out,
                        int N) {
    __shared__ float tile[32][33];
    int k0 = blockIdx.y * 32, n0 = blockIdx.x * 32;
    int tx = threadIdx.x & 31, ty = threadIdx.x >> 5;
    #pragma unroll
    for (int i = 0; i < 4; i++)
        tile[ty + 8*i][tx] = in[(size_t)(k0 + ty + 8*i) * N + n0 + tx];
    __syncthreads();
    #pragma unroll
    for (int i = 0; i < 4; i++) {
        int n = n0 + ty + 8*i, k = k0 + tx;
        out[(size_t)n * 1024 + k] = __float2half_rn(tile[tx][ty + 8*i]);
    }
}

// g_v [b,k,h,a] -> g_vhi/g_vlo [(b,h), a, k]
__global__ void conv_vT() {
    __shared__ float tile[32][33];
    int bh = blockIdx.z, b = bh >> 4, h = bh & 15;
    int k0 = blockIdx.x * 32, a0 = blockIdx.y * 32;
    int tx = threadIdx.x & 31, ty = threadIdx.x >> 5;
    #pragma unroll
    for (int i = 0; i < 4; i++)
        tile[ty + 8*i][tx] =
            g_v[((((size_t)b << 10) + k0 + ty + 8*i) * 16 + h) * 64 + a0 + tx];
    __syncthreads();
    #pragma unroll
    for (int i = 0; i < 4; i++) {
        int a = a0 + ty + 8*i, k = k0 + tx;
        __half hi, lo; split2h(tile[tx][ty + 8*i], hi, lo);
        size_t o = ((size_t)bh * 64 + a) * 1024 + k;
        g_vhi[o] = hi;
        g_vlo[o] = lo;
    }
}

// masks f32 [b,q,k] -> bit-packed uint64 [(b,q)][k/64]
__global__ void mask_pack(const float* __restrict__ masks) {
    int idx = blockIdx.x * 256 + threadIdx.x;       // 0..B*T*16-1
    const float4* p = (const float4*)masks + (size_t)idx * 16;
    uint64_t bits = 0;
    #pragma unroll
    for (int i = 0; i < 16; i++) {
        float4 v = p[i];
        bits |= (uint64_t)(v.x != 0.f) << (i*4 + 0);
        bits |= (uint64_t)(v.y != 0.f) << (i*4 + 1);
        bits |= (uint64_t)(v.z != 0.f) << (i*4 + 2);
        bits |= (uint64_t)(v.w != 0.f) << (i*4 + 3);
    }
    g_mpack[idx] = bits;
}

__global__ void proj_kernel(const float* __restrict__ embs,
                            const float* __restrict__ sc) {
    int t = threadIdx.x;
    if (t < 32) {
        float s = 0.f;
        #pragma unroll
        for (int a = 0; a < 64; a++) s += embs[t*64 + a] * sc[a];
        g_proj[t] = s;
    }
}

__global__ void detect_kernel(const void* __restrict__ ab, int E) {
    __shared__ int bad;
    if (threadIdx.x == 0) bad = 0;
    __syncthreads();
    int n = E < 256 ? E : 256;
    if ((int)threadIdx.x < n) {
        const long long* p = (const long long*)ab + (size_t)threadIdx.x * 4;
        long long et = p[0], bi = p[1], qi = p[2], ki = p[3];
        if (et < 0 || et >= 32 || bi < 0 || bi >= B_ ||
            qi < 0 || qi >= T_ || ki < 0 || ki >= T_) atomicExch(&bad, 1);
    }
    __syncthreads();
    if (threadIdx.x == 0) g_is64 = !bad;
}

__global__ void init_bs_kernel() {
    int i = blockIdx.x * blockDim.x + threadIdx.x;
    ((float4*)g_bs)[i]  = make_float4(0.f, 0.f, 0.f, 0.f);
    ((int4*)g_lastE)[i] = make_int4(-1, -1, -1, -1);
}

__device__ __forceinline__ void load_edge(const void* ab, int e,
                                          int& et, int& bi, int& qi, int& ki) {
    if (g_is64) {
        const long long* r = (const long long*)ab + (size_t)e * 4;
        et = (int)r[0]; bi = (int)r[1]; qi = (int)r[2]; ki = (int)r[3];
    } else {
        const int* r = (const int*)ab + (size_t)e * 4;
        et = r[0]; bi = r[1]; qi = r[2]; ki = r[3];
    }
}

__global__ void scatter_max_kernel(const void* __restrict__ ab, int E) {
    int e = blockIdx.x * blockDim.x + threadIdx.x;
    if (e >= E) return;
    int et, bi, qi, ki; load_edge(ab, e, et, bi, qi, ki);
    atomicMax(&g_lastE[((size_t)bi*T_ + qi)*T_ + ki], e);
}

__global__ void scatter_write_kernel(const void* __restrict__ ab, int E) {
    int e = blockIdx.x * blockDim.x + threadIdx.x;
    if (e >= E) return;
    int et, bi, qi, ki; load_edge(ab, e, et, bi, qi, ki);
    size_t idx = ((size_t)bi*T_ + qi)*T_ + ki;
    if (g_lastE[idx] == e) g_bs[idx] = g_proj[et];
}

// ---------------- flash attention: fused score+softmax+context ---------------
// Q [hi|lo] 128-wide; K hi-only 64-wide; V hi/lo planes.
// Q tile 128x136 pitch; stage = { K 64x72, Vh 64x72, Vl 64x72 }.
#define FL_QBYTES 34816
#define FL_STAGE  27648
#define FL_VHOFF  9216
#define FL_VLOFF  18432
#define FL_SMEM   (FL_QBYTES + 2*FL_STAGE)

__device__ __forceinline__ void cpa16(void* smem, const void* gmem) {
    uint32_t d = (uint32_t)__cvta_generic_to_shared(smem);
    asm volatile("cp.async.cg.shared.global [%0], [%1], 16;\n" :: "r"(d), "l"(gmem));
}

__device__ __forceinline__ void flash_load_kv(char* smem_raw, int t, int bh, int kt,
                                              int stage) {
    char* base = smem_raw + FL_QBYTES + stage * FL_STAGE;
    __half* Ks = (__half*)base;
    __half* Vh = (__half*)(base + FL_VHOFF);
    __half* Vl = (__half*)(base + FL_VLOFF);
    const __half* ksrc = g_kb + ((size_t)(bh << 10) + kt) * 64;
    #pragma unroll
    for (int i = 0; i < 2; i++) {
        int u = t + i * 256;
        int row = u >> 3, c = u & 7;
        cpa16(&Ks[row * 72 + c * 8], &ksrc[(size_t)row * 64 + c * 8]);
    }
    const __half* vh = g_vhi + (size_t)bh * 64 * 1024 + kt;
    const __half* vl = g_vlo + (size_t)bh * 64 * 1024 + kt;
    #pragma unroll
    for (int i = 0; i < 2; i++) {
        int u = t + i * 256;
        int row = u >> 3, c = u & 7;
        cpa16(&Vh[row * 72 + c * 8], &vh[(size_t)row * 1024 + c * 8]);
        cpa16(&Vl[row * 72 + c * 8], &vl[(size_t)row * 1024 + c * 8]);
    }
    asm volatile("cp.async.commit_group;\n");
}

__global__ __launch_bounds__(256) void flash_kernel() {
    extern __shared__ char smem_raw[];
    __half* Qs = (__half*)smem_raw;             // [128][136]
    const int t = threadIdx.x;
    const int w = t >> 5, lane = t & 31;
    const int g = lane >> 2, t4 = lane & 3;
    const int bh = blockIdx.y, b = bh >> 4, h = bh & 15;
    const int q0 = blockIdx.x * 128;

    {
        const __half* src = g_qs + ((size_t)(bh << 10) + q0) * 128;
        #pragma unroll
        for (int i = 0; i < 8; i++) {
            int u = t + i * 256;
            int row = u >> 4, c = u & 15;
            *(uint4*)&Qs[row * 136 + c * 8] = *(const uint4*)&src[(size_t)row * 128 + c * 8];
        }
    }
    flash_load_kv(smem_raw, t, bh, 0, 0);
    flash_load_kv(smem_raw, t, bh, 64, 1);
    __syncthreads();

    uint32_t qf[8][4];
    #pragma unroll
    for (int kc = 0; kc < 8; kc++) {
        const __half* p = &Qs[(w * 16 + g) * 136 + kc * 16 + t4 * 2];
        qf[kc][0] = *(const uint32_t*)(p);
        qf[kc][1] = *(const uint32_t*)(p + 8 * 136);
        qf[kc][2] = *(const uint32_t*)(p + 8);
        qf[kc][3] = *(const uint32_t*)(p + 8 * 136 + 8);
    }

    const int r0 = q0 + w * 16 + g;
    float m0 = -1e38f, m1 = -1e38f, l0 = 0.f, l1 = 0.f;
    float oacc[8][4];
    #pragma unroll
    for (int nt = 0; nt < 8; nt++)
        #pragma unroll
        for (int c = 0; c < 4; c++) oacc[nt][c] = 0.f;

    const float C1 = 0.125f * 1.44269504f;

    for (int it = 0; it < 16; it++) {
        if (it < 15) asm volatile("cp.async.wait_group 1;\n");
        else         asm volatile("cp.async.wait_group 0;\n");
        __syncthreads();
        const int stage = it & 1;
        char* base = smem_raw + FL_QBYTES + stage * FL_STAGE;
        const __half* Ks = (const __half*)base;
        const __half* Vh = (const __half*)(base + FL_VHOFF);
        const __half* Vl = (const __half*)(base + FL_VLOFF);
        const int kt = it * 64;

        float sacc[8][4];
        #pragma unroll
        for (int nt = 0; nt < 8; nt++)
            #pragma unroll
            for (int c = 0; c < 4; c++) sacc[nt][c] = 0.f;
        #pragma unroll
        for (int nt = 0; nt < 8; nt++) {
            const __half* pr = &Ks[(nt * 8 + g) * 72 + t4 * 2];
            #pragma unroll
            for (int kc = 0; kc < 4; kc++) {
                uint32_t h0 = *(const uint32_t*)(pr + kc * 16);
                uint32_t h1 = *(const uint32_t*)(pr + kc * 16 + 8);
                mma16816(sacc[nt], qf[kc], h0, h1);         // Qh·Kh
                mma16816(sacc[nt], qf[4 + kc], h0, h1);     // Ql·Kh
            }
        }

        uint64_t w0 = g_mpack[(((size_t)b << 10) + r0) * 16 + it];
        uint64_t w1 = g_mpack[(((size_t)b << 10) + r0 + 8) * 16 + it];
        float mt0 = -1e38f, mt1 = -1e38f;
        #pragma unroll
        for (int nt = 0; nt < 8; nt++) {
            int c0 = kt + nt * 8 + t4 * 2;
            int sh = nt * 8 + t4 * 2;
            float2 ks2 = *(const float2*)&g_ksumT[((size_t)bh << 10) + c0];
            size_t mb0 = ((((size_t)b << 10) + r0) << 10) + c0;
            size_t mb1 = ((((size_t)b << 10) + r0 + 8) << 10) + c0;
            float2 bs0 = *(const float2*)&g_bs[mb0];
            float2 bs1 = *(const float2*)&g_bs[mb1];
            float s0 = (sacc[nt][0] + bs0.x * ks2.x) * C1;
            float s1 = (sacc[nt][1] + bs0.y * ks2.y) * C1;
            float s2 = (sacc[nt][2] + bs1.x * ks2.x) * C1;
            float s3 = (sacc[nt][3] + bs1.y * ks2.y) * C1;
            sacc[nt][0] = ((w0 >> sh) & 1)       ? -1e37f : s0;
            sacc[nt][1] = ((w0 >> (sh + 1)) & 1) ? -1e37f : s1;
            sacc[nt][2] = ((w1 >> sh) & 1)       ? -1e37f : s2;
            sacc[nt][3] = ((w1 >> (sh + 1)) & 1) ? -1e37f : s3;
            mt0 = fmaxf(mt0, fmaxf(sacc[nt][0], sacc[nt][1]));
            mt1 = fmaxf(mt1, fmaxf(sacc[nt][2], sacc[nt][3]));
        }
        mt0 = fmaxf(mt0, __shfl_xor_sync(0xffffffffu, mt0, 1));
        mt0 = fmaxf(mt0, __shfl_xor_sync(0xffffffffu, mt0, 2));
        mt1 = fmaxf(mt1, __shfl_xor_sync(0xffffffffu, mt1, 1));
        mt1 = fmaxf(mt1, __shfl_xor_sync(0xffffffffu, mt1, 2));
        float mn0 = fmaxf(m0, mt0), mn1 = fmaxf(m1, mt1);
        float sc0 = ex2f(m0 - mn0), sc1 = ex2f(m1 - mn1);
        m0 = mn0; m1 = mn1;
        l0 *= sc0; l1 *= sc1;

        uint32_t phi0[8], phi1[8];
        #pragma unroll
        for (int nt = 0; nt < 8; nt++) {
            float p0 = ex2f(sacc[nt][0] - m0), p1 = ex2f(sacc[nt][1] - m0);
            float p2 = ex2f(sacc[nt][2] - m1), p3 = ex2f(sacc[nt][3] - m1);
            l0 += p0 + p1; l1 += p2 + p3;
            __half2 h0 = __float22half2_rn(make_float2(p0, p1));
            __half2 h1 = __float22half2_rn(make_float2(p2, p3));
            phi0[nt] = *(uint32_t*)&h0;
            phi1[nt] = *(uint32_t*)&h1;
            oacc[nt][0] *= sc0; oacc[nt][1] *= sc0;
            oacc[nt][2] *= sc1; oacc[nt][3] *= sc1;
        }

        #pragma unroll
        for (int kc = 0; kc < 4; kc++) {
            uint32_t ah[4] = {phi0[2*kc], phi1[2*kc], phi0[2*kc+1], phi1[2*kc+1]};
            #pragma unroll
            for (int nt = 0; nt < 8; nt++) {
                const __half* ph = &Vh[(nt * 8 + g) * 72 + kc * 16 + t4 * 2];
                const __half* pl = &Vl[(nt * 8 + g) * 72 + kc * 16 + t4 * 2];
                uint32_t bh0 = *(const uint32_t*)(ph);
                uint32_t bh1 = *(const uint32_t*)(ph + 8);
                uint32_t bl0 = *(const uint32_t*)(pl);
                uint32_t bl1 = *(const uint32_t*)(pl + 8);
                mma16816(oacc[nt], ah, bh0, bh1);
                mma16816(oacc[nt], ah, bl0, bl1);
            }
        }
        __syncthreads();
        if (it + 2 < 16) flash_load_kv(smem_raw, t, bh, (it + 2) * 64, stage);
    }

    l0 += __shfl_xor_sync(0xffffffffu, l0, 1);
    l0 += __shfl_xor_sync(0xffffffffu, l0, 2);
    l1 += __shfl_xor_sync(0xffffffffu, l1, 1);
    l1 += __shfl_xor_sync(0xffffffffu, l1, 2);
    float inv0 = 1.0f / l0, inv1 = 1.0f / l1;
    size_t rowA0 = ((size_t)b << 10) + r0;
    size_t rowA1 = rowA0 + 8;
    #pragma unroll
    for (int nt = 0; nt < 8; nt++) {
        int col = (h << 6) + nt * 8 + t4 * 2;
        float o0 = oacc[nt][0] * inv0, o1 = oacc[nt][1] * inv0;
        float o2 = oacc[nt][2] * inv1, o3 = oacc[nt][3] * inv1;
        __half h0a, l0a, h1a, l1a, h2a, l2a, h3a, l3a;
        split2h(o0, h0a, l0a); split2h(o1, h1a, l1a);
        split2h(o2, h2a, l2a); split2h(o3, h3a, l3a);
        __half2 H0; H0.x=h0a; H0.y=h1a;
        __half2 L0; L0.x=l0a; L0.y=l1a;
        __half2 H1; H1.x=h2a; H1.y=h3a;
        __half2 L1; L1.x=l2a; L1.y=l3a;
        __half* d0 = g_sa + rowA0 * 2048 + col;
        __half* d1 = g_sa + rowA1 * 2048 + col;
        *(__half2*)(d0)        = H0;
        *(__half2*)(d0 + 1024) = L0;
        *(__half2*)(d1)        = H1;
        *(__half2*)(d1 + 1024) = L1;
    }
}

// ---------------- launch ----------------------------------------------------
extern "C" void kernel_launch(void* const* d_in, const int* in_sizes, int n_in,
                              void* d_out, int out_size) {
    const float* states      = (const float*)d_in[0];
    const float* keys        = (const float*)d_in[1];
    const float* masks       = (const float*)d_in[2];
    const void*  abias       = (const void*) d_in[3];
    const float* Wq          = (const float*)d_in[4];
    const float* Wk          = (const float*)d_in[5];
    const float* Wv          = (const float*)d_in[6];
    const float* Wout        = (const float*)d_in[7];
    const float* bias_embs   = (const float*)d_in[8];
    const float* bias_scalar = (const float*)d_in[9];
    float* out = (float*)d_out;
    int E = in_sizes[3] / 4;

    cudaFuncSetAttribute(flash_kernel,
                         cudaFuncAttributeMaxDynamicSharedMemorySize, FL_SMEM);
    cudaFuncSetAttribute(proj_gemm,
                         cudaFuncAttributeMaxDynamicSharedMemorySize, GSMEM);
    cudaFuncSetAttribute(gemm_out,
                         cudaFuncAttributeMaxDynamicSharedMemorySize, GSMEM);

    __half *psa, *pka, *pwq, *pwk, *pwv, *pwo;
    cudaGetSymbolAddress((void**)&psa, g_sa);
    cudaGetSymbolAddress((void**)&pka, g_ka);
    cudaGetSymbolAddress((void**)&pwq, g_wq);
    cudaGetSymbolAddress((void**)&pwk, g_wk);
    cudaGetSymbolAddress((void**)&pwv, g_wv);
    cudaGetSymbolAddress((void**)&pwo, g_wo);

    // conversions
    conv_a<<<8192, 256>>>((const float4*)states, psa);
    conv_a<<<8192, 256>>>((const float4*)keys,   pka);
    dim3 gt(32, 32);
    conv_bT<<<gt, 256>>>(Wq,   pwq, 1024);
    conv_bT<<<gt, 256>>>(Wk,   pwk, 1024);
    conv_bT<<<gt, 256>>>(Wv,   pwv, 1024);
    conv_bT<<<gt, 256>>>(Wout, pwo, 1024);
    mask_pack<<<512, 256>>>(masks);

    // fused Q/K/V projections (epilogues write flash layouts + ksum directly)
    dim3 gp(8, 64, 3);
    proj_gemm<<<gp, 256, GSMEM>>>();

    // side computations
    proj_kernel<<<1, 32>>>(bias_embs, bias_scalar);
    detect_kernel<<<1, 256>>>(abias, E);
    init_bs_kernel<<<(B_*T_*T_/4)/256, 256>>>();
    scatter_max_kernel<<<(E + 255)/256, 256>>>(abias, E);
    scatter_write_kernel<<<(E + 255)/256, 256>>>(abias, E);

    // V transpose for flash
    dim3 gv(32, 2, 128);
    conv_vT<<<gv, 256>>>();

    // fused attention (writes ctx split-fp16 into g_sa)
    dim3 gf(T_/128, B_*H_);
    flash_kernel<<<gf, 256, FL_SMEM>>>();

    // output projection
    dim3 gg(8, 64);
    gemm_out<<<gg, 256, GSMEM>>>(out);
}

// round 15
// speedup vs baseline: 6.2139x; 1.2524x over previous
#include <cuda_runtime.h>
#include <cuda_fp16.h>
#include <cstdint>

#define B_ 8
#define T_ 1024
#define D_ 1024
#define H_ 16
#define A_ 64

// ---------------- scratch (device globals: allocation-free) ----------------
__device__ float g_v[B_*T_*H_*A_];          // [b,t,h,a] (V proj, fp32 for transpose)
__device__ float g_ksumT[B_*H_*T_];         // [(b,h),t]
__device__ __half g_bs[B_*T_*T_];           // [b,q,k] fp16
__device__ int   g_lastE[B_*T_*T_];
__device__ float g_proj[32];
__device__ int   g_is64;
__device__ uint64_t g_mpack[B_*T_*16];      // mask bits: [(b,q)][k/64]

// split-fp16 operands
__device__ __align__(16) __half g_sa[8192*2048];        // A-side [hi|lo]: states, later ctx
__device__ __align__(16) __half g_ka[8192*2048];        // keys [hi|lo]
__device__ __align__(16) __half g_wq[1024*1024];        // weights hi-only, [N][K]
__device__ __align__(16) __half g_wk[1024*1024];
__device__ __align__(16) __half g_wv[1024*1024];
__device__ __align__(16) __half g_wo[1024*1024];
__device__ __align__(16) __half g_qs[B_*H_*T_*128];     // Q [hi|lo], rows (b,h,t)
__device__ __align__(16) __half g_kb[B_*H_*T_*64];      // K hi-only, rows (b,h,t)
__device__ __align__(16) __half g_vhi[B_*H_*A_*T_];     // [(b,h),a,k]
__device__ __align__(16) __half g_vlo[B_*H_*A_*T_];

// ---------------- mma.sync m16n8k16 fp16 ------------------------------------
__device__ __forceinline__ void mma16816(float* d, const uint32_t* a,
                                         uint32_t b0, uint32_t b1) {
    asm volatile(
        "mma.sync.aligned.m16n8k16.row.col.f32.f16.f16.f32 "
        "{%0,%1,%2,%3}, {%4,%5,%6,%7}, {%8,%9}, {%0,%1,%2,%3};\n"
        : "+f"(d[0]), "+f"(d[1]), "+f"(d[2]), "+f"(d[3])
        : "r"(a[0]), "r"(a[1]), "r"(a[2]), "r"(a[3]), "r"(b0), "r"(b1));
}

__device__ __forceinline__ void ldsm_x4(uint32_t& r0, uint32_t& r1,
                                        uint32_t& r2, uint32_t& r3, uint32_t addr) {
    asm volatile("ldmatrix.sync.aligned.m8n8.x4.shared.b16 {%0,%1,%2,%3}, [%4];"
                 : "=r"(r0), "=r"(r1), "=r"(r2), "=r"(r3) : "r"(addr));
}

__device__ __forceinline__ float ex2f(float x) {
    float r;
    asm("ex2.approx.f32 %0, %1;" : "=f"(r) : "f"(x));
    return r;
}

__device__ __forceinline__ void cpa16s(uint32_t smem, const void* gmem) {
    asm volatile("cp.async.cg.shared.global [%0], [%1], 16;\n"
                 :: "r"(smem), "l"(gmem));
}

__device__ __forceinline__ void split2h(float v, __half& hi, __half& lo) {
    hi = __float2half_rn(v);
    lo = __float2half_rn(v - __half2float(hi));
}

// ---------------- 2-term split NT GEMM core ---------------------------------
// A [M][2048] fp16 [hi|lo]; B [N][1024] fp16 hi-only. Logical K=1024, BK=32.
// 128x128 tile, 256 threads (8 warps: 4m x 2n), 4-stage cp.async.
// Stage (24KB): Ah@0, Al@8192, Bh@16384; 128 rows x 64B each;
// swizzle: 16B chunk c at row r -> chunk (c ^ ((r>>1)&3)).
#define GNS 4
#define GSB 24576
#define GSMEM (GNS*GSB)

__device__ __forceinline__ void g_ld_stage(uint32_t sb, const __half* Ag,
                                           const __half* Bg, int k0, int t) {
    #pragma unroll
    for (int i = 0; i < 2; i++) {
        int j = t + (i << 8);              // 0..511
        int row = j >> 2, c = j & 3;
        uint32_t sw = (uint32_t)((c ^ ((row >> 1) & 3)) << 4);
        const __half* ga = Ag + (size_t)row * 2048 + k0 + c * 8;
        cpa16s(sb + row * 64 + sw,           ga);                              // Ah
        cpa16s(sb + 8192  + row * 64 + sw,   ga + 1024);                       // Al
        cpa16s(sb + 16384 + row * 64 + sw,   Bg + (size_t)row * 1024 + k0 + c * 8); // Bh
    }
}

__device__ __forceinline__ void gemm_mainloop(
    uint32_t dbase, const __half* Ag, const __half* Bg, int t,
    int wm, int wn, int lrow, int lchk, float acc[2][8][4])
{
    const int nIt = 32;
    #pragma unroll
    for (int s = 0; s < GNS - 1; s++) {
        g_ld_stage(dbase + s * GSB, Ag, Bg, s << 5, t);
        asm volatile("cp.async.commit_group;\n");
    }
    int st = 0, pst = GNS - 1;
    for (int i = 0; i < nIt; i++) {
        asm volatile("cp.async.wait_group %0;\n" :: "n"(GNS - 2));
        __syncthreads();
        if (i + GNS - 1 < nIt)
            g_ld_stage(dbase + pst * GSB, Ag, Bg, (i + 3) << 5, t);
        asm volatile("cp.async.commit_group;\n");

        const uint32_t sA = dbase + st * GSB;
        #pragma unroll
        for (int k16 = 0; k16 < 2; k16++) {
            const int chk = k16 * 2 + lchk;
            uint32_t afh[2][4], afl[2][4];
            #pragma unroll
            for (int mt = 0; mt < 2; mt++) {
                int row = wm + mt * 16 + lrow;
                uint32_t off = row * 64 + ((chk ^ ((row >> 1) & 3)) << 4);
                ldsm_x4(afh[mt][0], afh[mt][1], afh[mt][2], afh[mt][3], sA + off);
                ldsm_x4(afl[mt][0], afl[mt][1], afl[mt][2], afl[mt][3],
                        sA + 8192 + off);
            }
            #pragma unroll
            for (int nq = 0; nq < 4; nq++) {
                int row = wn + nq * 16 + lrow;
                uint32_t off = row * 64 + ((chk ^ ((row >> 1) & 3)) << 4);
                uint32_t h0, h1, h2, h3;
                ldsm_x4(h0, h1, h2, h3, sA + 16384 + off);
                mma16816(acc[0][nq*2+0], afh[0], h0, h2);
                mma16816(acc[0][nq*2+1], afh[0], h1, h3);
                mma16816(acc[1][nq*2+0], afh[1], h0, h2);
                mma16816(acc[1][nq*2+1], afh[1], h1, h3);
                mma16816(acc[0][nq*2+0], afl[0], h0, h2);
                mma16816(acc[0][nq*2+1], afl[0], h1, h3);
                mma16816(acc[1][nq*2+0], afl[1], h0, h2);
                mma16816(acc[1][nq*2+1], afl[1], h1, h3);
            }
        }
        st = (st + 1 == GNS) ? 0 : st + 1;
        pst = (pst + 1 == GNS) ? 0 : pst + 1;
    }
}

// fused Q/K/V projection GEMM; blockIdx.z: 0=Q, 1=K, 2=V
__global__ __launch_bounds__(256, 2) void proj_gemm() {
    extern __shared__ char gsm[];
    const uint32_t dbase = (uint32_t)__cvta_generic_to_shared(gsm);
    const int t = threadIdx.x;
    const int z = blockIdx.z;
    const int m0 = blockIdx.y * 128, n0 = blockIdx.x * 128;

    const __half* Ag = (z == 0) ? g_sa : g_ka;
    const __half* Bg = (z == 0) ? g_wq : (z == 1) ? g_wk : g_wv;
    Ag += (size_t)m0 * 2048;
    Bg += (size_t)n0 * 1024;

    const int w = t >> 5, lane = t & 31;
    const int wm = (w & 3) * 32, wn = (w >> 2) * 64;
    const int g  = lane >> 2, t4 = lane & 3;
    const int lrow = lane & 15;
    const int lchk = lane >> 4;

    float acc[2][8][4];
    #pragma unroll
    for (int i = 0; i < 2; i++)
        #pragma unroll
        for (int j = 0; j < 8; j++)
            #pragma unroll
            for (int c = 0; c < 4; c++) acc[i][j][c] = 0.f;

    gemm_mainloop(dbase, Ag, Bg, t, wm, wn, lrow, lchk, acc);

    if (z == 2) {
        #pragma unroll
        for (int mt = 0; mt < 2; mt++) {
            #pragma unroll
            for (int nt8 = 0; nt8 < 8; nt8++) {
                int row = m0 + wm + mt * 16 + g;
                int col = n0 + wn + nt8 * 8 + t4 * 2;
                *(float2*)&g_v[(size_t)row * 1024 + col] =
                    make_float2(acc[mt][nt8][0], acc[mt][nt8][1]);
                *(float2*)&g_v[(size_t)(row + 8) * 1024 + col] =
                    make_float2(acc[mt][nt8][2], acc[mt][nt8][3]);
            }
        }
    } else if (z == 0) {
        const int h = (n0 + wn) >> 6;
        #pragma unroll
        for (int mt = 0; mt < 2; mt++) {
            int r = m0 + wm + mt * 16 + g;
            int b = r >> 10, tt = r & 1023;
            size_t rq0 = ((((size_t)b << 4) + h) << 10) + tt;
            #pragma unroll
            for (int nt8 = 0; nt8 < 8; nt8++) {
                int a = nt8 * 8 + t4 * 2;
                __half h0,l0,h1,l1,h2,l2,h3,l3;
                split2h(acc[mt][nt8][0], h0, l0);
                split2h(acc[mt][nt8][1], h1, l1);
                split2h(acc[mt][nt8][2], h2, l2);
                split2h(acc[mt][nt8][3], h3, l3);
                __half2 H0; H0.x=h0; H0.y=h1;
                __half2 L0; L0.x=l0; L0.y=l1;
                __half2 H1; H1.x=h2; H1.y=h3;
                __half2 L1; L1.x=l2; L1.y=l3;
                *(__half2*)&g_qs[rq0 * 128 + a]            = H0;
                *(__half2*)&g_qs[rq0 * 128 + 64 + a]       = L0;
                *(__half2*)&g_qs[(rq0 + 8) * 128 + a]      = H1;
                *(__half2*)&g_qs[(rq0 + 8) * 128 + 64 + a] = L1;
            }
        }
    } else {
        const int h = (n0 + wn) >> 6;
        #pragma unroll
        for (int mt = 0; mt < 2; mt++) {
            int r = m0 + wm + mt * 16 + g;
            int b = r >> 10, tt = r & 1023;
            size_t rk0 = ((((size_t)b << 4) + h) << 10) + tt;
            float s0 = 0.f, s1 = 0.f;
            #pragma unroll
            for (int nt8 = 0; nt8 < 8; nt8++) {
                int a = nt8 * 8 + t4 * 2;
                __half2 H0; H0.x = __float2half_rn(acc[mt][nt8][0]);
                            H0.y = __float2half_rn(acc[mt][nt8][1]);
                __half2 H1; H1.x = __float2half_rn(acc[mt][nt8][2]);
                            H1.y = __float2half_rn(acc[mt][nt8][3]);
                *(__half2*)&g_kb[rk0 * 64 + a]       = H0;
                *(__half2*)&g_kb[(rk0 + 8) * 64 + a] = H1;
                s0 += acc[mt][nt8][0] + acc[mt][nt8][1];
                s1 += acc[mt][nt8][2] + acc[mt][nt8][3];
            }
            s0 += __shfl_xor_sync(0xffffffffu, s0, 1);
            s0 += __shfl_xor_sync(0xffffffffu, s0, 2);
            s1 += __shfl_xor_sync(0xffffffffu, s1, 1);
            s1 += __shfl_xor_sync(0xffffffffu, s1, 2);
            if (t4 == 0) {
                g_ksumT[rk0]     = s0;
                g_ksumT[rk0 + 8] = s1;
            }
        }
    }
}

// output projection: C = (Ah+Al)·Wo^T, fp32 out
__global__ __launch_bounds__(256, 2) void gemm_out(float* __restrict__ C) {
    extern __shared__ char gsm[];
    const uint32_t dbase = (uint32_t)__cvta_generic_to_shared(gsm);
    const int t = threadIdx.x;
    const int m0 = blockIdx.y * 128, n0 = blockIdx.x * 128;
    const __half* Ag = g_sa + (size_t)m0 * 2048;
    const __half* Bg = g_wo + (size_t)n0 * 1024;

    const int w = t >> 5, lane = t & 31;
    const int wm = (w & 3) * 32, wn = (w >> 2) * 64;
    const int g  = lane >> 2, t4 = lane & 3;
    const int lrow = lane & 15;
    const int lchk = lane >> 4;

    float acc[2][8][4];
    #pragma unroll
    for (int i = 0; i < 2; i++)
        #pragma unroll
        for (int j = 0; j < 8; j++)
            #pragma unroll
            for (int c = 0; c < 4; c++) acc[i][j][c] = 0.f;

    gemm_mainloop(dbase, Ag, Bg, t, wm, wn, lrow, lchk, acc);

    #pragma unroll
    for (int mt = 0; mt < 2; mt++) {
        #pragma unroll
        for (int nt8 = 0; nt8 < 8; nt8++) {
            int row = m0 + wm + mt * 16 + g;
            int col = n0 + wn + nt8 * 8 + t4 * 2;
            *(float2*)&C[(size_t)row * 1024 + col] =
                make_float2(acc[mt][nt8][0], acc[mt][nt8][1]);
            *(float2*)&C[(size_t)(row + 8) * 1024 + col] =
                make_float2(acc[mt][nt8][2], acc[mt][nt8][3]);
        }
    }
}

// ---------------- conversions ------------------------------------------------
// f32 [M][1024] -> fp16 [M][2048] as [hi|lo]
__global__ void conv_a(const float4* __restrict__ in, __half* __restrict__ out) {
    size_t idx = (size_t)blockIdx.x * 256 + threadIdx.x;
    float4 v = in[idx];
    size_t m = idx >> 8;
    int k4 = (int)(idx & 255) * 4;
    __half h0,h1,h2,h3,l0,l1,l2,l3;
    split2h(v.x,h0,l0); split2h(v.y,h1,l1); split2h(v.z,h2,l2); split2h(v.w,h3,l3);
    __half2 hp0, hp1, lp0, lp1;
    hp0.x=h0; hp0.y=h1; hp1.x=h2; hp1.y=h3;
    lp0.x=l0; lp0.y=l1; lp1.x=l2; lp1.y=l3;
    __half* o = out + m * 2048 + k4;
    ((__half2*)o)[0] = hp0;          ((__half2*)o)[1] = hp1;
    ((__half2*)(o + 1024))[0] = lp0; ((__half2*)(o + 1024))[1] = lp1;
}

// f32 [K=1024][N] -> fp16 [N][1024] transposed, hi only
__global__ void conv_bT(const float* __restrict__ in, __half* __restrict__ out,
                        int N) {
    __shared__ float tile[32][33];
    int k0 = blockIdx.y * 32, n0 = blockIdx.x * 32;
    int tx = threadIdx.x & 31, ty = threadIdx.x >> 5;
    #pragma unroll
    for (int i = 0; i < 4; i++)
        tile[ty + 8*i][tx] = in[(size_t)(k0 + ty + 8*i) * N + n0 + tx];
    __syncthreads();
    #pragma unroll
    for (int i = 0; i < 4; i++) {
        int n = n0 + ty + 8*i, k = k0 + tx;
        out[(size_t)n * 1024 + k] = __float2half_rn(tile[tx][ty + 8*i]);
    }
}

// g_v [b,k,h,a] -> g_vhi/g_vlo [(b,h), a, k]
__global__ void conv_vT() {
    __shared__ float tile[32][33];
    int bh = blockIdx.z, b = bh >> 4, h = bh & 15;
    int k0 = blockIdx.x * 32, a0 = blockIdx.y * 32;
    int tx = threadIdx.x & 31, ty = threadIdx.x >> 5;
    #pragma unroll
    for (int i = 0; i < 4; i++)
        tile[ty + 8*i][tx] =
            g_v[((((size_t)b << 10) + k0 + ty + 8*i) * 16 + h) * 64 + a0 + tx];
    __syncthreads();
    #pragma unroll
    for (int i = 0; i < 4; i++) {
        int a = a0 + ty + 8*i, k = k0 + tx;
        __half hi, lo; split2h(tile[tx][ty + 8*i], hi, lo);
        size_t o = ((size_t)bh * 64 + a) * 1024 + k;
        g_vhi[o] = hi;
        g_vlo[o] = lo;
    }
}

// masks f32 [b,q,k] -> bit-packed uint64 [(b,q)][k/64]
__global__ void mask_pack(const float* __restrict__ masks) {
    int idx = blockIdx.x * 256 + threadIdx.x;       // 0..B*T*16-1
    const float4* p = (const float4*)masks + (size_t)idx * 16;
    uint64_t bits = 0;
    #pragma unroll
    for (int i = 0; i < 16; i++) {
        float4 v = p[i];
        bits |= (uint64_t)(v.x != 0.f) << (i*4 + 0);
        bits |= (uint64_t)(v.y != 0.f) << (i*4 + 1);
        bits |= (uint64_t)(v.z != 0.f) << (i*4 + 2);
        bits |= (uint64_t)(v.w != 0.f) << (i*4 + 3);
    }
    g_mpack[idx] = bits;
}

// proj[e] = bias_embs[e,:]·bias_scalar  +  int64 dtype detect (one block, 256 thr)
__global__ void proj_detect_kernel(const float* __restrict__ embs,
                                   const float* __restrict__ sc,
                                   const void* __restrict__ ab, int E) {
    __shared__ int bad;
    int t = threadIdx.x;
    if (t == 0) bad = 0;
    __syncthreads();
    if (t < 32) {
        float s = 0.f;
        #pragma unroll
        for (int a = 0; a < 64; a++) s += embs[t*64 + a] * sc[a];
        g_proj[t] = s;
    }
    int n = E < 256 ? E : 256;
    if (t < n) {
        const long long* p = (const long long*)ab + (size_t)t * 4;
        long long et = p[0], bi = p[1], qi = p[2], ki = p[3];
        if (et < 0 || et >= 32 || bi < 0 || bi >= B_ ||
            qi < 0 || qi >= T_ || ki < 0 || ki >= T_) atomicExch(&bad, 1);
    }
    __syncthreads();
    if (t == 0) g_is64 = !bad;
}

// zero g_bs (fp16, 1M int4) + g_lastE (-1, 2M int4); 2M threads
__global__ void init_bs_kernel() {
    int i = blockIdx.x * blockDim.x + threadIdx.x;          // 0..2M-1
    ((int4*)g_lastE)[i] = make_int4(-1, -1, -1, -1);
    if (i < (B_*T_*T_/8))
        ((int4*)g_bs)[i] = make_int4(0, 0, 0, 0);
}

__device__ __forceinline__ void load_edge(const void* ab, int e,
                                          int& et, int& bi, int& qi, int& ki) {
    if (g_is64) {
        const long long* r = (const long long*)ab + (size_t)e * 4;
        et = (int)r[0]; bi = (int)r[1]; qi = (int)r[2]; ki = (int)r[3];
    } else {
        const int* r = (const int*)ab + (size_t)e * 4;
        et = r[0]; bi = r[1]; qi = r[2]; ki = r[3];
    }
}

__global__ void scatter_max_kernel(const void* __restrict__ ab, int E) {
    int e = blockIdx.x * blockDim.x + threadIdx.x;
    if (e >= E) return;
    int et, bi, qi, ki; load_edge(ab, e, et, bi, qi, ki);
    atomicMax(&g_lastE[((size_t)bi*T_ + qi)*T_ + ki], e);
}

__global__ void scatter_write_kernel(const void* __restrict__ ab, int E) {
    int e = blockIdx.x * blockDim.x + threadIdx.x;
    if (e >= E) return;
    int et, bi, qi, ki; load_edge(ab, e, et, bi, qi, ki);
    size_t idx = ((size_t)bi*T_ + qi)*T_ + ki;
    if (g_lastE[idx] == e) g_bs[idx] = __float2half_rn(g_proj[et]);
}

// ---------------- flash attention: fused score+softmax+context ---------------
// Q [hi|lo] 128-wide; K hi-only 64-wide; V hi/lo planes.
// Q tile 128x136 pitch; stage = { K 64x72, Vh 64x72, Vl 64x72 }.
#define FL_QBYTES 34816
#define FL_STAGE  27648
#define FL_VHOFF  9216
#define FL_VLOFF  18432
#define FL_SMEM   (FL_QBYTES + 2*FL_STAGE)

__device__ __forceinline__ void cpa16(void* smem, const void* gmem) {
    uint32_t d = (uint32_t)__cvta_generic_to_shared(smem);
    asm volatile("cp.async.cg.shared.global [%0], [%1], 16;\n" :: "r"(d), "l"(gmem));
}

__device__ __forceinline__ void flash_load_kv(char* smem_raw, int t, int bh, int kt,
                                              int stage) {
    char* base = smem_raw + FL_QBYTES + stage * FL_STAGE;
    __half* Ks = (__half*)base;
    __half* Vh = (__half*)(base + FL_VHOFF);
    __half* Vl = (__half*)(base + FL_VLOFF);
    const __half* ksrc = g_kb + ((size_t)(bh << 10) + kt) * 64;
    #pragma unroll
    for (int i = 0; i < 2; i++) {
        int u = t + i * 256;
        int row = u >> 3, c = u & 7;
        cpa16(&Ks[row * 72 + c * 8], &ksrc[(size_t)row * 64 + c * 8]);
    }
    const __half* vh = g_vhi + (size_t)bh * 64 * 1024 + kt;
    const __half* vl = g_vlo + (size_t)bh * 64 * 1024 + kt;
    #pragma unroll
    for (int i = 0; i < 2; i++) {
        int u = t + i * 256;
        int row = u >> 3, c = u & 7;
        cpa16(&Vh[row * 72 + c * 8], &vh[(size_t)row * 1024 + c * 8]);
        cpa16(&Vl[row * 72 + c * 8], &vl[(size_t)row * 1024 + c * 8]);
    }
    asm volatile("cp.async.commit_group;\n");
}

__global__ __launch_bounds__(256, 2) void flash_kernel() {
    extern __shared__ char smem_raw[];
    __half* Qs = (__half*)smem_raw;             // [128][136]
    const int t = threadIdx.x;
    const int w = t >> 5, lane = t & 31;
    const int g = lane >> 2, t4 = lane & 3;
    const int bh = blockIdx.y, b = bh >> 4, h = bh & 15;
    const int q0 = blockIdx.x * 128;

    {
        const __half* src = g_qs + ((size_t)(bh << 10) + q0) * 128;
        #pragma unroll
        for (int i = 0; i < 8; i++) {
            int u = t + i * 256;
            int row = u >> 4, c = u & 15;
            *(uint4*)&Qs[row * 136 + c * 8] = *(const uint4*)&src[(size_t)row * 128 + c * 8];
        }
    }
    flash_load_kv(smem_raw, t, bh, 0, 0);
    flash_load_kv(smem_raw, t, bh, 64, 1);
    __syncthreads();

    uint32_t qf[8][4];
    #pragma unroll
    for (int kc = 0; kc < 8; kc++) {
        const __half* p = &Qs[(w * 16 + g) * 136 + kc * 16 + t4 * 2];
        qf[kc][0] = *(const uint32_t*)(p);
        qf[kc][1] = *(const uint32_t*)(p + 8 * 136);
        qf[kc][2] = *(const uint32_t*)(p + 8);
        qf[kc][3] = *(const uint32_t*)(p + 8 * 136 + 8);
    }

    const int r0 = q0 + w * 16 + g;
    float m0 = -1e38f, m1 = -1e38f, l0 = 0.f, l1 = 0.f;
    float oacc[8][4];
    #pragma unroll
    for (int nt = 0; nt < 8; nt++)
        #pragma unroll
        for (int c = 0; c < 4; c++) oacc[nt][c] = 0.f;

    const float C1 = 0.125f * 1.44269504f;

    for (int it = 0; it < 16; it++) {
        if (it < 15) asm volatile("cp.async.wait_group 1;\n");
        else         asm volatile("cp.async.wait_group 0;\n");
        __syncthreads();
        const int stage = it & 1;
        char* base = smem_raw + FL_QBYTES + stage * FL_STAGE;
        const __half* Ks = (const __half*)base;
        const __half* Vh = (const __half*)(base + FL_VHOFF);
        const __half* Vl = (const __half*)(base + FL_VLOFF);
        const int kt = it * 64;

        float sacc[8][4];
        #pragma unroll
        for (int nt = 0; nt < 8; nt++)
            #pragma unroll
            for (int c = 0; c < 4; c++) sacc[nt][c] = 0.f;
        #pragma unroll
        for (int nt = 0; nt < 8; nt++) {
            const __half* pr = &Ks[(nt * 8 + g) * 72 + t4 * 2];
            #pragma unroll
            for (int kc = 0; kc < 4; kc++) {
                uint32_t h0 = *(const uint32_t*)(pr + kc * 16);
                uint32_t h1 = *(const uint32_t*)(pr + kc * 16 + 8);
                mma16816(sacc[nt], qf[kc], h0, h1);         // Qh·Kh
                mma16816(sacc[nt], qf[4 + kc], h0, h1);     // Ql·Kh
            }
        }

        uint64_t w0 = g_mpack[(((size_t)b << 10) + r0) * 16 + it];
        uint64_t w1 = g_mpack[(((size_t)b << 10) + r0 + 8) * 16 + it];
        float mt0 = -1e38f, mt1 = -1e38f;
        #pragma unroll
        for (int nt = 0; nt < 8; nt++) {
            int c0 = kt + nt * 8 + t4 * 2;
            int sh = nt * 8 + t4 * 2;
            float2 ks2 = *(const float2*)&g_ksumT[((size_t)bh << 10) + c0];
            size_t mb0 = ((((size_t)b << 10) + r0) << 10) + c0;
            size_t mb1 = ((((size_t)b << 10) + r0 + 8) << 10) + c0;
            float2 bs0 = __half22float2(*(const __half2*)&g_bs[mb0]);
            float2 bs1 = __half22float2(*(const __half2*)&g_bs[mb1]);
            float s0 = (sacc[nt][0] + bs0.x * ks2.x) * C1;
            float s1 = (sacc[nt][1] + bs0.y * ks2.y) * C1;
            float s2 = (sacc[nt][2] + bs1.x * ks2.x) * C1;
            float s3 = (sacc[nt][3] + bs1.y * ks2.y) * C1;
            sacc[nt][0] = ((w0 >> sh) & 1)       ? -1e37f : s0;
            sacc[nt][1] = ((w0 >> (sh + 1)) & 1) ? -1e37f : s1;
            sacc[nt][2] = ((w1 >> sh) & 1)       ? -1e37f : s2;
            sacc[nt][3] = ((w1 >> (sh + 1)) & 1) ? -1e37f : s3;
            mt0 = fmaxf(mt0, fmaxf(sacc[nt][0], sacc[nt][1]));
            mt1 = fmaxf(mt1, fmaxf(sacc[nt][2], sacc[nt][3]));
        }
        mt0 = fmaxf(mt0, __shfl_xor_sync(0xffffffffu, mt0, 1));
        mt0 = fmaxf(mt0, __shfl_xor_sync(0xffffffffu, mt0, 2));
        mt1 = fmaxf(mt1, __shfl_xor_sync(0xffffffffu, mt1, 1));
        mt1 = fmaxf(mt1, __shfl_xor_sync(0xffffffffu, mt1, 2));
        float mn0 = fmaxf(m0, mt0), mn1 = fmaxf(m1, mt1);
        float sc0 = ex2f(m0 - mn0), sc1 = ex2f(m1 - mn1);
        m0 = mn0; m1 = mn1;
        l0 *= sc0; l1 *= sc1;

        uint32_t phi0[8], phi1[8];
        #pragma unroll
        for (int nt = 0; nt < 8; nt++) {
            float p0 = ex2f(sacc[nt][0] - m0), p1 = ex2f(sacc[nt][1] - m0);
            float p2 = ex2f(sacc[nt][2] - m1), p3 = ex2f(sacc[nt][3] - m1);
            l0 += p0 + p1; l1 += p2 + p3;
            __half2 h0 = __float22half2_rn(make_float2(p0, p1));
            __half2 h1 = __float22half2_rn(make_float2(p2, p3));
            phi0[nt] = *(uint32_t*)&h0;
            phi1[nt] = *(uint32_t*)&h1;
            oacc[nt][0] *= sc0; oacc[nt][1] *= sc0;
            oacc[nt][2] *= sc1; oacc[nt][3] *= sc1;
        }

        #pragma unroll
        for (int kc = 0; kc < 4; kc++) {
            uint32_t ah[4] = {phi0[2*kc], phi1[2*kc], phi0[2*kc+1], phi1[2*kc+1]};
            #pragma unroll
            for (int nt = 0; nt < 8; nt++) {
                const __half* ph = &Vh[(nt * 8 + g) * 72 + kc * 16 + t4 * 2];
                const __half* pl = &Vl[(nt * 8 + g) * 72 + kc * 16 + t4 * 2];
                uint32_t bh0 = *(const uint32_t*)(ph);
                uint32_t bh1 = *(const uint32_t*)(ph + 8);
                uint32_t bl0 = *(const uint32_t*)(pl);
                uint32_t bl1 = *(const uint32_t*)(pl + 8);
                mma16816(oacc[nt], ah, bh0, bh1);
                mma16816(oacc[nt], ah, bl0, bl1);
            }
        }
        __syncthreads();
        if (it + 2 < 16) flash_load_kv(smem_raw, t, bh, (it + 2) * 64, stage);
    }

    l0 += __shfl_xor_sync(0xffffffffu, l0, 1);
    l0 += __shfl_xor_sync(0xffffffffu, l0, 2);
    l1 += __shfl_xor_sync(0xffffffffu, l1, 1);
    l1 += __shfl_xor_sync(0xffffffffu, l1, 2);
    float inv0 = 1.0f / l0, inv1 = 1.0f / l1;
    size_t rowA0 = ((size_t)b << 10) + r0;
    size_t rowA1 = rowA0 + 8;
    #pragma unroll
    for (int nt = 0; nt < 8; nt++) {
        int col = (h << 6) + nt * 8 + t4 * 2;
        float o0 = oacc[nt][0] * inv0, o1 = oacc[nt][1] * inv0;
        float o2 = oacc[nt][2] * inv1, o3 = oacc[nt][3] * inv1;
        __half h0a, l0a, h1a, l1a, h2a, l2a, h3a, l3a;
        split2h(o0, h0a, l0a); split2h(o1, h1a, l1a);
        split2h(o2, h2a, l2a); split2h(o3, h3a, l3a);
        __half2 H0; H0.x=h0a; H0.y=h1a;
        __half2 L0; L0.x=l0a; L0.y=l1a;
        __half2 H1; H1.x=h2a; H1.y=h3a;
        __half2 L1; L1.x=l2a; L1.y=l3a;
        __half* d0 = g_sa + rowA0 * 2048 + col;
        __half* d1 = g_sa + rowA1 * 2048 + col;
        *(__half2*)(d0)        = H0;
        *(__half2*)(d0 + 1024) = L0;
        *(__half2*)(d1)        = H1;
        *(__half2*)(d1 + 1024) = L1;
    }
}

// ---------------- launch ----------------------------------------------------
extern "C" void kernel_launch(void* const* d_in, const int* in_sizes, int n_in,
                              void* d_out, int out_size) {
    const float* states      = (const float*)d_in[0];
    const float* keys        = (const float*)d_in[1];
    const float* masks       = (const float*)d_in[2];
    const void*  abias       = (const void*) d_in[3];
    const float* Wq          = (const float*)d_in[4];
    const float* Wk          = (const float*)d_in[5];
    const float* Wv          = (const float*)d_in[6];
    const float* Wout        = (const float*)d_in[7];
    const float* bias_embs   = (const float*)d_in[8];
    const float* bias_scalar = (const float*)d_in[9];
    float* out = (float*)d_out;
    int E = in_sizes[3] / 4;

    cudaFuncSetAttribute(flash_kernel,
                         cudaFuncAttributeMaxDynamicSharedMemorySize, FL_SMEM);
    cudaFuncSetAttribute(proj_gemm,
                         cudaFuncAttributeMaxDynamicSharedMemorySize, GSMEM);
    cudaFuncSetAttribute(gemm_out,
                         cudaFuncAttributeMaxDynamicSharedMemorySize, GSMEM);

    __half *psa, *pka, *pwq, *pwk, *pwv, *pwo;
    cudaGetSymbolAddress((void**)&psa, g_sa);
    cudaGetSymbolAddress((void**)&pka, g_ka);
    cudaGetSymbolAddress((void**)&pwq, g_wq);
    cudaGetSymbolAddress((void**)&pwk, g_wk);
    cudaGetSymbolAddress((void**)&pwv, g_wv);
    cudaGetSymbolAddress((void**)&pwo, g_wo);

    // conversions
    conv_a<<<8192, 256>>>((const float4*)states, psa);
    conv_a<<<8192, 256>>>((const float4*)keys,   pka);
    dim3 gt(32, 32);
    conv_bT<<<gt, 256>>>(Wq,   pwq, 1024);
    conv_bT<<<gt, 256>>>(Wk,   pwk, 1024);
    conv_bT<<<gt, 256>>>(Wv,   pwv, 1024);
    conv_bT<<<gt, 256>>>(Wout, pwo, 1024);
    mask_pack<<<512, 256>>>(masks);

    // fused Q/K/V projections (epilogues write flash layouts + ksum directly)
    dim3 gp(8, 64, 3);
    proj_gemm<<<gp, 256, GSMEM>>>();

    // side computations
    proj_detect_kernel<<<1, 256>>>(bias_embs, bias_scalar, abias, E);
    init_bs_kernel<<<8192, 256>>>();
    scatter_max_kernel<<<(E + 255)/256, 256>>>(abias, E);
    scatter_write_kernel<<<(E + 255)/256, 256>>>(abias, E);

    // V transpose for flash
    dim3 gv(32, 2, 128);
    conv_vT<<<gv, 256>>>();

    // fused attention (writes ctx split-fp16 into g_sa)
    dim3 gf(T_/128, B_*H_);
    flash_kernel<<<gf, 256, FL_SMEM>>>();

    // output projection
    dim3 gg(8, 64);
    gemm_out<<<gg, 256, GSMEM>>>(out);
}

// round 16
// speedup vs baseline: 6.3792x; 1.0266x over previous
#include <cuda_runtime.h>
#include <cuda_fp16.h>
#include <cstdint>

#define B_ 8
#define T_ 1024
#define D_ 1024
#define H_ 16
#define A_ 64

// ---------------- scratch (device globals: allocation-free) ----------------
__device__ float g_ksumT[B_*H_*T_];         // [(b,h),t]
__device__ __half g_bs[B_*T_*T_];           // [b,q,k] fp16
__device__ int   g_lastE[B_*T_*T_];
__device__ float g_proj[32];
__device__ int   g_is64;
__device__ uint64_t g_mpack[B_*T_*16];      // mask bits: [(b,q)][k/64]

// split-fp16 operands
__device__ __align__(16) __half g_sa[8192*2048];        // A-side [hi|lo]: states, later ctx
__device__ __align__(16) __half g_ka[8192*2048];        // keys [hi|lo]
__device__ __align__(16) __half g_wq[1024*1024];        // weights hi-only, [N][K]
__device__ __align__(16) __half g_wk[1024*1024];
__device__ __align__(16) __half g_wv[1024*1024];
__device__ __align__(16) __half g_wo[1024*1024];
__device__ __align__(16) __half g_qs[B_*H_*T_*128];     // Q [hi|lo], rows (b,h,t)
__device__ __align__(16) __half g_kb[B_*H_*T_*64];      // K hi-only, rows (b,h,t)
__device__ __align__(16) __half g_vhi[B_*H_*A_*T_];     // [(b,h),a,k]
__device__ __align__(16) __half g_vlo[B_*H_*A_*T_];

// ---------------- mma.sync m16n8k16 fp16 ------------------------------------
__device__ __forceinline__ void mma16816(float* d, const uint32_t* a,
                                         uint32_t b0, uint32_t b1) {
    asm volatile(
        "mma.sync.aligned.m16n8k16.row.col.f32.f16.f16.f32 "
        "{%0,%1,%2,%3}, {%4,%5,%6,%7}, {%8,%9}, {%0,%1,%2,%3};\n"
        : "+f"(d[0]), "+f"(d[1]), "+f"(d[2]), "+f"(d[3])
        : "r"(a[0]), "r"(a[1]), "r"(a[2]), "r"(a[3]), "r"(b0), "r"(b1));
}

__device__ __forceinline__ void ldsm_x4(uint32_t& r0, uint32_t& r1,
                                        uint32_t& r2, uint32_t& r3, uint32_t addr) {
    asm volatile("ldmatrix.sync.aligned.m8n8.x4.shared.b16 {%0,%1,%2,%3}, [%4];"
                 : "=r"(r0), "=r"(r1), "=r"(r2), "=r"(r3) : "r"(addr));
}

__device__ __forceinline__ float ex2f(float x) {
    float r;
    asm("ex2.approx.f32 %0, %1;" : "=f"(r) : "f"(x));
    return r;
}

__device__ __forceinline__ void cpa16s(uint32_t smem, const void* gmem) {
    asm volatile("cp.async.cg.shared.global [%0], [%1], 16;\n"
                 :: "r"(smem), "l"(gmem));
}

__device__ __forceinline__ void split2h(float v, __half& hi, __half& lo) {
    hi = __float2half_rn(v);
    lo = __float2half_rn(v - __half2float(hi));
}

// ---------------- 2-term split NT GEMM core ---------------------------------
// A [M][2048] fp16 [hi|lo]; B [N][1024] fp16 hi-only. Logical K=1024, BK=32.
// 128x128 tile, 256 threads (8 warps: 4m x 2n), 4-stage cp.async.
#define GNS 4
#define GSB 24576
#define GSMEM (GNS*GSB)

__device__ __forceinline__ void g_ld_stage(uint32_t sb, const __half* Ag,
                                           const __half* Bg, int k0, int t) {
    #pragma unroll
    for (int i = 0; i < 2; i++) {
        int j = t + (i << 8);              // 0..511
        int row = j >> 2, c = j & 3;
        uint32_t sw = (uint32_t)((c ^ ((row >> 1) & 3)) << 4);
        const __half* ga = Ag + (size_t)row * 2048 + k0 + c * 8;
        cpa16s(sb + row * 64 + sw,           ga);                              // Ah
        cpa16s(sb + 8192  + row * 64 + sw,   ga + 1024);                       // Al
        cpa16s(sb + 16384 + row * 64 + sw,   Bg + (size_t)row * 1024 + k0 + c * 8); // Bh
    }
}

__device__ __forceinline__ void gemm_mainloop(
    uint32_t dbase, const __half* Ag, const __half* Bg, int t,
    int wm, int wn, int lrow, int lchk, float acc[2][8][4])
{
    const int nIt = 32;
    #pragma unroll
    for (int s = 0; s < GNS - 1; s++) {
        g_ld_stage(dbase + s * GSB, Ag, Bg, s << 5, t);
        asm volatile("cp.async.commit_group;\n");
    }
    int st = 0, pst = GNS - 1;
    for (int i = 0; i < nIt; i++) {
        asm volatile("cp.async.wait_group %0;\n" :: "n"(GNS - 2));
        __syncthreads();
        if (i + GNS - 1 < nIt)
            g_ld_stage(dbase + pst * GSB, Ag, Bg, (i + 3) << 5, t);
        asm volatile("cp.async.commit_group;\n");

        const uint32_t sA = dbase + st * GSB;
        #pragma unroll
        for (int k16 = 0; k16 < 2; k16++) {
            const int chk = k16 * 2 + lchk;
            uint32_t afh[2][4], afl[2][4];
            #pragma unroll
            for (int mt = 0; mt < 2; mt++) {
                int row = wm + mt * 16 + lrow;
                uint32_t off = row * 64 + ((chk ^ ((row >> 1) & 3)) << 4);
                ldsm_x4(afh[mt][0], afh[mt][1], afh[mt][2], afh[mt][3], sA + off);
                ldsm_x4(afl[mt][0], afl[mt][1], afl[mt][2], afl[mt][3],
                        sA + 8192 + off);
            }
            #pragma unroll
            for (int nq = 0; nq < 4; nq++) {
                int row = wn + nq * 16 + lrow;
                uint32_t off = row * 64 + ((chk ^ ((row >> 1) & 3)) << 4);
                uint32_t h0, h1, h2, h3;
                ldsm_x4(h0, h1, h2, h3, sA + 16384 + off);
                mma16816(acc[0][nq*2+0], afh[0], h0, h2);
                mma16816(acc[0][nq*2+1], afh[0], h1, h3);
                mma16816(acc[1][nq*2+0], afh[1], h0, h2);
                mma16816(acc[1][nq*2+1], afh[1], h1, h3);
                mma16816(acc[0][nq*2+0], afl[0], h0, h2);
                mma16816(acc[0][nq*2+1], afl[0], h1, h3);
                mma16816(acc[1][nq*2+0], afl[1], h0, h2);
                mma16816(acc[1][nq*2+1], afl[1], h1, h3);
            }
        }
        st = (st + 1 == GNS) ? 0 : st + 1;
        pst = (pst + 1 == GNS) ? 0 : pst + 1;
    }
}

// fused Q/K/V projection GEMM; blockIdx.z: 0=Q, 1=K, 2=V
__global__ __launch_bounds__(256, 2) void proj_gemm() {
    extern __shared__ char gsm[];
    const uint32_t dbase = (uint32_t)__cvta_generic_to_shared(gsm);
    const int t = threadIdx.x;
    const int z = blockIdx.z;
    const int m0 = blockIdx.y * 128, n0 = blockIdx.x * 128;

    const __half* Ag = (z == 0) ? g_sa : g_ka;
    const __half* Bg = (z == 0) ? g_wq : (z == 1) ? g_wk : g_wv;
    Ag += (size_t)m0 * 2048;
    Bg += (size_t)n0 * 1024;

    const int w = t >> 5, lane = t & 31;
    const int wm = (w & 3) * 32, wn = (w >> 2) * 64;
    const int g  = lane >> 2, t4 = lane & 3;
    const int lrow = lane & 15;
    const int lchk = lane >> 4;

    float acc[2][8][4];
    #pragma unroll
    for (int i = 0; i < 2; i++)
        #pragma unroll
        for (int j = 0; j < 8; j++)
            #pragma unroll
            for (int c = 0; c < 4; c++) acc[i][j][c] = 0.f;

    gemm_mainloop(dbase, Ag, Bg, t, wm, wn, lrow, lchk, acc);

    if (z == 2) {
        // V: transpose-split in smem, write g_vhi/g_vlo [(b,h),a,k] coalesced.
        __syncthreads();                       // all warps done reading stages
        __half* smh = (__half*)gsm;            // [128 a][136 k] hi
        __half* sml = smh + 128 * 136;         // lo
        #pragma unroll
        for (int mt = 0; mt < 2; mt++) {
            int kl = wm + mt * 16 + g;         // local k (token) row
            #pragma unroll
            for (int nt8 = 0; nt8 < 8; nt8++) {
                int al = wn + nt8 * 8 + t4 * 2;  // local a col
                __half h0,l0,h1,l1,h2,l2,h3,l3;
                split2h(acc[mt][nt8][0], h0, l0);
                split2h(acc[mt][nt8][1], h1, l1);
                split2h(acc[mt][nt8][2], h2, l2);
                split2h(acc[mt][nt8][3], h3, l3);
                smh[al * 136 + kl]           = h0;
                smh[(al + 1) * 136 + kl]     = h1;
                smh[al * 136 + kl + 8]       = h2;
                smh[(al + 1) * 136 + kl + 8] = h3;
                sml[al * 136 + kl]           = l0;
                sml[(al + 1) * 136 + kl]     = l1;
                sml[al * 136 + kl + 8]       = l2;
                sml[(al + 1) * 136 + kl + 8] = l3;
            }
        }
        __syncthreads();
        // coalesced writeout: thread t -> a-row t>>1, k-segment (t&1)*64
        int al = t >> 1, seg = (t & 1) * 64;
        int h = (n0 + al) >> 6, ain = (n0 + al) & 63;
        int b = m0 >> 10, tt0 = m0 & 1023;
        size_t dst = ((((size_t)b * 16 + h) * 64 + ain) << 10) + tt0 + seg;
        #pragma unroll
        for (int i = 0; i < 8; i++) {
            *(uint4*)&g_vhi[dst + i * 8] = *(uint4*)&smh[al * 136 + seg + i * 8];
            *(uint4*)&g_vlo[dst + i * 8] = *(uint4*)&sml[al * 136 + seg + i * 8];
        }
    } else if (z == 0) {
        const int h = (n0 + wn) >> 6;
        #pragma unroll
        for (int mt = 0; mt < 2; mt++) {
            int r = m0 + wm + mt * 16 + g;
            int b = r >> 10, tt = r & 1023;
            size_t rq0 = ((((size_t)b << 4) + h) << 10) + tt;
            #pragma unroll
            for (int nt8 = 0; nt8 < 8; nt8++) {
                int a = nt8 * 8 + t4 * 2;
                __half h0,l0,h1,l1,h2,l2,h3,l3;
                split2h(acc[mt][nt8][0], h0, l0);
                split2h(acc[mt][nt8][1], h1, l1);
                split2h(acc[mt][nt8][2], h2, l2);
                split2h(acc[mt][nt8][3], h3, l3);
                __half2 H0; H0.x=h0; H0.y=h1;
                __half2 L0; L0.x=l0; L0.y=l1;
                __half2 H1; H1.x=h2; H1.y=h3;
                __half2 L1; L1.x=l2; L1.y=l3;
                *(__half2*)&g_qs[rq0 * 128 + a]            = H0;
                *(__half2*)&g_qs[rq0 * 128 + 64 + a]       = L0;
                *(__half2*)&g_qs[(rq0 + 8) * 128 + a]      = H1;
                *(__half2*)&g_qs[(rq0 + 8) * 128 + 64 + a] = L1;
            }
        }
    } else {
        const int h = (n0 + wn) >> 6;
        #pragma unroll
        for (int mt = 0; mt < 2; mt++) {
            int r = m0 + wm + mt * 16 + g;
            int b = r >> 10, tt = r & 1023;
            size_t rk0 = ((((size_t)b << 4) + h) << 10) + tt;
            float s0 = 0.f, s1 = 0.f;
            #pragma unroll
            for (int nt8 = 0; nt8 < 8; nt8++) {
                int a = nt8 * 8 + t4 * 2;
                __half2 H0; H0.x = __float2half_rn(acc[mt][nt8][0]);
                            H0.y = __float2half_rn(acc[mt][nt8][1]);
                __half2 H1; H1.x = __float2half_rn(acc[mt][nt8][2]);
                            H1.y = __float2half_rn(acc[mt][nt8][3]);
                *(__half2*)&g_kb[rk0 * 64 + a]       = H0;
                *(__half2*)&g_kb[(rk0 + 8) * 64 + a] = H1;
                s0 += acc[mt][nt8][0] + acc[mt][nt8][1];
                s1 += acc[mt][nt8][2] + acc[mt][nt8][3];
            }
            s0 += __shfl_xor_sync(0xffffffffu, s0, 1);
            s0 += __shfl_xor_sync(0xffffffffu, s0, 2);
            s1 += __shfl_xor_sync(0xffffffffu, s1, 1);
            s1 += __shfl_xor_sync(0xffffffffu, s1, 2);
            if (t4 == 0) {
                g_ksumT[rk0]     = s0;
                g_ksumT[rk0 + 8] = s1;
            }
        }
    }
}

// output projection: C = (Ah+Al)·Wo^T, fp32 out
__global__ __launch_bounds__(256, 2) void gemm_out(float* __restrict__ C) {
    extern __shared__ char gsm[];
    const uint32_t dbase = (uint32_t)__cvta_generic_to_shared(gsm);
    const int t = threadIdx.x;
    const int m0 = blockIdx.y * 128, n0 = blockIdx.x * 128;
    const __half* Ag = g_sa + (size_t)m0 * 2048;
    const __half* Bg = g_wo + (size_t)n0 * 1024;

    const int w = t >> 5, lane = t & 31;
    const int wm = (w & 3) * 32, wn = (w >> 2) * 64;
    const int g  = lane >> 2, t4 = lane & 3;
    const int lrow = lane & 15;
    const int lchk = lane >> 4;

    float acc[2][8][4];
    #pragma unroll
    for (int i = 0; i < 2; i++)
        #pragma unroll
        for (int j = 0; j < 8; j++)
            #pragma unroll
            for (int c = 0; c < 4; c++) acc[i][j][c] = 0.f;

    gemm_mainloop(dbase, Ag, Bg, t, wm, wn, lrow, lchk, acc);

    #pragma unroll
    for (int mt = 0; mt < 2; mt++) {
        #pragma unroll
        for (int nt8 = 0; nt8 < 8; nt8++) {
            int row = m0 + wm + mt * 16 + g;
            int col = n0 + wn + nt8 * 8 + t4 * 2;
            *(float2*)&C[(size_t)row * 1024 + col] =
                make_float2(acc[mt][nt8][0], acc[mt][nt8][1]);
            *(float2*)&C[(size_t)(row + 8) * 1024 + col] =
                make_float2(acc[mt][nt8][2], acc[mt][nt8][3]);
        }
    }
}

// ---------------- conversions ------------------------------------------------
// f32 [M][1024] -> fp16 [M][2048] [hi|lo]; blockIdx.y: 0=states->g_sa, 1=keys->g_ka
__global__ void conv_a2(const float4* __restrict__ s, const float4* __restrict__ k) {
    const float4* in = blockIdx.y ? k : s;
    __half* out = blockIdx.y ? g_ka : g_sa;
    size_t idx = (size_t)blockIdx.x * 256 + threadIdx.x;
    float4 v = in[idx];
    size_t m = idx >> 8;
    int k4 = (int)(idx & 255) * 4;
    __half h0,h1,h2,h3,l0,l1,l2,l3;
    split2h(v.x,h0,l0); split2h(v.y,h1,l1); split2h(v.z,h2,l2); split2h(v.w,h3,l3);
    __half2 hp0, hp1, lp0, lp1;
    hp0.x=h0; hp0.y=h1; hp1.x=h2; hp1.y=h3;
    lp0.x=l0; lp0.y=l1; lp1.x=l2; lp1.y=l3;
    __half* o = out + m * 2048 + k4;
    ((__half2*)o)[0] = hp0;          ((__half2*)o)[1] = hp1;
    ((__half2*)(o + 1024))[0] = lp0; ((__half2*)(o + 1024))[1] = lp1;
}

// all 4 weights: f32 [1024][1024] -> fp16 [N][1024] transposed hi-only; z selects
__global__ void conv_w(const float* __restrict__ Wq, const float* __restrict__ Wk,
                       const float* __restrict__ Wv, const float* __restrict__ Wo) {
    const float* in = (blockIdx.z == 0) ? Wq : (blockIdx.z == 1) ? Wk
                    : (blockIdx.z == 2) ? Wv : Wo;
    __half* out = (blockIdx.z == 0) ? g_wq : (blockIdx.z == 1) ? g_wk
                : (blockIdx.z == 2) ? g_wv : g_wo;
    __shared__ float tile[32][33];
    int k0 = blockIdx.y * 32, n0 = blockIdx.x * 32;
    int tx = threadIdx.x & 31, ty = threadIdx.x >> 5;
    #pragma unroll
    for (int i = 0; i < 4; i++)
        tile[ty + 8*i][tx] = in[(size_t)(k0 + ty + 8*i) * 1024 + n0 + tx];
    __syncthreads();
    #pragma unroll
    for (int i = 0; i < 4; i++) {
        int n = n0 + ty + 8*i, k = k0 + tx;
        out[(size_t)n * 1024 + k] = __float2half_rn(tile[tx][ty + 8*i]);
    }
}

// init g_lastE (-1) + zero g_bs + mask_pack, one launch (grid 8192 x 256)
__global__ void init_all(const float* __restrict__ masks) {
    int i = blockIdx.x * 256 + threadIdx.x;                 // 0..2M-1
    ((int4*)g_lastE)[i] = make_int4(-1, -1, -1, -1);
    if (i < (B_*T_*T_/8))
        ((int4*)g_bs)[i] = make_int4(0, 0, 0, 0);
    if (i < B_*T_*16) {
        const float4* p = (const float4*)masks + (size_t)i * 16;
        uint64_t bits = 0;
        #pragma unroll
        for (int j = 0; j < 16; j++) {
            float4 v = p[j];
            bits |= (uint64_t)(v.x != 0.f) << (j*4 + 0);
            bits |= (uint64_t)(v.y != 0.f) << (j*4 + 1);
            bits |= (uint64_t)(v.z != 0.f) << (j*4 + 2);
            bits |= (uint64_t)(v.w != 0.f) << (j*4 + 3);
        }
        g_mpack[i] = bits;
    }
}

// proj[e] = bias_embs[e,:]·bias_scalar  +  int64 dtype detect
__global__ void proj_detect_kernel(const float* __restrict__ embs,
                                   const float* __restrict__ sc,
                                   const void* __restrict__ ab, int E) {
    __shared__ int bad;
    int t = threadIdx.x;
    if (t == 0) bad = 0;
    __syncthreads();
    if (t < 32) {
        float s = 0.f;
        #pragma unroll
        for (int a = 0; a < 64; a++) s += embs[t*64 + a] * sc[a];
        g_proj[t] = s;
    }
    int n = E < 256 ? E : 256;
    if (t < n) {
        const long long* p = (const long long*)ab + (size_t)t * 4;
        long long et = p[0], bi = p[1], qi = p[2], ki = p[3];
        if (et < 0 || et >= 32 || bi < 0 || bi >= B_ ||
            qi < 0 || qi >= T_ || ki < 0 || ki >= T_) atomicExch(&bad, 1);
    }
    __syncthreads();
    if (t == 0) g_is64 = !bad;
}

__device__ __forceinline__ void load_edge(const void* ab, int e,
                                          int& et, int& bi, int& qi, int& ki) {
    if (g_is64) {
        const long long* r = (const long long*)ab + (size_t)e * 4;
        et = (int)r[0]; bi = (int)r[1]; qi = (int)r[2]; ki = (int)r[3];
    } else {
        const int* r = (const int*)ab + (size_t)e * 4;
        et = r[0]; bi = r[1]; qi = r[2]; ki = r[3];
    }
}

__global__ void scatter_max_kernel(const void* __restrict__ ab, int E) {
    int e = blockIdx.x * blockDim.x + threadIdx.x;
    if (e >= E) return;
    int et, bi, qi, ki; load_edge(ab, e, et, bi, qi, ki);
    atomicMax(&g_lastE[((size_t)bi*T_ + qi)*T_ + ki], e);
}

__global__ void scatter_write_kernel(const void* __restrict__ ab, int E) {
    int e = blockIdx.x * blockDim.x + threadIdx.x;
    if (e >= E) return;
    int et, bi, qi, ki; load_edge(ab, e, et, bi, qi, ki);
    size_t idx = ((size_t)bi*T_ + qi)*T_ + ki;
    if (g_lastE[idx] == e) g_bs[idx] = __float2half_rn(g_proj[et]);
}

// ---------------- flash attention: fused score+softmax+context ---------------
#define FL_QBYTES 34816
#define FL_STAGE  27648
#define FL_VHOFF  9216
#define FL_VLOFF  18432
#define FL_SMEM   (FL_QBYTES + 2*FL_STAGE)

__device__ __forceinline__ void cpa16(void* smem, const void* gmem) {
    uint32_t d = (uint32_t)__cvta_generic_to_shared(smem);
    asm volatile("cp.async.cg.shared.global [%0], [%1], 16;\n" :: "r"(d), "l"(gmem));
}

__device__ __forceinline__ void flash_load_kv(char* smem_raw, int t, int bh, int kt,
                                              int stage) {
    char* base = smem_raw + FL_QBYTES + stage * FL_STAGE;
    __half* Ks = (__half*)base;
    __half* Vh = (__half*)(base + FL_VHOFF);
    __half* Vl = (__half*)(base + FL_VLOFF);
    const __half* ksrc = g_kb + ((size_t)(bh << 10) + kt) * 64;
    #pragma unroll
    for (int i = 0; i < 2; i++) {
        int u = t + i * 256;
        int row = u >> 3, c = u & 7;
        cpa16(&Ks[row * 72 + c * 8], &ksrc[(size_t)row * 64 + c * 8]);
    }
    const __half* vh = g_vhi + (size_t)bh * 64 * 1024 + kt;
    const __half* vl = g_vlo + (size_t)bh * 64 * 1024 + kt;
    #pragma unroll
    for (int i = 0; i < 2; i++) {
        int u = t + i * 256;
        int row = u >> 3, c = u & 7;
        cpa16(&Vh[row * 72 + c * 8], &vh[(size_t)row * 1024 + c * 8]);
        cpa16(&Vl[row * 72 + c * 8], &vl[(size_t)row * 1024 + c * 8]);
    }
    asm volatile("cp.async.commit_group;\n");
}

__global__ __launch_bounds__(256, 2) void flash_kernel() {
    extern __shared__ char smem_raw[];
    __half* Qs = (__half*)smem_raw;             // [128][136]
    const int t = threadIdx.x;
    const int w = t >> 5, lane = t & 31;
    const int g = lane >> 2, t4 = lane & 3;
    const int bh = blockIdx.y, b = bh >> 4, h = bh & 15;
    const int q0 = blockIdx.x * 128;

    {
        const __half* src = g_qs + ((size_t)(bh << 10) + q0) * 128;
        #pragma unroll
        for (int i = 0; i < 8; i++) {
            int u = t + i * 256;
            int row = u >> 4, c = u & 15;
            *(uint4*)&Qs[row * 136 + c * 8] = *(const uint4*)&src[(size_t)row * 128 + c * 8];
        }
    }
    flash_load_kv(smem_raw, t, bh, 0, 0);
    flash_load_kv(smem_raw, t, bh, 64, 1);
    __syncthreads();

    uint32_t qf[8][4];
    #pragma unroll
    for (int kc = 0; kc < 8; kc++) {
        const __half* p = &Qs[(w * 16 + g) * 136 + kc * 16 + t4 * 2];
        qf[kc][0] = *(const uint32_t*)(p);
        qf[kc][1] = *(const uint32_t*)(p + 8 * 136);
        qf[kc][2] = *(const uint32_t*)(p + 8);
        qf[kc][3] = *(const uint32_t*)(p + 8 * 136 + 8);
    }

    const int r0 = q0 + w * 16 + g;
    float m0 = -1e38f, m1 = -1e38f, l0 = 0.f, l1 = 0.f;
    float oacc[8][4];
    #pragma unroll
    for (int nt = 0; nt < 8; nt++)
        #pragma unroll
        for (int c = 0; c < 4; c++) oacc[nt][c] = 0.f;

    const float C1 = 0.125f * 1.44269504f;

    for (int it = 0; it < 16; it++) {
        if (it < 15) asm volatile("cp.async.wait_group 1;\n");
        else         asm volatile("cp.async.wait_group 0;\n");
        __syncthreads();
        const int stage = it & 1;
        char* base = smem_raw + FL_QBYTES + stage * FL_STAGE;
        const __half* Ks = (const __half*)base;
        const __half* Vh = (const __half*)(base + FL_VHOFF);
        const __half* Vl = (const __half*)(base + FL_VLOFF);
        const int kt = it * 64;

        float sacc[8][4];
        #pragma unroll
        for (int nt = 0; nt < 8; nt++)
            #pragma unroll
            for (int c = 0; c < 4; c++) sacc[nt][c] = 0.f;
        #pragma unroll
        for (int nt = 0; nt < 8; nt++) {
            const __half* pr = &Ks[(nt * 8 + g) * 72 + t4 * 2];
            #pragma unroll
            for (int kc = 0; kc < 4; kc++) {
                uint32_t h0 = *(const uint32_t*)(pr + kc * 16);
                uint32_t h1 = *(const uint32_t*)(pr + kc * 16 + 8);
                mma16816(sacc[nt], qf[kc], h0, h1);         // Qh·Kh
                mma16816(sacc[nt], qf[4 + kc], h0, h1);     // Ql·Kh
            }
        }

        uint64_t w0 = g_mpack[(((size_t)b << 10) + r0) * 16 + it];
        uint64_t w1 = g_mpack[(((size_t)b << 10) + r0 + 8) * 16 + it];
        float mt0 = -1e38f, mt1 = -1e38f;
        #pragma unroll
        for (int nt = 0; nt < 8; nt++) {
            int c0 = kt + nt * 8 + t4 * 2;
            int sh = nt * 8 + t4 * 2;
            float2 ks2 = *(const float2*)&g_ksumT[((size_t)bh << 10) + c0];
            size_t mb0 = ((((size_t)b << 10) + r0) << 10) + c0;
            size_t mb1 = ((((size_t)b << 10) + r0 + 8) << 10) + c0;
            float2 bs0 = __half22float2(*(const __half2*)&g_bs[mb0]);
            float2 bs1 = __half22float2(*(const __half2*)&g_bs[mb1]);
            float s0 = (sacc[nt][0] + bs0.x * ks2.x) * C1;
            float s1 = (sacc[nt][1] + bs0.y * ks2.y) * C1;
            float s2 = (sacc[nt][2] + bs1.x * ks2.x) * C1;
            float s3 = (sacc[nt][3] + bs1.y * ks2.y) * C1;
            sacc[nt][0] = ((w0 >> sh) & 1)       ? -1e37f : s0;
            sacc[nt][1] = ((w0 >> (sh + 1)) & 1) ? -1e37f : s1;
            sacc[nt][2] = ((w1 >> sh) & 1)       ? -1e37f : s2;
            sacc[nt][3] = ((w1 >> (sh + 1)) & 1) ? -1e37f : s3;
            mt0 = fmaxf(mt0, fmaxf(sacc[nt][0], sacc[nt][1]));
            mt1 = fmaxf(mt1, fmaxf(sacc[nt][2], sacc[nt][3]));
        }
        mt0 = fmaxf(mt0, __shfl_xor_sync(0xffffffffu, mt0, 1));
        mt0 = fmaxf(mt0, __shfl_xor_sync(0xffffffffu, mt0, 2));
        mt1 = fmaxf(mt1, __shfl_xor_sync(0xffffffffu, mt1, 1));
        mt1 = fmaxf(mt1, __shfl_xor_sync(0xffffffffu, mt1, 2));
        float mn0 = fmaxf(m0, mt0), mn1 = fmaxf(m1, mt1);
        float sc0 = ex2f(m0 - mn0), sc1 = ex2f(m1 - mn1);
        m0 = mn0; m1 = mn1;
        l0 *= sc0; l1 *= sc1;

        uint32_t phi0[8], phi1[8];
        #pragma unroll
        for (int nt = 0; nt < 8; nt++) {
            float p0 = ex2f(sacc[nt][0] - m0), p1 = ex2f(sacc[nt][1] - m0);
            float p2 = ex2f(sacc[nt][2] - m1), p3 = ex2f(sacc[nt][3] - m1);
            l0 += p0 + p1; l1 += p2 + p3;
            __half2 h0 = __float22half2_rn(make_float2(p0, p1));
            __half2 h1 = __float22half2_rn(make_float2(p2, p3));
            phi0[nt] = *(uint32_t*)&h0;
            phi1[nt] = *(uint32_t*)&h1;
            oacc[nt][0] *= sc0; oacc[nt][1] *= sc0;
            oacc[nt][2] *= sc1; oacc[nt][3] *= sc1;
        }

        #pragma unroll
        for (int kc = 0; kc < 4; kc++) {
            uint32_t ah[4] = {phi0[2*kc], phi1[2*kc], phi0[2*kc+1], phi1[2*kc+1]};
            #pragma unroll
            for (int nt = 0; nt < 8; nt++) {
                const __half* ph = &Vh[(nt * 8 + g) * 72 + kc * 16 + t4 * 2];
                const __half* pl = &Vl[(nt * 8 + g) * 72 + kc * 16 + t4 * 2];
                uint32_t bh0 = *(const uint32_t*)(ph);
                uint32_t bh1 = *(const uint32_t*)(ph + 8);
                uint32_t bl0 = *(const uint32_t*)(pl);
                uint32_t bl1 = *(const uint32_t*)(pl + 8);
                mma16816(oacc[nt], ah, bh0, bh1);
                mma16816(oacc[nt], ah, bl0, bl1);
            }
        }
        __syncthreads();
        if (it + 2 < 16) flash_load_kv(smem_raw, t, bh, (it + 2) * 64, stage);
    }

    l0 += __shfl_xor_sync(0xffffffffu, l0, 1);
    l0 += __shfl_xor_sync(0xffffffffu, l0, 2);
    l1 += __shfl_xor_sync(0xffffffffu, l1, 1);
    l1 += __shfl_xor_sync(0xffffffffu, l1, 2);
    float inv0 = 1.0f / l0, inv1 = 1.0f / l1;
    size_t rowA0 = ((size_t)b << 10) + r0;
    size_t rowA1 = rowA0 + 8;
    #pragma unroll
    for (int nt = 0; nt < 8; nt++) {
        int col = (h << 6) + nt * 8 + t4 * 2;
        float o0 = oacc[nt][0] * inv0, o1 = oacc[nt][1] * inv0;
        float o2 = oacc[nt][2] * inv1, o3 = oacc[nt][3] * inv1;
        __half h0a, l0a, h1a, l1a, h2a, l2a, h3a, l3a;
        split2h(o0, h0a, l0a); split2h(o1, h1a, l1a);
        split2h(o2, h2a, l2a); split2h(o3, h3a, l3a);
        __half2 H0; H0.x=h0a; H0.y=h1a;
        __half2 L0; L0.x=l0a; L0.y=l1a;
        __half2 H1; H1.x=h2a; H1.y=h3a;
        __half2 L1; L1.x=l2a; L1.y=l3a;
        __half* d0 = g_sa + rowA0 * 2048 + col;
        __half* d1 = g_sa + rowA1 * 2048 + col;
        *(__half2*)(d0)        = H0;
        *(__half2*)(d0 + 1024) = L0;
        *(__half2*)(d1)        = H1;
        *(__half2*)(d1 + 1024) = L1;
    }
}

// ---------------- launch ----------------------------------------------------
extern "C" void kernel_launch(void* const* d_in, const int* in_sizes, int n_in,
                              void* d_out, int out_size) {
    const float* states      = (const float*)d_in[0];
    const float* keys        = (const float*)d_in[1];
    const float* masks       = (const float*)d_in[2];
    const void*  abias       = (const void*) d_in[3];
    const float* Wq          = (const float*)d_in[4];
    const float* Wk          = (const float*)d_in[5];
    const float* Wv          = (const float*)d_in[6];
    const float* Wout        = (const float*)d_in[7];
    const float* bias_embs   = (const float*)d_in[8];
    const float* bias_scalar = (const float*)d_in[9];
    float* out = (float*)d_out;
    int E = in_sizes[3] / 4;

    cudaFuncSetAttribute(flash_kernel,
                         cudaFuncAttributeMaxDynamicSharedMemorySize, FL_SMEM);
    cudaFuncSetAttribute(proj_gemm,
                         cudaFuncAttributeMaxDynamicSharedMemorySize, GSMEM);
    cudaFuncSetAttribute(gemm_out,
                         cudaFuncAttributeMaxDynamicSharedMemorySize, GSMEM);

    // conversions (merged launches)
    dim3 ga(8192, 2);
    conv_a2<<<ga, 256>>>((const float4*)states, (const float4*)keys);
    dim3 gw(32, 32, 4);
    conv_w<<<gw, 256>>>(Wq, Wk, Wv, Wout);

    // fused Q/K/V projections (epilogues write flash layouts + ksum + V planes)
    dim3 gp(8, 64, 3);
    proj_gemm<<<gp, 256, GSMEM>>>();

    // side computations
    proj_detect_kernel<<<1, 256>>>(bias_embs, bias_scalar, abias, E);
    init_all<<<8192, 256>>>(masks);
    scatter_max_kernel<<<(E + 255)/256, 256>>>(abias, E);
    scatter_write_kernel<<<(E + 255)/256, 256>>>(abias, E);

    // fused attention (writes ctx split-fp16 into g_sa)
    dim3 gf(T_/128, B_*H_);
    flash_kernel<<<gf, 256, FL_SMEM>>>();

    // output projection
    dim3 gg(8, 64);
    gemm_out<<<gg, 256, GSMEM>>>(out);
}